// round 5
// baseline (speedup 1.0000x reference)
#include <cuda_runtime.h>
#include <cuda_bf16.h>
#include <mma.h>
#include <math.h>
#include <stdint.h>

using namespace nvcuda;

// ---------------- problem constants ----------------
#define Bsz 2
#define Nn  2048
#define Dd  128
#define Hh  4
#define Ff  64
#define HF  256
#define FC1n 1024
#define FC2n 256

// output layout (f32)
#define OUT_GAT 0
#define OUT_FC  12288
#define OUT_LOG 12800
#define OUT_MAP 12804

// ---------------- scratch ----------------
__device__ float g_wcat1[Dd * HF];
__device__ float g_wcat2[HF * HF];
__device__ float g_hproj[Bsz * Nn * HF];
__device__ float g_x1[Bsz * Nn * HF];
__device__ float g_x2[Bsz * Nn * HF];
__device__ float g_es[Bsz * Hh * Nn];
__device__ float g_ed[Bsz * Hh * Nn];
__device__ float g_inv[Bsz * Hh * Nn];
__device__ unsigned g_adjbits[Nn * 64];                      // 512 KB bitmask
__device__ __nv_bfloat16 g_hTh[Bsz * HF * Nn];               // h^T hi
__device__ __nv_bfloat16 g_hTl[Bsz * HF * Nn];               // h^T lo
__device__ float g_fc1[Bsz * FC1n];
__device__ float g_y1[Bsz * FC1n];
__device__ float g_fc2[Bsz * FC2n];
__device__ float g_part[8 * Bsz * FC1n];

// ---------------- f32x2 helpers (SIMT proj GEMM) ----------------
__device__ __forceinline__ unsigned long long pack2(float x, float y) {
    unsigned long long r;
    asm("mov.b64 %0, {%1, %2};" : "=l"(r) : "r"(__float_as_uint(x)), "r"(__float_as_uint(y)));
    return r;
}
__device__ __forceinline__ unsigned long long rep2(float x) {
    unsigned long long r; unsigned u = __float_as_uint(x);
    asm("mov.b64 %0, {%1, %1};" : "=l"(r) : "r"(u));
    return r;
}
__device__ __forceinline__ void fma2(unsigned long long &d, unsigned long long a, unsigned long long b) {
    asm("fma.rn.f32x2 %0, %1, %2, %0;" : "+l"(d) : "l"(a), "l"(b));
}
__device__ __forceinline__ float2 unpk2(unsigned long long v) {
    float2 f; f.x = __uint_as_float((unsigned)v); f.y = __uint_as_float((unsigned)(v >> 32));
    return f;
}

// ---------------- cp.async helpers ----------------
__device__ __forceinline__ uint32_t smem_u32(const void* p) {
    uint32_t a;
    asm("{ .reg .u64 t; cvta.to.shared.u64 t, %1; cvt.u32.u64 %0, t; }" : "=r"(a) : "l"(p));
    return a;
}
#define CP16(saddr, gptr) asm volatile("cp.async.cg.shared.global [%0], [%1], 16;" :: "r"(saddr), "l"(gptr) : "memory")
#define CP_COMMIT() asm volatile("cp.async.commit_group;" ::: "memory")
#define CP_WAIT1()  asm volatile("cp.async.wait_group 1;" ::: "memory")
#define CP_WAIT0()  asm volatile("cp.async.wait_group 0;" ::: "memory")

// ---------------- repack ----------------
__global__ void repack_k(const float* __restrict__ W1, const float* __restrict__ W2) {
    int t = blockIdx.x * blockDim.x + threadIdx.x;
    if (t < Hh * Dd * Ff) {
        int h = t / (Dd * Ff); int r = t % (Dd * Ff); int d = r / Ff; int f = r % Ff;
        g_wcat1[d * HF + h * Ff + f] = W1[t];
    }
    if (t < Hh * HF * Ff) {
        int h = t / (HF * Ff); int r = t % (HF * Ff); int k = r / Ff; int f = r % Ff;
        g_wcat2[k * HF + h * Ff + f] = W2[t];
    }
}

// ---------------- adj -> bitmask ----------------
__global__ void adjpack_k(const int* __restrict__ adj) {
    int w = (blockIdx.x * blockDim.x + threadIdx.x) >> 5;   // word index, 0..131071
    int lane = threadIdx.x & 31;
    int i = w >> 6, widx = w & 63;
    int a = adj[(long)i * Nn + widx * 32 + lane];
    unsigned m = __ballot_sync(0xffffffffu, a > 0);
    if (!lane) g_adjbits[w] = m;
}

// ---------------- SIMT projection GEMM (modes 0/1) ----------------
__global__ void __launch_bounds__(256) gemm_k(const float* __restrict__ xin, int mode) {
    const float *A, *B; float *C; int K, lda;
    if (mode == 0) { A = xin;  B = g_wcat1; C = g_hproj; K = Dd; lda = Dd; }
    else           { A = g_x1; B = g_wcat2; C = g_hproj; K = HF; lda = HF; }
    const int ldb = HF, ldc = HF;

    __shared__ float As[16][128];
    __shared__ float Bs[16][64];

    int tid = threadIdx.x;
    int m0 = blockIdx.x * 128, n0 = blockIdx.y * 64;
    int tx = tid & 15, ty = tid >> 4;
    int a_r = tid >> 2, a_k = (tid & 3) << 2;
    int b_k = tid >> 4, b_n = (tid & 15) << 2;

    const float* Ap0 = A + (long)(m0 + a_r) * lda + a_k;
    const float* Ap1 = Ap0 + (long)64 * lda;
    const float* Bp  = B + (long)b_k * ldb + n0 + b_n;

    unsigned long long acc[4][4];
#pragma unroll
    for (int i = 0; i < 4; i++)
#pragma unroll
        for (int j = 0; j < 4; j++) acc[i][j] = 0ULL;

    float4 av0 = *(const float4*)Ap0;
    float4 av1 = *(const float4*)Ap1;
    float4 bv  = *(const float4*)Bp;

    for (int k0 = 0; k0 < K; k0 += 16) {
        __syncthreads();
        As[a_k + 0][a_r] = av0.x; As[a_k + 1][a_r] = av0.y;
        As[a_k + 2][a_r] = av0.z; As[a_k + 3][a_r] = av0.w;
        As[a_k + 0][a_r + 64] = av1.x; As[a_k + 1][a_r + 64] = av1.y;
        As[a_k + 2][a_r + 64] = av1.z; As[a_k + 3][a_r + 64] = av1.w;
        *(float4*)&Bs[b_k][b_n] = bv;
        __syncthreads();
        if (k0 + 16 < K) {
            av0 = *(const float4*)(Ap0 + k0 + 16);
            av1 = *(const float4*)(Ap1 + k0 + 16);
            bv  = *(const float4*)(Bp + (long)(k0 + 16) * ldb);
        }
#pragma unroll
        for (int kk = 0; kk < 16; kk++) {
            float4 aA = *(const float4*)&As[kk][ty * 8];
            float4 aB = *(const float4*)&As[kk][ty * 8 + 4];
            float4 b4 = *(const float4*)&Bs[kk][tx * 4];
            unsigned long long au[4], bu[4];
            au[0] = pack2(aA.x, aA.y); au[1] = pack2(aA.z, aA.w);
            au[2] = pack2(aB.x, aB.y); au[3] = pack2(aB.z, aB.w);
            bu[0] = rep2(b4.x); bu[1] = rep2(b4.y); bu[2] = rep2(b4.z); bu[3] = rep2(b4.w);
#pragma unroll
            for (int ip = 0; ip < 4; ip++)
#pragma unroll
                for (int j = 0; j < 4; j++) fma2(acc[ip][j], au[ip], bu[j]);
        }
    }
#pragma unroll
    for (int ip = 0; ip < 4; ip++) {
        float2 c0 = unpk2(acc[ip][0]), c1 = unpk2(acc[ip][1]);
        float2 c2 = unpk2(acc[ip][2]), c3 = unpk2(acc[ip][3]);
        float4 lo = make_float4(c0.x, c1.x, c2.x, c3.x);
        float4 hi = make_float4(c0.y, c1.y, c2.y, c3.y);
        int r0 = m0 + ty * 8 + 2 * ip;
        *(float4*)&C[(long)r0 * ldc + n0 + tx * 4] = lo;
        *(float4*)&C[(long)(r0 + 1) * ldc + n0 + tx * 4] = hi;
    }
}

// ---------------- es/ed ----------------
__global__ void esed_k(const float* __restrict__ asrc, const float* __restrict__ adst)
{
    int warp = (blockIdx.x * blockDim.x + threadIdx.x) >> 5;
    int lane = threadIdx.x & 31;
    int b = warp >> 13, rem = warp & 8191, h = rem >> 11, n = rem & 2047;
    const float* hr = g_hproj + ((long)(b * Nn + n) * HF + h * Ff);
    float v0 = hr[lane], v1 = hr[lane + 32];
    float s = v0 * asrc[h * Ff + lane] + v1 * asrc[h * Ff + lane + 32];
    float d = v0 * adst[h * Ff + lane] + v1 * adst[h * Ff + lane + 32];
#pragma unroll
    for (int o = 16; o; o >>= 1) {
        s += __shfl_xor_sync(0xffffffffu, s, o);
        d += __shfl_xor_sync(0xffffffffu, d, o);
    }
    if (!lane) { g_es[warp] = s; g_ed[warp] = d; }
}

// ---------------- row stats: inv row-sums + attention map (no att store) ----------------
__global__ void __launch_bounds__(256) rowstat_k(int layer, float* __restrict__ omap)
{
    __shared__ float red[8];
    int bi = blockIdx.x;
    int b = bi >> 11, i = bi & 2047;
    int tid = threadIdx.x, lane = tid & 31, wid = tid >> 5;

    float msk[8], am[8];
#pragma unroll
    for (int k = 0; k < 8; k++) {
        int j = tid + 256 * k;
        unsigned w = g_adjbits[i * 64 + (j >> 5)];
        msk[k] = ((w >> (j & 31)) & 1u) ? 1.f : 0.f;
        am[k] = 0.f;
    }

    for (int hh = 0; hh < Hh; hh++) {
        int ro = ((b << 2) + hh) << 11;
        float esi = g_es[ro + i];
        const float* edp = g_ed + ro;

        float p[8];
        float lsum = 0.f;
#pragma unroll
        for (int k = 0; k < 8; k++) {
            float s = esi + edp[tid + 256 * k];
            float e = fmaxf(s, 0.2f * s);
            float pe = __expf(e) * msk[k];
            p[k] = pe;
            lsum += pe;
        }
#pragma unroll
        for (int o = 16; o; o >>= 1) lsum += __shfl_xor_sync(0xffffffffu, lsum, o);
        if (!lane) red[wid] = lsum;
        __syncthreads();
        float inv = 1.f / (red[0] + red[1] + red[2] + red[3] + red[4] + red[5] + red[6] + red[7]);
        if (tid == 0) g_inv[ro + i] = inv;
        __syncthreads();
#pragma unroll
        for (int k = 0; k < 8; k++) am[k] += 0.125f * p[k] * inv;
    }

    float* mrow = omap + ((long)bi << 11);
    if (layer == 0) {
#pragma unroll
        for (int k = 0; k < 8; k++) mrow[tid + 256 * k] = am[k];
    } else {
#pragma unroll
        for (int k = 0; k < 8; k++) mrow[tid + 256 * k] += am[k];
    }
}

// ---------------- transpose hproj -> hT bf16 hi/lo ----------------
__global__ void hT_k() {
    __shared__ float t[32][33];
    int b = blockIdx.z;
    int j0 = blockIdx.x * 32, c0 = blockIdx.y * 32;
    int tx = threadIdx.x, ty = threadIdx.y;
#pragma unroll
    for (int i = 0; i < 4; i++) {
        int j = j0 + ty + 8 * i;
        t[ty + 8 * i][tx] = g_hproj[((long)b * Nn + j) * HF + c0 + tx];
    }
    __syncthreads();
#pragma unroll
    for (int i = 0; i < 4; i++) {
        int c = c0 + ty + 8 * i;
        float v = t[tx][ty + 8 * i];
        __nv_bfloat16 hi = __float2bfloat16(v);
        float lo = v - __bfloat162float(hi);
        long o = ((long)b * HF + c) * Nn + j0 + tx;
        g_hTh[o] = hi;
        g_hTl[o] = __float2bfloat16(lo);
    }
}

// ---------------- fused att-gen + wmma GEMM ----------------
// Per CTA: M=128 rows (i), N=64 (f), K=2048 (j) in 32 chunks of 64. z = b*4+h.
// smem: sA hi[128x72]bf16 18432 | sA lo 18432 | sB 2 stages x (hi 9216 + lo 9216)
#define A_LDM 72
#define SA_LO  18432
#define SB_OFF 36864
#define SB_ST  18432
#define SM_TOTAL 73728

__global__ void __launch_bounds__(512) attmma_k(int layer) {
    extern __shared__ char smem[];
    uint32_t sb = smem_u32(smem);
    int tid = threadIdx.x, wid = tid >> 5;
    int z = blockIdx.z;
    int b = z >> 2;
    int m0 = blockIdx.x * 128;
    int row0 = (wid >> 1) * 16;          // 16-row strip per warp pair
    int nh = (wid & 1) * 32;             // N-half per warp

    // gen-mapping constants (fixed per thread)
    int gr = tid >> 2;                   // row 0..127
    int q4 = tid & 3;                    // 16-col segment
    float esi = g_es[(long)z * Nn + m0 + gr];
    const unsigned* awp = g_adjbits + (long)(m0 + gr) * 64 + (q4 >> 1);
    int bshift = (q4 & 1) * 16;
    uint32_t genA_hi = sb + gr * 144 + q4 * 32;
    uint32_t genA_lo = genA_hi + SA_LO;

    // B cp.async mapping
    int brow = tid >> 3, bseg = tid & 7;
    uint32_t bso = brow * 144 + bseg * 16;
    long bgo = ((long)z * 64 + brow) * Nn + bseg * 8;

    wmma::fragment<wmma::accumulator, 16, 16, 16, float> acc[2];
    wmma::fill_fragment(acc[0], 0.f);
    wmma::fill_fragment(acc[1], 0.f);

    // prefetch B chunk 0
    {
        uint32_t s0 = sb + SB_OFF;
        CP16(s0 + bso, g_hTh + bgo);
        CP16(s0 + SB_ST / 2 + bso, g_hTl + bgo);
        CP_COMMIT();
    }

    for (int c = 0; c < 32; ++c) {
        long j0 = (long)c * 64;
        // ---- generate A tile (unnormalized p, bf16 hi/lo) ----
        {
            unsigned bits = (awp[c * 2] >> bshift);
            const float4* edp = (const float4*)(g_ed + (long)z * Nn + j0 + q4 * 16);
            unsigned uhi[8], ulo[8];
#pragma unroll
            for (int g = 0; g < 4; g++) {
                float4 e4 = edp[g];
                float ev[4] = {e4.x, e4.y, e4.z, e4.w};
                float hv[4], lv[4];
#pragma unroll
                for (int u = 0; u < 4; u++) {
                    float s = esi + ev[u];
                    float lk = fmaxf(s, 0.2f * s);
                    float p = __expf(lk);
                    if (!((bits >> (g * 4 + u)) & 1u)) p = 0.f;
                    __nv_bfloat16 hb = __float2bfloat16(p);
                    hv[u] = __bfloat162float(hb);
                    lv[u] = p - hv[u];
                }
                __nv_bfloat162 h01 = __floats2bfloat162_rn(hv[0], hv[1]);
                __nv_bfloat162 h23 = __floats2bfloat162_rn(hv[2], hv[3]);
                __nv_bfloat162 l01 = __floats2bfloat162_rn(lv[0], lv[1]);
                __nv_bfloat162 l23 = __floats2bfloat162_rn(lv[2], lv[3]);
                uhi[g * 2 + 0] = *(unsigned*)&h01; uhi[g * 2 + 1] = *(unsigned*)&h23;
                ulo[g * 2 + 0] = *(unsigned*)&l01; ulo[g * 2 + 1] = *(unsigned*)&l23;
            }
            asm volatile("st.shared.v4.b32 [%0], {%1,%2,%3,%4};" :: "r"(genA_hi),
                         "r"(uhi[0]), "r"(uhi[1]), "r"(uhi[2]), "r"(uhi[3]) : "memory");
            asm volatile("st.shared.v4.b32 [%0], {%1,%2,%3,%4};" :: "r"(genA_hi + 16),
                         "r"(uhi[4]), "r"(uhi[5]), "r"(uhi[6]), "r"(uhi[7]) : "memory");
            asm volatile("st.shared.v4.b32 [%0], {%1,%2,%3,%4};" :: "r"(genA_lo),
                         "r"(ulo[0]), "r"(ulo[1]), "r"(ulo[2]), "r"(ulo[3]) : "memory");
            asm volatile("st.shared.v4.b32 [%0], {%1,%2,%3,%4};" :: "r"(genA_lo + 16),
                         "r"(ulo[4]), "r"(ulo[5]), "r"(ulo[6]), "r"(ulo[7]) : "memory");
        }
        // ---- prefetch next B chunk, wait current ----
        if (c + 1 < 32) {
            uint32_t sN = sb + SB_OFF + ((c + 1) & 1) * SB_ST;
            CP16(sN + bso, g_hTh + bgo + (c + 1) * 64);
            CP16(sN + SB_ST / 2 + bso, g_hTl + bgo + (c + 1) * 64);
            CP_COMMIT();
            CP_WAIT1();
        } else {
            CP_WAIT0();
        }
        __syncthreads();

        const __nv_bfloat16* Ah = (const __nv_bfloat16*)smem;
        const __nv_bfloat16* Al = (const __nv_bfloat16*)(smem + SA_LO);
        const char* sB = smem + SB_OFF + (c & 1) * SB_ST;
        const __nv_bfloat16* Bh = (const __nv_bfloat16*)sB;
        const __nv_bfloat16* Bl = (const __nv_bfloat16*)(sB + SB_ST / 2);

#pragma unroll
        for (int kk = 0; kk < 4; kk++) {
            wmma::fragment<wmma::matrix_a, 16, 16, 16, __nv_bfloat16, wmma::row_major> fa_h, fa_l;
            wmma::load_matrix_sync(fa_h, Ah + row0 * A_LDM + kk * 16, A_LDM);
            wmma::load_matrix_sync(fa_l, Al + row0 * A_LDM + kk * 16, A_LDM);
#pragma unroll
            for (int n = 0; n < 2; n++) {
                wmma::fragment<wmma::matrix_b, 16, 16, 16, __nv_bfloat16, wmma::col_major> fb_h, fb_l;
                wmma::load_matrix_sync(fb_h, Bh + (nh + n * 16) * A_LDM + kk * 16, A_LDM);
                wmma::load_matrix_sync(fb_l, Bl + (nh + n * 16) * A_LDM + kk * 16, A_LDM);
                wmma::mma_sync(acc[n], fa_h, fb_h, acc[n]);
                wmma::mma_sync(acc[n], fa_h, fb_l, acc[n]);
                wmma::mma_sync(acc[n], fa_l, fb_h, acc[n]);
            }
        }
        __syncthreads();
    }

    // epilogue: accums -> smem -> inv-scale + relu -> global
    float* Cs = (float*)smem;
    wmma::store_matrix_sync(Cs + row0 * A_LDM + nh,      acc[0], A_LDM, wmma::mem_row_major);
    wmma::store_matrix_sync(Cs + row0 * A_LDM + nh + 16, acc[1], A_LDM, wmma::mem_row_major);
    __syncthreads();

    float* C = (layer == 0 ? g_x1 : g_x2) + ((long)(b * Nn + m0) * HF + (z & 3) * 64);
    const float* invp = g_inv + (long)z * Nn + m0;
#pragma unroll
    for (int i = 0; i < 4; i++) {
        int q = tid + 512 * i;           // 2048 float4
        int row = q >> 4, cg = q & 15;
        float inv = invp[row];
        float4 v = *(float4*)&Cs[row * A_LDM + cg * 4];
        v.x = fmaxf(v.x, 0.f) * inv; v.y = fmaxf(v.y, 0.f) * inv;
        v.z = fmaxf(v.z, 0.f) * inv; v.w = fmaxf(v.w, 0.f) * inv;
        *(float4*)(C + (long)row * HF + cg * 4) = v;
    }
}

// ---------------- pools ----------------
__global__ void pool_k(const float* __restrict__ xparam,
                       const float* __restrict__ w, const float* __restrict__ wb,
                       float* __restrict__ out, int mode)
{
    int warp = (blockIdx.x * 256 + threadIdx.x) >> 5;
    int lane = threadIdx.x & 31;
    const float* rows; int rowlen, off; float scale;
    if (mode == 0)      { rows = xparam; rowlen = Dd; off = 0;      scale = 1.f / 128.f; }
    else if (mode == 1) { rows = g_x1;   rowlen = HF; off = Nn;     scale = 1.f; }
    else                { rows = g_x2;   rowlen = HF; off = 2 * Nn; scale = 1.f; }
    const float* rp = rows + (long)warp * rowlen;
    float acc = 0.f;
    if (mode == 0) { for (int c = lane; c < rowlen; c += 32) acc += rp[c]; }
    else           { for (int c = lane; c < rowlen; c += 32) acc += rp[c] * w[c]; }
#pragma unroll
    for (int o = 16; o; o >>= 1) acc += __shfl_xor_sync(0xffffffffu, acc, o);
    if (!lane) {
        int b = warp >> 11, n = warp & 2047;
        out[(long)b * (3 * Nn) + off + n] = acc * scale + (mode == 0 ? 0.f : wb[0]);
    }
}

// ---------------- MLP head ----------------
__global__ void __launch_bounds__(256) fc_part_k(const float* __restrict__ in_param,
                                                 const float* __restrict__ W,
                                                 int use_y1, int IC, int OC)
{
    __shared__ float red0[256], red1[256];
    const float* in = use_y1 ? (const float*)g_y1 : in_param;
    int tid = threadIdx.x;
    int cl = tid & 63, ks = tid >> 6;
    int c = blockIdx.x * 64 + cl;
    int kchunk = IC >> 5;
    int k0 = (blockIdx.y * 4 + ks) * kchunk;
    const float* in0 = in;
    const float* in1 = in + IC;
    float a0 = 0.f, a1 = 0.f;
#pragma unroll 4
    for (int k = k0; k < k0 + kchunk; k++) {
        float w = W[(long)k * OC + c];
        a0 += in0[k] * w;
        a1 += in1[k] * w;
    }
    red0[tid] = a0; red1[tid] = a1;
    __syncthreads();
    if (ks == 0) {
        a0 = red0[tid] + red0[tid + 64] + red0[tid + 128] + red0[tid + 192];
        a1 = red1[tid] + red1[tid + 64] + red1[tid + 128] + red1[tid + 192];
        long base = (long)blockIdx.y * (2 * OC);
        g_part[base + c] = a0;
        g_part[base + OC + c] = a1;
    }
}

__global__ void fc_reduce_k(const float* __restrict__ bias, int mode, int OC, int tot)
{
    int t = blockIdx.x * 256 + threadIdx.x;
    if (t >= tot) return;
    float s = bias[t % OC];
#pragma unroll
    for (int p = 0; p < 8; p++) s += g_part[(long)p * tot + t];
    if (mode == 0) g_fc1[t] = s; else g_fc2[t] = s;
}

__global__ void ln_relu_k(int mode, float* __restrict__ out_param,
                          const float* __restrict__ g, const float* __restrict__ be)
{
    __shared__ float r1[8], r2[8];
    int C = (mode == 0) ? FC1n : FC2n;
    const float* in = (mode == 0) ? (const float*)g_fc1 : (const float*)g_fc2;
    float* outp = (mode == 0) ? (float*)g_y1 : out_param;
    int b = blockIdx.x, tid = threadIdx.x, lane = tid & 31, wid = tid >> 5;
    const float* row = in + (long)b * C;
    float s = 0.f, ss = 0.f;
    for (int c = tid; c < C; c += 256) { float v = row[c]; s += v; ss += v * v; }
#pragma unroll
    for (int o = 16; o; o >>= 1) {
        s  += __shfl_xor_sync(0xffffffffu, s, o);
        ss += __shfl_xor_sync(0xffffffffu, ss, o);
    }
    if (!lane) { r1[wid] = s; r2[wid] = ss; }
    __syncthreads();
    s = 0.f; ss = 0.f;
#pragma unroll
    for (int w = 0; w < 8; w++) { s += r1[w]; ss += r2[w]; }
    float m = s / C;
    float var = ss / C - m * m;
    float r = rsqrtf(var + 1e-5f);
    for (int c = tid; c < C; c += 256) {
        float v = row[c];
        outp[(long)b * C + c] = fmaxf((v - m) * r * g[c] + be[c], 0.f);
    }
}

__global__ void cls_k(const float* __restrict__ feat, const float* __restrict__ W,
                      const float* __restrict__ wb, float* __restrict__ out)
{
    int tid = threadIdx.x;
    if (tid >= 128) return;
    int lane = tid & 31, w = tid >> 5;
    int b = w >> 1, l = w & 1;
    float acc = 0.f;
    for (int k = lane; k < FC2n; k += 32) acc += feat[b * FC2n + k] * W[k * 2 + l];
#pragma unroll
    for (int o = 16; o; o >>= 1) acc += __shfl_xor_sync(0xffffffffu, acc, o);
    if (!lane) out[b * 2 + l] = acc + wb[l];
}

// ---------------- host launcher ----------------
extern "C" void kernel_launch(void* const* d_in, const int* in_sizes, int n_in,
                              void* d_out, int out_size)
{
    const float* x        = (const float*)d_in[0];
    const int*   adj      = (const int*)  d_in[1];
    const float* a1_src   = (const float*)d_in[4];
    const float* a1_dst   = (const float*)d_in[5];
    const float* pool1_W  = (const float*)d_in[6];
    const float* pool1_b  = (const float*)d_in[7];
    const float* a2_src   = (const float*)d_in[9];
    const float* a2_dst   = (const float*)d_in[10];
    const float* pool2_W  = (const float*)d_in[11];
    const float* pool2_b  = (const float*)d_in[12];
    const float* fc1_W    = (const float*)d_in[13];
    const float* fc1_b    = (const float*)d_in[14];
    const float* ln1_g    = (const float*)d_in[15];
    const float* ln1_b    = (const float*)d_in[16];
    const float* fc2_W    = (const float*)d_in[17];
    const float* fc2_b    = (const float*)d_in[18];
    const float* ln2_g    = (const float*)d_in[19];
    const float* ln2_b    = (const float*)d_in[20];
    const float* cls_W    = (const float*)d_in[21];
    const float* cls_b    = (const float*)d_in[22];

    float* out = (float*)d_out;

    cudaFuncSetAttribute(attmma_k, cudaFuncAttributeMaxDynamicSharedMemorySize, SM_TOTAL);

    repack_k<<<256, 256>>>((const float*)d_in[3], (const float*)d_in[8]);
    adjpack_k<<<16384, 256>>>(adj);

    // layer 1
    gemm_k<<<dim3(32, 4, 1), 256>>>(x, 0);
    esed_k<<<2048, 256>>>(a1_src, a1_dst);
    rowstat_k<<<4096, 256>>>(0, out + OUT_MAP);
    hT_k<<<dim3(64, 8, 2), dim3(32, 8)>>>();
    attmma_k<<<dim3(16, 1, 8), 512, SM_TOTAL>>>(0);

    pool_k<<<512, 256>>>(x, pool1_W, pool1_b, out + OUT_GAT, 0);
    pool_k<<<512, 256>>>(x, pool1_W, pool1_b, out + OUT_GAT, 1);

    // layer 2
    gemm_k<<<dim3(32, 4, 1), 256>>>(x, 1);
    esed_k<<<2048, 256>>>(a2_src, a2_dst);
    rowstat_k<<<4096, 256>>>(1, out + OUT_MAP);
    hT_k<<<dim3(64, 8, 2), dim3(32, 8)>>>();
    attmma_k<<<dim3(16, 1, 8), 512, SM_TOTAL>>>(1);

    pool_k<<<512, 256>>>(x, pool2_W, pool2_b, out + OUT_GAT, 2);

    // head
    fc_part_k<<<dim3(16, 8), 256>>>(out + OUT_GAT, fc1_W, 0, 3 * Nn, FC1n);
    fc_reduce_k<<<8, 256>>>(fc1_b, 0, FC1n, Bsz * FC1n);
    ln_relu_k<<<2, 256>>>(0, out, ln1_g, ln1_b);

    fc_part_k<<<dim3(4, 8), 256>>>(out, fc2_W, 1, FC1n, FC2n);
    fc_reduce_k<<<2, 256>>>(fc2_b, 1, FC2n, Bsz * FC2n);
    ln_relu_k<<<2, 256>>>(1, out + OUT_FC, ln2_g, ln2_b);

    cls_k<<<1, 128>>>(out + OUT_FC, cls_W, cls_b, out + OUT_LOG);
}

// round 6
// speedup vs baseline: 1.0283x; 1.0283x over previous
#include <cuda_runtime.h>
#include <cuda_bf16.h>
#include <mma.h>
#include <math.h>
#include <stdint.h>

using namespace nvcuda;

// ---------------- problem constants ----------------
#define Bsz 2
#define Nn  2048
#define Dd  128
#define Hh  4
#define Ff  64
#define HF  256
#define FC1n 1024
#define FC2n 256

// output layout (f32)
#define OUT_GAT 0
#define OUT_FC  12288
#define OUT_LOG 12800
#define OUT_MAP 12804

// ---------------- scratch ----------------
__device__ float g_wcat1[Dd * HF];
__device__ float g_wcat2[HF * HF];
__device__ float g_hproj[Bsz * Nn * HF];
__device__ float g_x1[Bsz * Nn * HF];
__device__ float g_x2[Bsz * Nn * HF];
__device__ float g_es[Bsz * Hh * Nn];
__device__ float g_ed[Bsz * Hh * Nn];
__device__ float g_inv[Bsz * Hh * Nn];
__device__ unsigned g_adjbits[Nn * 64];                      // 512 KB bitmask
__device__ __nv_bfloat16 g_hTh[Bsz * HF * Nn];               // h^T hi
__device__ __nv_bfloat16 g_hTl[Bsz * HF * Nn];               // h^T lo
__device__ float g_fc1[Bsz * FC1n];
__device__ float g_y1[Bsz * FC1n];
__device__ float g_fc2[Bsz * FC2n];
__device__ float g_part[8 * Bsz * FC1n];

// ---------------- f32x2 helpers (SIMT proj GEMM) ----------------
__device__ __forceinline__ unsigned long long pack2(float x, float y) {
    unsigned long long r;
    asm("mov.b64 %0, {%1, %2};" : "=l"(r) : "r"(__float_as_uint(x)), "r"(__float_as_uint(y)));
    return r;
}
__device__ __forceinline__ unsigned long long rep2(float x) {
    unsigned long long r; unsigned u = __float_as_uint(x);
    asm("mov.b64 %0, {%1, %1};" : "=l"(r) : "r"(u));
    return r;
}
__device__ __forceinline__ void fma2(unsigned long long &d, unsigned long long a, unsigned long long b) {
    asm("fma.rn.f32x2 %0, %1, %2, %0;" : "+l"(d) : "l"(a), "l"(b));
}
__device__ __forceinline__ float2 unpk2(unsigned long long v) {
    float2 f; f.x = __uint_as_float((unsigned)v); f.y = __uint_as_float((unsigned)(v >> 32));
    return f;
}

// ---------------- cp.async helpers ----------------
__device__ __forceinline__ uint32_t smem_u32(const void* p) {
    uint32_t a;
    asm("{ .reg .u64 t; cvta.to.shared.u64 t, %1; cvt.u32.u64 %0, t; }" : "=r"(a) : "l"(p));
    return a;
}
#define CP16(saddr, gptr) asm volatile("cp.async.cg.shared.global [%0], [%1], 16;" :: "r"(saddr), "l"(gptr) : "memory")
#define CP_COMMIT() asm volatile("cp.async.commit_group;" ::: "memory")
#define CP_WAIT0()  asm volatile("cp.async.wait_group 0;" ::: "memory")

// ---------------- repack ----------------
__global__ void repack_k(const float* __restrict__ W1, const float* __restrict__ W2) {
    int t = blockIdx.x * blockDim.x + threadIdx.x;
    if (t < Hh * Dd * Ff) {
        int h = t / (Dd * Ff); int r = t % (Dd * Ff); int d = r / Ff; int f = r % Ff;
        g_wcat1[d * HF + h * Ff + f] = W1[t];
    }
    if (t < Hh * HF * Ff) {
        int h = t / (HF * Ff); int r = t % (HF * Ff); int k = r / Ff; int f = r % Ff;
        g_wcat2[k * HF + h * Ff + f] = W2[t];
    }
}

// ---------------- adj -> bitmask ----------------
__global__ void adjpack_k(const int* __restrict__ adj) {
    int w = (blockIdx.x * blockDim.x + threadIdx.x) >> 5;   // word index
    int lane = threadIdx.x & 31;
    int i = w >> 6, widx = w & 63;
    int a = adj[(long)i * Nn + widx * 32 + lane];
    unsigned m = __ballot_sync(0xffffffffu, a > 0);
    if (!lane) g_adjbits[w] = m;
}

// ---------------- SIMT projection GEMM + fused es/ed epilogue ----------------
// blockIdx.y = head. CTA covers rows [m0,m0+128) x head's 64 F-cols -> es/ed dots
// are fully CTA-local; reduce across the 16 tx lanes through padded smem.
__global__ void __launch_bounds__(256) gemm_k(const float* __restrict__ xin,
                                              const float* __restrict__ asrc,
                                              const float* __restrict__ adst, int mode) {
    const float *A, *B; float *C; int K, lda;
    if (mode == 0) { A = xin;  B = g_wcat1; C = g_hproj; K = Dd; lda = Dd; }
    else           { A = g_x1; B = g_wcat2; C = g_hproj; K = HF; lda = HF; }
    const int ldb = HF, ldc = HF;

    __shared__ float As[16][128];
    __shared__ float Bs[16][64];
    __shared__ float esp[16][129];
    __shared__ float edp[16][129];
    __shared__ float av[64], dv[64];

    int tid = threadIdx.x;
    int head = blockIdx.y;
    int m0 = blockIdx.x * 128, n0 = head * 64;
    int tx = tid & 15, ty = tid >> 4;
    int a_r = tid >> 2, a_k = (tid & 3) << 2;
    int b_k = tid >> 4, b_n = (tid & 15) << 2;

    if (tid < 64)       av[tid] = asrc[n0 + tid];
    else if (tid < 128) dv[tid - 64] = adst[n0 + tid - 64];

    const float* Ap0 = A + (long)(m0 + a_r) * lda + a_k;
    const float* Ap1 = Ap0 + (long)64 * lda;
    const float* Bp  = B + (long)b_k * ldb + n0 + b_n;

    unsigned long long acc[4][4];
#pragma unroll
    for (int i = 0; i < 4; i++)
#pragma unroll
        for (int j = 0; j < 4; j++) acc[i][j] = 0ULL;

    float4 av0 = *(const float4*)Ap0;
    float4 av1 = *(const float4*)Ap1;
    float4 bv  = *(const float4*)Bp;

    for (int k0 = 0; k0 < K; k0 += 16) {
        __syncthreads();
        As[a_k + 0][a_r] = av0.x; As[a_k + 1][a_r] = av0.y;
        As[a_k + 2][a_r] = av0.z; As[a_k + 3][a_r] = av0.w;
        As[a_k + 0][a_r + 64] = av1.x; As[a_k + 1][a_r + 64] = av1.y;
        As[a_k + 2][a_r + 64] = av1.z; As[a_k + 3][a_r + 64] = av1.w;
        *(float4*)&Bs[b_k][b_n] = bv;
        __syncthreads();
        if (k0 + 16 < K) {
            av0 = *(const float4*)(Ap0 + k0 + 16);
            av1 = *(const float4*)(Ap1 + k0 + 16);
            bv  = *(const float4*)(Bp + (long)(k0 + 16) * ldb);
        }
#pragma unroll
        for (int kk = 0; kk < 16; kk++) {
            float4 aA = *(const float4*)&As[kk][ty * 8];
            float4 aB = *(const float4*)&As[kk][ty * 8 + 4];
            float4 b4 = *(const float4*)&Bs[kk][tx * 4];
            unsigned long long au[4], bu[4];
            au[0] = pack2(aA.x, aA.y); au[1] = pack2(aA.z, aA.w);
            au[2] = pack2(aB.x, aB.y); au[3] = pack2(aB.z, aB.w);
            bu[0] = rep2(b4.x); bu[1] = rep2(b4.y); bu[2] = rep2(b4.z); bu[3] = rep2(b4.w);
#pragma unroll
            for (int ip = 0; ip < 4; ip++)
#pragma unroll
                for (int j = 0; j < 4; j++) fma2(acc[ip][j], au[ip], bu[j]);
        }
    }

    float as0 = av[tx * 4], as1 = av[tx * 4 + 1], as2 = av[tx * 4 + 2], as3 = av[tx * 4 + 3];
    float ad0 = dv[tx * 4], ad1 = dv[tx * 4 + 1], ad2 = dv[tx * 4 + 2], ad3 = dv[tx * 4 + 3];

#pragma unroll
    for (int ip = 0; ip < 4; ip++) {
        float2 c0 = unpk2(acc[ip][0]), c1 = unpk2(acc[ip][1]);
        float2 c2 = unpk2(acc[ip][2]), c3 = unpk2(acc[ip][3]);
        float4 lo = make_float4(c0.x, c1.x, c2.x, c3.x);
        float4 hi = make_float4(c0.y, c1.y, c2.y, c3.y);
        int rl = ty * 8 + 2 * ip;
        esp[tx][rl]     = lo.x * as0 + lo.y * as1 + lo.z * as2 + lo.w * as3;
        edp[tx][rl]     = lo.x * ad0 + lo.y * ad1 + lo.z * ad2 + lo.w * ad3;
        esp[tx][rl + 1] = hi.x * as0 + hi.y * as1 + hi.z * as2 + hi.w * as3;
        edp[tx][rl + 1] = hi.x * ad0 + hi.y * ad1 + hi.z * ad2 + hi.w * ad3;
        int r0 = m0 + rl;
        *(float4*)&C[(long)r0 * ldc + n0 + tx * 4] = lo;
        *(float4*)&C[(long)(r0 + 1) * ldc + n0 + tx * 4] = hi;
    }
    __syncthreads();
    {
        int row = tid & 127, which = tid >> 7;
        const float (*src)[129] = which ? edp : esp;
        float s = 0.f;
#pragma unroll
        for (int t = 0; t < 16; t++) s += src[t][row];
        int r = m0 + row;
        int bb = r >> 11, n = r & 2047;
        int idx = (((bb << 2) + head) << 11) | n;
        if (which) g_ed[idx] = s; else g_es[idx] = s;
    }
}

// ---------------- row stats: inv row-sums + attention map ----------------
__global__ void __launch_bounds__(256) rowstat_k(int layer, float* __restrict__ omap)
{
    __shared__ float red[8];
    int bi = blockIdx.x;
    int b = bi >> 11, i = bi & 2047;
    int tid = threadIdx.x, lane = tid & 31, wid = tid >> 5;

    float msk[8], am[8];
#pragma unroll
    for (int k = 0; k < 8; k++) {
        int j = tid + 256 * k;
        unsigned w = g_adjbits[i * 64 + (j >> 5)];
        msk[k] = ((w >> (j & 31)) & 1u) ? 1.f : 0.f;
        am[k] = 0.f;
    }

    for (int hh = 0; hh < Hh; hh++) {
        int ro = ((b << 2) + hh) << 11;
        float esi = g_es[ro + i];
        const float* edpp = g_ed + ro;

        float p[8];
        float lsum = 0.f;
#pragma unroll
        for (int k = 0; k < 8; k++) {
            float s = esi + edpp[tid + 256 * k];
            float e = fmaxf(s, 0.2f * s);
            float pe = __expf(e) * msk[k];
            p[k] = pe;
            lsum += pe;
        }
#pragma unroll
        for (int o = 16; o; o >>= 1) lsum += __shfl_xor_sync(0xffffffffu, lsum, o);
        if (!lane) red[wid] = lsum;
        __syncthreads();
        float inv = 1.f / (red[0] + red[1] + red[2] + red[3] + red[4] + red[5] + red[6] + red[7]);
        if (tid == 0) g_inv[ro + i] = inv;
        __syncthreads();
#pragma unroll
        for (int k = 0; k < 8; k++) am[k] += 0.125f * p[k] * inv;
    }

    float* mrow = omap + ((long)bi << 11);
    if (layer == 0) {
#pragma unroll
        for (int k = 0; k < 8; k++) mrow[tid + 256 * k] = am[k];
    } else {
#pragma unroll
        for (int k = 0; k < 8; k++) mrow[tid + 256 * k] += am[k];
    }
}

// ---------------- transpose hproj -> hT bf16 hi/lo ----------------
__global__ void hT_k() {
    __shared__ float t[32][33];
    int b = blockIdx.z;
    int j0 = blockIdx.x * 32, c0 = blockIdx.y * 32;
    int tx = threadIdx.x, ty = threadIdx.y;
#pragma unroll
    for (int i = 0; i < 4; i++) {
        int j = j0 + ty + 8 * i;
        t[ty + 8 * i][tx] = g_hproj[((long)b * Nn + j) * HF + c0 + tx];
    }
    __syncthreads();
#pragma unroll
    for (int i = 0; i < 4; i++) {
        int c = c0 + ty + 8 * i;
        float v = t[tx][ty + 8 * i];
        __nv_bfloat16 hi = __float2bfloat16(v);
        float lo = v - __bfloat162float(hi);
        long o = ((long)b * HF + c) * Nn + j0 + tx;
        g_hTh[o] = hi;
        g_hTl[o] = __float2bfloat16(lo);
    }
}

// ---------------- fused att-gen + wmma GEMM (double-buffered A, 1 sync/chunk) ----------------
// smem: A stage0 (hi 18432 | lo 18432) | A stage1 (...) | B stage0 (hi 9216 | lo 9216) | B stage1
#define A_LDM 72
#define SA_LO  18432
#define A_ST   36864
#define SB_OFF 73728
#define SB_ST  18432
#define SM_TOTAL 110592

__device__ __forceinline__ void gen_chunk(uint32_t sb, int stage, int c,
    float esi, const unsigned* __restrict__ awp, int bshift, uint32_t genoff, long edbase)
{
    unsigned bits = awp[c * 2] >> bshift;
    const float4* e4p = (const float4*)(g_ed + edbase + (long)c * 64);
    uint32_t ah = sb + stage * A_ST + genoff;
    uint32_t al = ah + SA_LO;
    unsigned uhi[8], ulo[8];
#pragma unroll
    for (int g = 0; g < 4; g++) {
        float4 e4 = e4p[g];
        float ev[4] = {e4.x, e4.y, e4.z, e4.w};
        unsigned pu[4]; float lv[4];
#pragma unroll
        for (int u = 0; u < 4; u++) {
            float s = esi + ev[u];
            float lk = fmaxf(s, 0.2f * s);
            float p = __expf(lk);
            if (!((bits >> (g * 4 + u)) & 1u)) p = 0.f;
            pu[u] = __float_as_uint(p);
            lv[u] = p - __uint_as_float(pu[u] & 0xFFFF0000u);   // exact truncation residual
        }
        uhi[g * 2 + 0] = __byte_perm(pu[0], pu[1], 0x7632);
        uhi[g * 2 + 1] = __byte_perm(pu[2], pu[3], 0x7632);
        __nv_bfloat162 l01 = __floats2bfloat162_rn(lv[0], lv[1]);
        __nv_bfloat162 l23 = __floats2bfloat162_rn(lv[2], lv[3]);
        ulo[g * 2 + 0] = *(unsigned*)&l01;
        ulo[g * 2 + 1] = *(unsigned*)&l23;
    }
    asm volatile("st.shared.v4.b32 [%0], {%1,%2,%3,%4};" :: "r"(ah),
                 "r"(uhi[0]), "r"(uhi[1]), "r"(uhi[2]), "r"(uhi[3]) : "memory");
    asm volatile("st.shared.v4.b32 [%0], {%1,%2,%3,%4};" :: "r"(ah + 16),
                 "r"(uhi[4]), "r"(uhi[5]), "r"(uhi[6]), "r"(uhi[7]) : "memory");
    asm volatile("st.shared.v4.b32 [%0], {%1,%2,%3,%4};" :: "r"(al),
                 "r"(ulo[0]), "r"(ulo[1]), "r"(ulo[2]), "r"(ulo[3]) : "memory");
    asm volatile("st.shared.v4.b32 [%0], {%1,%2,%3,%4};" :: "r"(al + 16),
                 "r"(ulo[4]), "r"(ulo[5]), "r"(ulo[6]), "r"(ulo[7]) : "memory");
}

__global__ void __launch_bounds__(512) attmma_k(int layer) {
    extern __shared__ char smem[];
    uint32_t sb = smem_u32(smem);
    int tid = threadIdx.x, wid = tid >> 5;
    int z = blockIdx.z;
    int b = z >> 2;
    int m0 = blockIdx.x * 128;
    int row0 = (wid >> 1) * 16;          // 16-row strip per warp pair
    int nh = (wid & 1) * 32;             // N-half per warp

    // gen constants
    int gr = tid >> 2, q4 = tid & 3;
    float esi = g_es[(long)z * Nn + m0 + gr];
    const unsigned* awp = g_adjbits + (long)(m0 + gr) * 64 + (q4 >> 1);
    int bshift = (q4 & 1) * 16;
    uint32_t genoff = gr * 144 + q4 * 32;
    long edbase = (long)z * Nn + q4 * 16;

    // B cp.async mapping
    int brow = tid >> 3, bseg = tid & 7;
    uint32_t bso = brow * 144 + bseg * 16;
    long bgo = ((long)z * 64 + brow) * Nn + bseg * 8;

    wmma::fragment<wmma::accumulator, 16, 16, 16, float> acc[2];
    wmma::fill_fragment(acc[0], 0.f);
    wmma::fill_fragment(acc[1], 0.f);

    // prologue: gen chunk 0 into A stage 0; prefetch B chunk 0 into B stage 0
    gen_chunk(sb, 0, 0, esi, awp, bshift, genoff, edbase);
    {
        uint32_t s0 = sb + SB_OFF;
        CP16(s0 + bso, g_hTh + bgo);
        CP16(s0 + SB_ST / 2 + bso, g_hTl + bgo);
        CP_COMMIT();
    }

    for (int c = 0; c < 32; ++c) {
        int cur = c & 1;
        CP_WAIT0();
        __syncthreads();     // A(cur) gen'd + B(cur) arrived; prior readers of !cur stages done

        if (c + 1 < 32) {    // prefetch B(c+1) into the other stage
            uint32_t sN = sb + SB_OFF + (cur ^ 1) * SB_ST;
            CP16(sN + bso, g_hTh + bgo + (c + 1) * 64);
            CP16(sN + SB_ST / 2 + bso, g_hTl + bgo + (c + 1) * 64);
            CP_COMMIT();
        }

        const char* sA = smem + cur * A_ST;
        const __nv_bfloat16* Ah = (const __nv_bfloat16*)sA;
        const __nv_bfloat16* Al = (const __nv_bfloat16*)(sA + SA_LO);
        const char* sB = smem + SB_OFF + cur * SB_ST;
        const __nv_bfloat16* Bh = (const __nv_bfloat16*)sB;
        const __nv_bfloat16* Bl = (const __nv_bfloat16*)(sB + SB_ST / 2);

#pragma unroll
        for (int kk = 0; kk < 4; kk++) {
            wmma::fragment<wmma::matrix_a, 16, 16, 16, __nv_bfloat16, wmma::row_major> fa_h, fa_l;
            wmma::load_matrix_sync(fa_h, Ah + row0 * A_LDM + kk * 16, A_LDM);
            wmma::load_matrix_sync(fa_l, Al + row0 * A_LDM + kk * 16, A_LDM);
#pragma unroll
            for (int n = 0; n < 2; n++) {
                wmma::fragment<wmma::matrix_b, 16, 16, 16, __nv_bfloat16, wmma::col_major> fb_h, fb_l;
                wmma::load_matrix_sync(fb_h, Bh + (nh + n * 16) * A_LDM + kk * 16, A_LDM);
                wmma::load_matrix_sync(fb_l, Bl + (nh + n * 16) * A_LDM + kk * 16, A_LDM);
                wmma::mma_sync(acc[n], fa_h, fb_h, acc[n]);
                wmma::mma_sync(acc[n], fa_h, fb_l, acc[n]);
                wmma::mma_sync(acc[n], fa_l, fb_h, acc[n]);
            }
        }

        // overlap: generate next chunk's A while tensor pipe drains
        if (c + 1 < 32)
            gen_chunk(sb, cur ^ 1, c + 1, esi, awp, bshift, genoff, edbase);
    }

    // epilogue: accums -> smem (stage-0 A region, free) -> inv-scale + relu -> global
    float* Cs = (float*)smem;
    wmma::store_matrix_sync(Cs + row0 * A_LDM + nh,      acc[0], A_LDM, wmma::mem_row_major);
    wmma::store_matrix_sync(Cs + row0 * A_LDM + nh + 16, acc[1], A_LDM, wmma::mem_row_major);
    __syncthreads();

    float* C = (layer == 0 ? g_x1 : g_x2) + ((long)(b * Nn + m0) * HF + (z & 3) * 64);
    const float* invp = g_inv + (long)z * Nn + m0;
#pragma unroll
    for (int i = 0; i < 4; i++) {
        int q = tid + 512 * i;           // 2048 float4
        int row = q >> 4, cg = q & 15;
        float inv = invp[row];
        float4 v = *(float4*)&Cs[row * A_LDM + cg * 4];
        v.x = fmaxf(v.x, 0.f) * inv; v.y = fmaxf(v.y, 0.f) * inv;
        v.z = fmaxf(v.z, 0.f) * inv; v.w = fmaxf(v.w, 0.f) * inv;
        *(float4*)(C + (long)row * HF + cg * 4) = v;
    }
}

// ---------------- pools ----------------
__global__ void pool_k(const float* __restrict__ xparam,
                       const float* __restrict__ w, const float* __restrict__ wb,
                       float* __restrict__ out, int mode)
{
    int warp = (blockIdx.x * 256 + threadIdx.x) >> 5;
    int lane = threadIdx.x & 31;
    const float* rows; int rowlen, off; float scale;
    if (mode == 0)      { rows = xparam; rowlen = Dd; off = 0;      scale = 1.f / 128.f; }
    else if (mode == 1) { rows = g_x1;   rowlen = HF; off = Nn;     scale = 1.f; }
    else                { rows = g_x2;   rowlen = HF; off = 2 * Nn; scale = 1.f; }
    const float* rp = rows + (long)warp * rowlen;
    float acc = 0.f;
    if (mode == 0) { for (int c = lane; c < rowlen; c += 32) acc += rp[c]; }
    else           { for (int c = lane; c < rowlen; c += 32) acc += rp[c] * w[c]; }
#pragma unroll
    for (int o = 16; o; o >>= 1) acc += __shfl_xor_sync(0xffffffffu, acc, o);
    if (!lane) {
        int b = warp >> 11, n = warp & 2047;
        out[(long)b * (3 * Nn) + off + n] = acc * scale + (mode == 0 ? 0.f : wb[0]);
    }
}

// ---------------- MLP head ----------------
__global__ void __launch_bounds__(256) fc_part_k(const float* __restrict__ in_param,
                                                 const float* __restrict__ W,
                                                 int use_y1, int IC, int OC)
{
    __shared__ float red0[256], red1[256];
    const float* in = use_y1 ? (const float*)g_y1 : in_param;
    int tid = threadIdx.x;
    int cl = tid & 63, ks = tid >> 6;
    int c = blockIdx.x * 64 + cl;
    int kchunk = IC >> 5;
    int k0 = (blockIdx.y * 4 + ks) * kchunk;
    const float* in0 = in;
    const float* in1 = in + IC;
    float a0 = 0.f, a1 = 0.f;
#pragma unroll 4
    for (int k = k0; k < k0 + kchunk; k++) {
        float w = W[(long)k * OC + c];
        a0 += in0[k] * w;
        a1 += in1[k] * w;
    }
    red0[tid] = a0; red1[tid] = a1;
    __syncthreads();
    if (ks == 0) {
        a0 = red0[tid] + red0[tid + 64] + red0[tid + 128] + red0[tid + 192];
        a1 = red1[tid] + red1[tid + 64] + red1[tid + 128] + red1[tid + 192];
        long base = (long)blockIdx.y * (2 * OC);
        g_part[base + c] = a0;
        g_part[base + OC + c] = a1;
    }
}

__global__ void fc_reduce_k(const float* __restrict__ bias, int mode, int OC, int tot)
{
    int t = blockIdx.x * 256 + threadIdx.x;
    if (t >= tot) return;
    float s = bias[t % OC];
#pragma unroll
    for (int p = 0; p < 8; p++) s += g_part[(long)p * tot + t];
    if (mode == 0) g_fc1[t] = s; else g_fc2[t] = s;
}

__global__ void ln_relu_k(int mode, float* __restrict__ out_param,
                          const float* __restrict__ g, const float* __restrict__ be)
{
    __shared__ float r1[8], r2[8];
    int C = (mode == 0) ? FC1n : FC2n;
    const float* in = (mode == 0) ? (const float*)g_fc1 : (const float*)g_fc2;
    float* outp = (mode == 0) ? (float*)g_y1 : out_param;
    int b = blockIdx.x, tid = threadIdx.x, lane = tid & 31, wid = tid >> 5;
    const float* row = in + (long)b * C;
    float s = 0.f, ss = 0.f;
    for (int c = tid; c < C; c += 256) { float v = row[c]; s += v; ss += v * v; }
#pragma unroll
    for (int o = 16; o; o >>= 1) {
        s  += __shfl_xor_sync(0xffffffffu, s, o);
        ss += __shfl_xor_sync(0xffffffffu, ss, o);
    }
    if (!lane) { r1[wid] = s; r2[wid] = ss; }
    __syncthreads();
    s = 0.f; ss = 0.f;
#pragma unroll
    for (int w = 0; w < 8; w++) { s += r1[w]; ss += r2[w]; }
    float m = s / C;
    float var = ss / C - m * m;
    float r = rsqrtf(var + 1e-5f);
    for (int c = tid; c < C; c += 256) {
        float v = row[c];
        outp[(long)b * C + c] = fmaxf((v - m) * r * g[c] + be[c], 0.f);
    }
}

__global__ void cls_k(const float* __restrict__ feat, const float* __restrict__ W,
                      const float* __restrict__ wb, float* __restrict__ out)
{
    int tid = threadIdx.x;
    if (tid >= 128) return;
    int lane = tid & 31, w = tid >> 5;
    int b = w >> 1, l = w & 1;
    float acc = 0.f;
    for (int k = lane; k < FC2n; k += 32) acc += feat[b * FC2n + k] * W[k * 2 + l];
#pragma unroll
    for (int o = 16; o; o >>= 1) acc += __shfl_xor_sync(0xffffffffu, acc, o);
    if (!lane) out[b * 2 + l] = acc + wb[l];
}

// ---------------- host launcher ----------------
extern "C" void kernel_launch(void* const* d_in, const int* in_sizes, int n_in,
                              void* d_out, int out_size)
{
    const float* x        = (const float*)d_in[0];
    const int*   adj      = (const int*)  d_in[1];
    const float* a1_src   = (const float*)d_in[4];
    const float* a1_dst   = (const float*)d_in[5];
    const float* pool1_W  = (const float*)d_in[6];
    const float* pool1_b  = (const float*)d_in[7];
    const float* a2_src   = (const float*)d_in[9];
    const float* a2_dst   = (const float*)d_in[10];
    const float* pool2_W  = (const float*)d_in[11];
    const float* pool2_b  = (const float*)d_in[12];
    const float* fc1_W    = (const float*)d_in[13];
    const float* fc1_b    = (const float*)d_in[14];
    const float* ln1_g    = (const float*)d_in[15];
    const float* ln1_b    = (const float*)d_in[16];
    const float* fc2_W    = (const float*)d_in[17];
    const float* fc2_b    = (const float*)d_in[18];
    const float* ln2_g    = (const float*)d_in[19];
    const float* ln2_b    = (const float*)d_in[20];
    const float* cls_W    = (const float*)d_in[21];
    const float* cls_b    = (const float*)d_in[22];

    float* out = (float*)d_out;

    cudaFuncSetAttribute(attmma_k, cudaFuncAttributeMaxDynamicSharedMemorySize, SM_TOTAL);

    repack_k<<<256, 256>>>((const float*)d_in[3], (const float*)d_in[8]);
    adjpack_k<<<16384, 256>>>(adj);

    // layer 1
    gemm_k<<<dim3(32, 4, 1), 256>>>(x, a1_src, a1_dst, 0);
    rowstat_k<<<4096, 256>>>(0, out + OUT_MAP);
    hT_k<<<dim3(64, 8, 2), dim3(32, 8)>>>();
    attmma_k<<<dim3(16, 1, 8), 512, SM_TOTAL>>>(0);

    pool_k<<<512, 256>>>(x, pool1_W, pool1_b, out + OUT_GAT, 0);
    pool_k<<<512, 256>>>(x, pool1_W, pool1_b, out + OUT_GAT, 1);

    // layer 2
    gemm_k<<<dim3(32, 4, 1), 256>>>(x, a2_src, a2_dst, 1);
    rowstat_k<<<4096, 256>>>(1, out + OUT_MAP);
    hT_k<<<dim3(64, 8, 2), dim3(32, 8)>>>();
    attmma_k<<<dim3(16, 1, 8), 512, SM_TOTAL>>>(1);

    pool_k<<<512, 256>>>(x, pool2_W, pool2_b, out + OUT_GAT, 2);

    // head
    fc_part_k<<<dim3(16, 8), 256>>>(out + OUT_GAT, fc1_W, 0, 3 * Nn, FC1n);
    fc_reduce_k<<<8, 256>>>(fc1_b, 0, FC1n, Bsz * FC1n);
    ln_relu_k<<<2, 256>>>(0, out, ln1_g, ln1_b);

    fc_part_k<<<dim3(4, 8), 256>>>(out, fc2_W, 1, FC1n, FC2n);
    fc_reduce_k<<<2, 256>>>(fc2_b, 1, FC2n, Bsz * FC2n);
    ln_relu_k<<<2, 256>>>(1, out + OUT_FC, ln2_g, ln2_b);

    cls_k<<<1, 128>>>(out + OUT_FC, cls_W, cls_b, out + OUT_LOG);
}

// round 7
// speedup vs baseline: 1.2271x; 1.1934x over previous
#include <cuda_runtime.h>
#include <cuda_bf16.h>
#include <cuda_fp16.h>
#include <mma.h>
#include <math.h>
#include <stdint.h>

using namespace nvcuda;

// ---------------- problem constants ----------------
#define Bsz 2
#define Nn  2048
#define Dd  128
#define Hh  4
#define Ff  64
#define HF  256
#define FC1n 1024
#define FC2n 256

// output layout (f32)
#define OUT_GAT 0
#define OUT_FC  12288
#define OUT_LOG 12800
#define OUT_MAP 12804

#define EXP_BIAS 8.0f
#define EXP_BIAS_INV 2980.9579870417283f   // e^8

// ---------------- scratch ----------------
__device__ float g_wcat1[Dd * HF];
__device__ float g_wcat2[HF * HF];
__device__ float g_hproj[Bsz * Nn * HF];
__device__ float g_x1[Bsz * Nn * HF];
__device__ float g_x2[Bsz * Nn * HF];
__device__ float g_es[Bsz * Hh * Nn];
__device__ float g_ed[Bsz * Hh * Nn];
__device__ float g_inv[Bsz * Hh * Nn];
__device__ unsigned g_adjbits[Nn * 64];                      // 512 KB bitmask
__device__ __half g_hT[Bsz * HF * Nn];                       // h^T fp16
__device__ float g_fc1[Bsz * FC1n];
__device__ float g_y1[Bsz * FC1n];
__device__ float g_fc2[Bsz * FC2n];
__device__ float g_part[8 * Bsz * FC1n];

// ---------------- f32x2 helpers (SIMT proj GEMM) ----------------
__device__ __forceinline__ unsigned long long pack2(float x, float y) {
    unsigned long long r;
    asm("mov.b64 %0, {%1, %2};" : "=l"(r) : "r"(__float_as_uint(x)), "r"(__float_as_uint(y)));
    return r;
}
__device__ __forceinline__ unsigned long long rep2(float x) {
    unsigned long long r; unsigned u = __float_as_uint(x);
    asm("mov.b64 %0, {%1, %1};" : "=l"(r) : "r"(u));
    return r;
}
__device__ __forceinline__ void fma2(unsigned long long &d, unsigned long long a, unsigned long long b) {
    asm("fma.rn.f32x2 %0, %1, %2, %0;" : "+l"(d) : "l"(a), "l"(b));
}
__device__ __forceinline__ float2 unpk2(unsigned long long v) {
    float2 f; f.x = __uint_as_float((unsigned)v); f.y = __uint_as_float((unsigned)(v >> 32));
    return f;
}

// ---------------- cp.async helpers ----------------
__device__ __forceinline__ uint32_t smem_u32(const void* p) {
    uint32_t a;
    asm("{ .reg .u64 t; cvta.to.shared.u64 t, %1; cvt.u32.u64 %0, t; }" : "=r"(a) : "l"(p));
    return a;
}
#define CP16(saddr, gptr) asm volatile("cp.async.cg.shared.global [%0], [%1], 16;" :: "r"(saddr), "l"(gptr) : "memory")
#define CP_COMMIT() asm volatile("cp.async.commit_group;" ::: "memory")
#define CP_WAIT0()  asm volatile("cp.async.wait_group 0;" ::: "memory")

// ---------------- repack ----------------
__global__ void repack_k(const float* __restrict__ W1, const float* __restrict__ W2) {
    int t = blockIdx.x * blockDim.x + threadIdx.x;
    if (t < Hh * Dd * Ff) {
        int h = t / (Dd * Ff); int r = t % (Dd * Ff); int d = r / Ff; int f = r % Ff;
        g_wcat1[d * HF + h * Ff + f] = W1[t];
    }
    if (t < Hh * HF * Ff) {
        int h = t / (HF * Ff); int r = t % (HF * Ff); int k = r / Ff; int f = r % Ff;
        g_wcat2[k * HF + h * Ff + f] = W2[t];
    }
}

// ---------------- adj -> bitmask ----------------
__global__ void adjpack_k(const int* __restrict__ adj) {
    int w = (blockIdx.x * blockDim.x + threadIdx.x) >> 5;   // word index
    int lane = threadIdx.x & 31;
    int i = w >> 6, widx = w & 63;
    int a = adj[(long)i * Nn + widx * 32 + lane];
    unsigned m = __ballot_sync(0xffffffffu, a > 0);
    if (!lane) g_adjbits[w] = m;
}

// ---------------- SIMT projection GEMM + fused es/ed epilogue ----------------
__global__ void __launch_bounds__(256) gemm_k(const float* __restrict__ xin,
                                              const float* __restrict__ asrc,
                                              const float* __restrict__ adst, int mode) {
    const float *A, *B; float *C; int K, lda;
    if (mode == 0) { A = xin;  B = g_wcat1; C = g_hproj; K = Dd; lda = Dd; }
    else           { A = g_x1; B = g_wcat2; C = g_hproj; K = HF; lda = HF; }
    const int ldb = HF, ldc = HF;

    __shared__ float As[16][128];
    __shared__ float Bs[16][64];
    __shared__ float esp[16][129];
    __shared__ float edp[16][129];
    __shared__ float av[64], dv[64];

    int tid = threadIdx.x;
    int head = blockIdx.y;
    int m0 = blockIdx.x * 128, n0 = head * 64;
    int tx = tid & 15, ty = tid >> 4;
    int a_r = tid >> 2, a_k = (tid & 3) << 2;
    int b_k = tid >> 4, b_n = (tid & 15) << 2;

    if (tid < 64)       av[tid] = asrc[n0 + tid];
    else if (tid < 128) dv[tid - 64] = adst[n0 + tid - 64];

    const float* Ap0 = A + (long)(m0 + a_r) * lda + a_k;
    const float* Ap1 = Ap0 + (long)64 * lda;
    const float* Bp  = B + (long)b_k * ldb + n0 + b_n;

    unsigned long long acc[4][4];
#pragma unroll
    for (int i = 0; i < 4; i++)
#pragma unroll
        for (int j = 0; j < 4; j++) acc[i][j] = 0ULL;

    float4 av0 = *(const float4*)Ap0;
    float4 av1 = *(const float4*)Ap1;
    float4 bv  = *(const float4*)Bp;

    for (int k0 = 0; k0 < K; k0 += 16) {
        __syncthreads();
        As[a_k + 0][a_r] = av0.x; As[a_k + 1][a_r] = av0.y;
        As[a_k + 2][a_r] = av0.z; As[a_k + 3][a_r] = av0.w;
        As[a_k + 0][a_r + 64] = av1.x; As[a_k + 1][a_r + 64] = av1.y;
        As[a_k + 2][a_r + 64] = av1.z; As[a_k + 3][a_r + 64] = av1.w;
        *(float4*)&Bs[b_k][b_n] = bv;
        __syncthreads();
        if (k0 + 16 < K) {
            av0 = *(const float4*)(Ap0 + k0 + 16);
            av1 = *(const float4*)(Ap1 + k0 + 16);
            bv  = *(const float4*)(Bp + (long)(k0 + 16) * ldb);
        }
#pragma unroll
        for (int kk = 0; kk < 16; kk++) {
            float4 aA = *(const float4*)&As[kk][ty * 8];
            float4 aB = *(const float4*)&As[kk][ty * 8 + 4];
            float4 b4 = *(const float4*)&Bs[kk][tx * 4];
            unsigned long long au[4], bu[4];
            au[0] = pack2(aA.x, aA.y); au[1] = pack2(aA.z, aA.w);
            au[2] = pack2(aB.x, aB.y); au[3] = pack2(aB.z, aB.w);
            bu[0] = rep2(b4.x); bu[1] = rep2(b4.y); bu[2] = rep2(b4.z); bu[3] = rep2(b4.w);
#pragma unroll
            for (int ip = 0; ip < 4; ip++)
#pragma unroll
                for (int j = 0; j < 4; j++) fma2(acc[ip][j], au[ip], bu[j]);
        }
    }

    float as0 = av[tx * 4], as1 = av[tx * 4 + 1], as2 = av[tx * 4 + 2], as3 = av[tx * 4 + 3];
    float ad0 = dv[tx * 4], ad1 = dv[tx * 4 + 1], ad2 = dv[tx * 4 + 2], ad3 = dv[tx * 4 + 3];

#pragma unroll
    for (int ip = 0; ip < 4; ip++) {
        float2 c0 = unpk2(acc[ip][0]), c1 = unpk2(acc[ip][1]);
        float2 c2 = unpk2(acc[ip][2]), c3 = unpk2(acc[ip][3]);
        float4 lo = make_float4(c0.x, c1.x, c2.x, c3.x);
        float4 hi = make_float4(c0.y, c1.y, c2.y, c3.y);
        int rl = ty * 8 + 2 * ip;
        esp[tx][rl]     = lo.x * as0 + lo.y * as1 + lo.z * as2 + lo.w * as3;
        edp[tx][rl]     = lo.x * ad0 + lo.y * ad1 + lo.z * ad2 + lo.w * ad3;
        esp[tx][rl + 1] = hi.x * as0 + hi.y * as1 + hi.z * as2 + hi.w * as3;
        edp[tx][rl + 1] = hi.x * ad0 + hi.y * ad1 + hi.z * ad2 + hi.w * ad3;
        int r0 = m0 + rl;
        *(float4*)&C[(long)r0 * ldc + n0 + tx * 4] = lo;
        *(float4*)&C[(long)(r0 + 1) * ldc + n0 + tx * 4] = hi;
    }
    __syncthreads();
    {
        int row = tid & 127, which = tid >> 7;
        const float (*src)[129] = which ? edp : esp;
        float s = 0.f;
#pragma unroll
        for (int t = 0; t < 16; t++) s += src[t][row];
        int r = m0 + row;
        int bb = r >> 11, n = r & 2047;
        int idx = (((bb << 2) + head) << 11) | n;
        if (which) g_ed[idx] = s; else g_es[idx] = s;
    }
}

// ---------------- row stats v2: warp-pair per head, 2 barriers ----------------
__global__ void __launch_bounds__(256) rowstat_k(int layer, float* __restrict__ omap)
{
    __shared__ unsigned sadj[64];
    __shared__ float hsum[8];
    __shared__ float smap[4][2048];

    int bi = blockIdx.x;
    int b = bi >> 11, i = bi & 2047;
    int tid = threadIdx.x, lane = tid & 31, wid = tid >> 5;
    int h = wid >> 1, q = wid & 1;

    if (tid < 64) sadj[tid] = g_adjbits[i * 64 + tid];
    __syncthreads();

    int ro = ((b << 2) + h) << 11;
    float esi = g_es[ro + i];
    const float4* edv = (const float4*)(g_ed + ro + q * 1024);

    float p[8][4];
    float lsum = 0.f;
#pragma unroll
    for (int k = 0; k < 8; k++) {
        float4 e4 = edv[lane + 32 * k];
        int j0 = q * 1024 + (lane + 32 * k) * 4;
        unsigned nib = (sadj[j0 >> 5] >> (j0 & 31)) & 0xFu;
        float ev[4] = {e4.x, e4.y, e4.z, e4.w};
#pragma unroll
        for (int u = 0; u < 4; u++) {
            float s = esi + ev[u];
            float e = fmaxf(s, 0.2f * s);
            float pe = __expf(e);
            pe = ((nib >> u) & 1u) ? pe : 0.f;
            p[k][u] = pe;
            lsum += pe;
        }
    }
#pragma unroll
    for (int o = 16; o; o >>= 1) lsum += __shfl_xor_sync(0xffffffffu, lsum, o);
    if (!lane) hsum[wid] = lsum;
    __syncthreads();

    float inv = 1.f / (hsum[h * 2] + hsum[h * 2 + 1]);
    if (!lane && !q) g_inv[ro + i] = inv;
    float iv = 0.125f * inv;

#pragma unroll
    for (int k = 0; k < 8; k++) {
        float4 m;
        m.x = p[k][0] * iv; m.y = p[k][1] * iv;
        m.z = p[k][2] * iv; m.w = p[k][3] * iv;
        *(float4*)&smap[h][q * 1024 + (lane + 32 * k) * 4] = m;
    }
    __syncthreads();

    float4* mrow = (float4*)(omap + ((long)bi << 11));
#pragma unroll
    for (int t = 0; t < 2; t++) {
        int j4 = tid + 256 * t;
        float4 a = *(float4*)&smap[0][j4 * 4];
        float4 c = *(float4*)&smap[1][j4 * 4];
        float4 d = *(float4*)&smap[2][j4 * 4];
        float4 e = *(float4*)&smap[3][j4 * 4];
        float4 r;
        r.x = a.x + c.x + d.x + e.x; r.y = a.y + c.y + d.y + e.y;
        r.z = a.z + c.z + d.z + e.z; r.w = a.w + c.w + d.w + e.w;
        if (layer) {
            float4 o = mrow[j4];
            r.x += o.x; r.y += o.y; r.z += o.z; r.w += o.w;
        }
        mrow[j4] = r;
    }
}

// ---------------- transpose hproj -> hT fp16 ----------------
__global__ void hT_k() {
    __shared__ float t[32][33];
    int b = blockIdx.z;
    int j0 = blockIdx.x * 32, c0 = blockIdx.y * 32;
    int tx = threadIdx.x, ty = threadIdx.y;
#pragma unroll
    for (int i = 0; i < 4; i++) {
        int j = j0 + ty + 8 * i;
        t[ty + 8 * i][tx] = g_hproj[((long)b * Nn + j) * HF + c0 + tx];
    }
    __syncthreads();
#pragma unroll
    for (int i = 0; i < 4; i++) {
        int c = c0 + ty + 8 * i;
        long o = ((long)b * HF + c) * Nn + j0 + tx;
        g_hT[o] = __float2half_rn(t[tx][ty + 8 * i]);
    }
}

// ---------------- fused att-gen + wmma GEMM (fp16 2-term) ----------------
// smem: A stage0 (hi 18432 | lo 18432) | A stage1 | B stage0 9216 | B stage1 9216
#define A_LDM 72
#define SA_LO  18432
#define A_ST   36864
#define SB_OFF 73728
#define SB_ST  9216
#define SM_TOTAL 92160

__device__ __forceinline__ void gen_chunk(uint32_t sb, int stage, int c,
    float esi, const unsigned* __restrict__ awp, int bshift, uint32_t genoff, long edbase)
{
    unsigned bits = awp[c * 2] >> bshift;
    const float4* e4p = (const float4*)(g_ed + edbase + (long)c * 64);
    uint32_t ah = sb + stage * A_ST + genoff;
    uint32_t al = ah + SA_LO;
    unsigned uhi[8], ulo[8];
#pragma unroll
    for (int g = 0; g < 4; g++) {
        float4 e4 = e4p[g];
        float ev[4] = {e4.x, e4.y, e4.z, e4.w};
        float pv[4];
#pragma unroll
        for (int u = 0; u < 4; u++) {
            float s = esi + ev[u];
            float lk = fmaxf(s, 0.2f * s);
            float p = __expf(lk - EXP_BIAS);
            if (!((bits >> (g * 4 + u)) & 1u)) p = 0.f;
            pv[u] = p;
        }
        __half2 h01 = __floats2half2_rn(pv[0], pv[1]);
        __half2 h23 = __floats2half2_rn(pv[2], pv[3]);
        float r0 = pv[0] - __half2float(__low2half(h01));
        float r1 = pv[1] - __half2float(__high2half(h01));
        float r2 = pv[2] - __half2float(__low2half(h23));
        float r3 = pv[3] - __half2float(__high2half(h23));
        __half2 l01 = __floats2half2_rn(r0, r1);
        __half2 l23 = __floats2half2_rn(r2, r3);
        uhi[g * 2 + 0] = *(unsigned*)&h01; uhi[g * 2 + 1] = *(unsigned*)&h23;
        ulo[g * 2 + 0] = *(unsigned*)&l01; ulo[g * 2 + 1] = *(unsigned*)&l23;
    }
    asm volatile("st.shared.v4.b32 [%0], {%1,%2,%3,%4};" :: "r"(ah),
                 "r"(uhi[0]), "r"(uhi[1]), "r"(uhi[2]), "r"(uhi[3]) : "memory");
    asm volatile("st.shared.v4.b32 [%0], {%1,%2,%3,%4};" :: "r"(ah + 16),
                 "r"(uhi[4]), "r"(uhi[5]), "r"(uhi[6]), "r"(uhi[7]) : "memory");
    asm volatile("st.shared.v4.b32 [%0], {%1,%2,%3,%4};" :: "r"(al),
                 "r"(ulo[0]), "r"(ulo[1]), "r"(ulo[2]), "r"(ulo[3]) : "memory");
    asm volatile("st.shared.v4.b32 [%0], {%1,%2,%3,%4};" :: "r"(al + 16),
                 "r"(ulo[4]), "r"(ulo[5]), "r"(ulo[6]), "r"(ulo[7]) : "memory");
}

__global__ void __launch_bounds__(512) attmma_k(int layer) {
    extern __shared__ char smem[];
    uint32_t sb = smem_u32(smem);
    int tid = threadIdx.x, wid = tid >> 5;
    int z = blockIdx.z;
    int b = z >> 2;
    int m0 = blockIdx.x * 128;
    int row0 = (wid >> 1) * 16;
    int nh = (wid & 1) * 32;

    // gen constants
    int gr = tid >> 2, q4 = tid & 3;
    float esi = g_es[(long)z * Nn + m0 + gr];
    const unsigned* awp = g_adjbits + (long)(m0 + gr) * 64 + (q4 >> 1);
    int bshift = (q4 & 1) * 16;
    uint32_t genoff = gr * 144 + q4 * 32;
    long edbase = (long)z * Nn + q4 * 16;

    // B cp.async mapping (64 rows x 128B per chunk, 512 threads x 16B)
    int brow = tid >> 3, bseg = tid & 7;
    uint32_t bso = brow * 144 + bseg * 16;
    long bgo = ((long)z * 64 + brow) * Nn + bseg * 8;

    wmma::fragment<wmma::accumulator, 16, 16, 16, float> acc[2];
    wmma::fill_fragment(acc[0], 0.f);
    wmma::fill_fragment(acc[1], 0.f);

    gen_chunk(sb, 0, 0, esi, awp, bshift, genoff, edbase);
    CP16(sb + SB_OFF + bso, g_hT + bgo);
    CP_COMMIT();

    for (int c = 0; c < 32; ++c) {
        int cur = c & 1;
        CP_WAIT0();
        __syncthreads();

        if (c + 1 < 32) {
            CP16(sb + SB_OFF + (cur ^ 1) * SB_ST + bso, g_hT + bgo + (c + 1) * 64);
            CP_COMMIT();
        }

        const char* sA = smem + cur * A_ST;
        const __half* Ah = (const __half*)sA;
        const __half* Al = (const __half*)(sA + SA_LO);
        const __half* Bh = (const __half*)(smem + SB_OFF + cur * SB_ST);

#pragma unroll
        for (int kk = 0; kk < 4; kk++) {
            wmma::fragment<wmma::matrix_a, 16, 16, 16, __half, wmma::row_major> fa_h, fa_l;
            wmma::load_matrix_sync(fa_h, Ah + row0 * A_LDM + kk * 16, A_LDM);
            wmma::load_matrix_sync(fa_l, Al + row0 * A_LDM + kk * 16, A_LDM);
#pragma unroll
            for (int n = 0; n < 2; n++) {
                wmma::fragment<wmma::matrix_b, 16, 16, 16, __half, wmma::col_major> fb;
                wmma::load_matrix_sync(fb, Bh + (nh + n * 16) * A_LDM + kk * 16, A_LDM);
                wmma::mma_sync(acc[n], fa_h, fb, acc[n]);
                wmma::mma_sync(acc[n], fa_l, fb, acc[n]);
            }
        }

        if (c + 1 < 32)
            gen_chunk(sb, cur ^ 1, c + 1, esi, awp, bshift, genoff, edbase);
    }

    float* Cs = (float*)smem;
    wmma::store_matrix_sync(Cs + row0 * A_LDM + nh,      acc[0], A_LDM, wmma::mem_row_major);
    wmma::store_matrix_sync(Cs + row0 * A_LDM + nh + 16, acc[1], A_LDM, wmma::mem_row_major);
    __syncthreads();

    float* C = (layer == 0 ? g_x1 : g_x2) + ((long)(b * Nn + m0) * HF + (z & 3) * 64);
    const float* invp = g_inv + (long)z * Nn + m0;
#pragma unroll
    for (int i = 0; i < 4; i++) {
        int q = tid + 512 * i;
        int row = q >> 4, cg = q & 15;
        float sc = invp[row] * EXP_BIAS_INV;
        float4 v = *(float4*)&Cs[row * A_LDM + cg * 4];
        v.x = fmaxf(v.x, 0.f) * sc; v.y = fmaxf(v.y, 0.f) * sc;
        v.z = fmaxf(v.z, 0.f) * sc; v.w = fmaxf(v.w, 0.f) * sc;
        *(float4*)(C + (long)row * HF + cg * 4) = v;
    }
}

// ---------------- pools ----------------
__global__ void pool_k(const float* __restrict__ xparam,
                       const float* __restrict__ w, const float* __restrict__ wb,
                       float* __restrict__ out, int mode)
{
    int warp = (blockIdx.x * 256 + threadIdx.x) >> 5;
    int lane = threadIdx.x & 31;
    const float* rows; int rowlen, off; float scale;
    if (mode == 0)      { rows = xparam; rowlen = Dd; off = 0;      scale = 1.f / 128.f; }
    else if (mode == 1) { rows = g_x1;   rowlen = HF; off = Nn;     scale = 1.f; }
    else                { rows = g_x2;   rowlen = HF; off = 2 * Nn; scale = 1.f; }
    const float* rp = rows + (long)warp * rowlen;
    float acc = 0.f;
    if (mode == 0) { for (int c = lane; c < rowlen; c += 32) acc += rp[c]; }
    else           { for (int c = lane; c < rowlen; c += 32) acc += rp[c] * w[c]; }
#pragma unroll
    for (int o = 16; o; o >>= 1) acc += __shfl_xor_sync(0xffffffffu, acc, o);
    if (!lane) {
        int b = warp >> 11, n = warp & 2047;
        out[(long)b * (3 * Nn) + off + n] = acc * scale + (mode == 0 ? 0.f : wb[0]);
    }
}

// ---------------- MLP head ----------------
__global__ void __launch_bounds__(256) fc_part_k(const float* __restrict__ in_param,
                                                 const float* __restrict__ W,
                                                 int use_y1, int IC, int OC)
{
    __shared__ float red0[256], red1[256];
    const float* in = use_y1 ? (const float*)g_y1 : in_param;
    int tid = threadIdx.x;
    int cl = tid & 63, ks = tid >> 6;
    int c = blockIdx.x * 64 + cl;
    int kchunk = IC >> 5;
    int k0 = (blockIdx.y * 4 + ks) * kchunk;
    const float* in0 = in;
    const float* in1 = in + IC;
    float a0 = 0.f, a1 = 0.f;
#pragma unroll 4
    for (int k = k0; k < k0 + kchunk; k++) {
        float w = W[(long)k * OC + c];
        a0 += in0[k] * w;
        a1 += in1[k] * w;
    }
    red0[tid] = a0; red1[tid] = a1;
    __syncthreads();
    if (ks == 0) {
        a0 = red0[tid] + red0[tid + 64] + red0[tid + 128] + red0[tid + 192];
        a1 = red1[tid] + red1[tid + 64] + red1[tid + 128] + red1[tid + 192];
        long base = (long)blockIdx.y * (2 * OC);
        g_part[base + c] = a0;
        g_part[base + OC + c] = a1;
    }
}

__global__ void fc_reduce_k(const float* __restrict__ bias, int mode, int OC, int tot)
{
    int t = blockIdx.x * 256 + threadIdx.x;
    if (t >= tot) return;
    float s = bias[t % OC];
#pragma unroll
    for (int p = 0; p < 8; p++) s += g_part[(long)p * tot + t];
    if (mode == 0) g_fc1[t] = s; else g_fc2[t] = s;
}

__global__ void ln_relu_k(int mode, float* __restrict__ out_param,
                          const float* __restrict__ g, const float* __restrict__ be)
{
    __shared__ float r1[8], r2[8];
    int C = (mode == 0) ? FC1n : FC2n;
    const float* in = (mode == 0) ? (const float*)g_fc1 : (const float*)g_fc2;
    float* outp = (mode == 0) ? (float*)g_y1 : out_param;
    int b = blockIdx.x, tid = threadIdx.x, lane = tid & 31, wid = tid >> 5;
    const float* row = in + (long)b * C;
    float s = 0.f, ss = 0.f;
    for (int c = tid; c < C; c += 256) { float v = row[c]; s += v; ss += v * v; }
#pragma unroll
    for (int o = 16; o; o >>= 1) {
        s  += __shfl_xor_sync(0xffffffffu, s, o);
        ss += __shfl_xor_sync(0xffffffffu, ss, o);
    }
    if (!lane) { r1[wid] = s; r2[wid] = ss; }
    __syncthreads();
    s = 0.f; ss = 0.f;
#pragma unroll
    for (int w = 0; w < 8; w++) { s += r1[w]; ss += r2[w]; }
    float m = s / C;
    float var = ss / C - m * m;
    float r = rsqrtf(var + 1e-5f);
    for (int c = tid; c < C; c += 256) {
        float v = row[c];
        outp[(long)b * C + c] = fmaxf((v - m) * r * g[c] + be[c], 0.f);
    }
}

__global__ void cls_k(const float* __restrict__ feat, const float* __restrict__ W,
                      const float* __restrict__ wb, float* __restrict__ out)
{
    int tid = threadIdx.x;
    if (tid >= 128) return;
    int lane = tid & 31, w = tid >> 5;
    int b = w >> 1, l = w & 1;
    float acc = 0.f;
    for (int k = lane; k < FC2n; k += 32) acc += feat[b * FC2n + k] * W[k * 2 + l];
#pragma unroll
    for (int o = 16; o; o >>= 1) acc += __shfl_xor_sync(0xffffffffu, acc, o);
    if (!lane) out[b * 2 + l] = acc + wb[l];
}

// ---------------- host launcher ----------------
extern "C" void kernel_launch(void* const* d_in, const int* in_sizes, int n_in,
                              void* d_out, int out_size)
{
    const float* x        = (const float*)d_in[0];
    const int*   adj      = (const int*)  d_in[1];
    const float* a1_src   = (const float*)d_in[4];
    const float* a1_dst   = (const float*)d_in[5];
    const float* pool1_W  = (const float*)d_in[6];
    const float* pool1_b  = (const float*)d_in[7];
    const float* a2_src   = (const float*)d_in[9];
    const float* a2_dst   = (const float*)d_in[10];
    const float* pool2_W  = (const float*)d_in[11];
    const float* pool2_b  = (const float*)d_in[12];
    const float* fc1_W    = (const float*)d_in[13];
    const float* fc1_b    = (const float*)d_in[14];
    const float* ln1_g    = (const float*)d_in[15];
    const float* ln1_b    = (const float*)d_in[16];
    const float* fc2_W    = (const float*)d_in[17];
    const float* fc2_b    = (const float*)d_in[18];
    const float* ln2_g    = (const float*)d_in[19];
    const float* ln2_b    = (const float*)d_in[20];
    const float* cls_W    = (const float*)d_in[21];
    const float* cls_b    = (const float*)d_in[22];

    float* out = (float*)d_out;

    cudaFuncSetAttribute(attmma_k, cudaFuncAttributeMaxDynamicSharedMemorySize, SM_TOTAL);

    repack_k<<<256, 256>>>((const float*)d_in[3], (const float*)d_in[8]);
    adjpack_k<<<16384, 256>>>(adj);

    // layer 1
    gemm_k<<<dim3(32, 4, 1), 256>>>(x, a1_src, a1_dst, 0);
    rowstat_k<<<4096, 256>>>(0, out + OUT_MAP);
    hT_k<<<dim3(64, 8, 2), dim3(32, 8)>>>();
    attmma_k<<<dim3(16, 1, 8), 512, SM_TOTAL>>>(0);

    pool_k<<<512, 256>>>(x, pool1_W, pool1_b, out + OUT_GAT, 0);
    pool_k<<<512, 256>>>(x, pool1_W, pool1_b, out + OUT_GAT, 1);

    // layer 2
    gemm_k<<<dim3(32, 4, 1), 256>>>(x, a2_src, a2_dst, 1);
    rowstat_k<<<4096, 256>>>(1, out + OUT_MAP);
    hT_k<<<dim3(64, 8, 2), dim3(32, 8)>>>();
    attmma_k<<<dim3(16, 1, 8), 512, SM_TOTAL>>>(1);

    pool_k<<<512, 256>>>(x, pool2_W, pool2_b, out + OUT_GAT, 2);

    // head
    fc_part_k<<<dim3(16, 8), 256>>>(out + OUT_GAT, fc1_W, 0, 3 * Nn, FC1n);
    fc_reduce_k<<<8, 256>>>(fc1_b, 0, FC1n, Bsz * FC1n);
    ln_relu_k<<<2, 256>>>(0, out, ln1_g, ln1_b);

    fc_part_k<<<dim3(4, 8), 256>>>(out, fc2_W, 1, FC1n, FC2n);
    fc_reduce_k<<<2, 256>>>(fc2_b, 1, FC2n, Bsz * FC2n);
    ln_relu_k<<<2, 256>>>(1, out + OUT_FC, ln2_g, ln2_b);

    cls_k<<<1, 128>>>(out + OUT_FC, cls_W, cls_b, out + OUT_LOG);
}

// round 8
// speedup vs baseline: 1.3198x; 1.0755x over previous
#include <cuda_runtime.h>
#include <cuda_bf16.h>
#include <cuda_fp16.h>
#include <mma.h>
#include <math.h>
#include <stdint.h>

using namespace nvcuda;

// ---------------- problem constants ----------------
#define Bsz 2
#define Nn  2048
#define Dd  128
#define Hh  4
#define Ff  64
#define HF  256
#define FC1n 1024
#define FC2n 256

// output layout (f32)
#define OUT_GAT 0
#define OUT_FC  12288
#define OUT_LOG 12800
#define OUT_MAP 12804

#define EXP_BIAS 8.0f
#define EXP_BIAS_INV 2980.9579870417283f   // e^8

// ---------------- scratch ----------------
__device__ float g_wcat1[Dd * HF];
__device__ float g_wcat2[HF * HF];
__device__ float g_x1[Bsz * Nn * HF];
__device__ float g_x2[Bsz * Nn * HF];
__device__ float g_es[Bsz * Hh * Nn];
__device__ float g_ed[Bsz * Hh * Nn];
__device__ float g_inv[Bsz * Hh * Nn];
__device__ unsigned g_adjbits[Nn * 64];                      // 512 KB bitmask
__device__ __half g_hT[Bsz * HF * Nn];                       // h^T fp16
__device__ float g_fc1[Bsz * FC1n];
__device__ float g_y1[Bsz * FC1n];
__device__ float g_fc2[Bsz * FC2n];
__device__ float g_part[8 * Bsz * FC1n];

// ---------------- f32x2 helpers (SIMT proj GEMM) ----------------
__device__ __forceinline__ unsigned long long pack2(float x, float y) {
    unsigned long long r;
    asm("mov.b64 %0, {%1, %2};" : "=l"(r) : "r"(__float_as_uint(x)), "r"(__float_as_uint(y)));
    return r;
}
__device__ __forceinline__ unsigned long long rep2(float x) {
    unsigned long long r; unsigned u = __float_as_uint(x);
    asm("mov.b64 %0, {%1, %1};" : "=l"(r) : "r"(u));
    return r;
}
__device__ __forceinline__ void fma2(unsigned long long &d, unsigned long long a, unsigned long long b) {
    asm("fma.rn.f32x2 %0, %1, %2, %0;" : "+l"(d) : "l"(a), "l"(b));
}
__device__ __forceinline__ float2 unpk2(unsigned long long v) {
    float2 f; f.x = __uint_as_float((unsigned)v); f.y = __uint_as_float((unsigned)(v >> 32));
    return f;
}

// ---------------- cp.async helpers ----------------
__device__ __forceinline__ uint32_t smem_u32(const void* p) {
    uint32_t a;
    asm("{ .reg .u64 t; cvta.to.shared.u64 t, %1; cvt.u32.u64 %0, t; }" : "=r"(a) : "l"(p));
    return a;
}
#define CP16(saddr, gptr) asm volatile("cp.async.cg.shared.global [%0], [%1], 16;" :: "r"(saddr), "l"(gptr) : "memory")
#define CP_COMMIT() asm volatile("cp.async.commit_group;" ::: "memory")
#define CP_WAIT0()  asm volatile("cp.async.wait_group 0;" ::: "memory")

// ---------------- repack ----------------
__global__ void repack_k(const float* __restrict__ W1, const float* __restrict__ W2) {
    int t = blockIdx.x * blockDim.x + threadIdx.x;
    if (t < Hh * Dd * Ff) {
        int h = t / (Dd * Ff); int r = t % (Dd * Ff); int d = r / Ff; int f = r % Ff;
        g_wcat1[d * HF + h * Ff + f] = W1[t];
    }
    if (t < Hh * HF * Ff) {
        int h = t / (HF * Ff); int r = t % (HF * Ff); int k = r / Ff; int f = r % Ff;
        g_wcat2[k * HF + h * Ff + f] = W2[t];
    }
}

// ---------------- adj -> bitmask ----------------
__global__ void adjpack_k(const int* __restrict__ adj) {
    int w = (blockIdx.x * blockDim.x + threadIdx.x) >> 5;   // word index
    int lane = threadIdx.x & 31;
    int i = w >> 6, widx = w & 63;
    int a = adj[(long)i * Nn + widx * 32 + lane];
    unsigned m = __ballot_sync(0xffffffffu, a > 0);
    if (!lane) g_adjbits[w] = m;
}

// ---------------- SIMT projection GEMM + fused es/ed + fused fp16 hT store ----------------
// blockIdx.y = head. CTA: rows [m0,m0+128) x head's 64 F-cols. No fp32 h is ever stored;
// the tile goes out only as (a) es/ed dots, (b) transposed fp16 into g_hT.
__global__ void __launch_bounds__(256) gemm_k(const float* __restrict__ xin,
                                              const float* __restrict__ asrc,
                                              const float* __restrict__ adst, int mode) {
    const float *A, *B; int K, lda;
    if (mode == 0) { A = xin;  B = g_wcat1; K = Dd; lda = Dd; }
    else           { A = g_x1; B = g_wcat2; K = HF; lda = HF; }
    const int ldb = HF;

    __shared__ float As[16][128];
    __shared__ float Bs[16][64];
    __shared__ float esp[16][129];
    __shared__ float edp[16][129];
    __shared__ float av[64], dv[64];
    __shared__ __half t16[64][136];

    int tid = threadIdx.x;
    int head = blockIdx.y;
    int m0 = blockIdx.x * 128, n0 = head * 64;
    int tx = tid & 15, ty = tid >> 4;
    int a_r = tid >> 2, a_k = (tid & 3) << 2;
    int b_k = tid >> 4, b_n = (tid & 15) << 2;

    if (tid < 64)       av[tid] = asrc[n0 + tid];
    else if (tid < 128) dv[tid - 64] = adst[n0 + tid - 64];

    const float* Ap0 = A + (long)(m0 + a_r) * lda + a_k;
    const float* Ap1 = Ap0 + (long)64 * lda;
    const float* Bp  = B + (long)b_k * ldb + n0 + b_n;

    unsigned long long acc[4][4];
#pragma unroll
    for (int i = 0; i < 4; i++)
#pragma unroll
        for (int j = 0; j < 4; j++) acc[i][j] = 0ULL;

    float4 av0 = *(const float4*)Ap0;
    float4 av1 = *(const float4*)Ap1;
    float4 bv  = *(const float4*)Bp;

    for (int k0 = 0; k0 < K; k0 += 16) {
        __syncthreads();
        As[a_k + 0][a_r] = av0.x; As[a_k + 1][a_r] = av0.y;
        As[a_k + 2][a_r] = av0.z; As[a_k + 3][a_r] = av0.w;
        As[a_k + 0][a_r + 64] = av1.x; As[a_k + 1][a_r + 64] = av1.y;
        As[a_k + 2][a_r + 64] = av1.z; As[a_k + 3][a_r + 64] = av1.w;
        *(float4*)&Bs[b_k][b_n] = bv;
        __syncthreads();
        if (k0 + 16 < K) {
            av0 = *(const float4*)(Ap0 + k0 + 16);
            av1 = *(const float4*)(Ap1 + k0 + 16);
            bv  = *(const float4*)(Bp + (long)(k0 + 16) * ldb);
        }
#pragma unroll
        for (int kk = 0; kk < 16; kk++) {
            float4 aA = *(const float4*)&As[kk][ty * 8];
            float4 aB = *(const float4*)&As[kk][ty * 8 + 4];
            float4 b4 = *(const float4*)&Bs[kk][tx * 4];
            unsigned long long au[4], bu[4];
            au[0] = pack2(aA.x, aA.y); au[1] = pack2(aA.z, aA.w);
            au[2] = pack2(aB.x, aB.y); au[3] = pack2(aB.z, aB.w);
            bu[0] = rep2(b4.x); bu[1] = rep2(b4.y); bu[2] = rep2(b4.z); bu[3] = rep2(b4.w);
#pragma unroll
            for (int ip = 0; ip < 4; ip++)
#pragma unroll
                for (int j = 0; j < 4; j++) fma2(acc[ip][j], au[ip], bu[j]);
        }
    }

    float as0 = av[tx * 4], as1 = av[tx * 4 + 1], as2 = av[tx * 4 + 2], as3 = av[tx * 4 + 3];
    float ad0 = dv[tx * 4], ad1 = dv[tx * 4 + 1], ad2 = dv[tx * 4 + 2], ad3 = dv[tx * 4 + 3];

#pragma unroll
    for (int ip = 0; ip < 4; ip++) {
        float2 c0 = unpk2(acc[ip][0]), c1 = unpk2(acc[ip][1]);
        float2 c2 = unpk2(acc[ip][2]), c3 = unpk2(acc[ip][3]);
        float4 lo = make_float4(c0.x, c1.x, c2.x, c3.x);
        float4 hi = make_float4(c0.y, c1.y, c2.y, c3.y);
        int rl = ty * 8 + 2 * ip;
        esp[tx][rl]     = lo.x * as0 + lo.y * as1 + lo.z * as2 + lo.w * as3;
        edp[tx][rl]     = lo.x * ad0 + lo.y * ad1 + lo.z * ad2 + lo.w * ad3;
        esp[tx][rl + 1] = hi.x * as0 + hi.y * as1 + hi.z * as2 + hi.w * as3;
        edp[tx][rl + 1] = hi.x * ad0 + hi.y * ad1 + hi.z * ad2 + hi.w * ad3;
        t16[tx * 4 + 0][rl]     = __float2half_rn(lo.x);
        t16[tx * 4 + 1][rl]     = __float2half_rn(lo.y);
        t16[tx * 4 + 2][rl]     = __float2half_rn(lo.z);
        t16[tx * 4 + 3][rl]     = __float2half_rn(lo.w);
        t16[tx * 4 + 0][rl + 1] = __float2half_rn(hi.x);
        t16[tx * 4 + 1][rl + 1] = __float2half_rn(hi.y);
        t16[tx * 4 + 2][rl + 1] = __float2half_rn(hi.z);
        t16[tx * 4 + 3][rl + 1] = __float2half_rn(hi.w);
    }
    __syncthreads();
    {
        int row = tid & 127, which = tid >> 7;
        const float (*src)[129] = which ? edp : esp;
        float s = 0.f;
#pragma unroll
        for (int t = 0; t < 16; t++) s += src[t][row];
        int r = m0 + row;
        int bb = r >> 11, n = r & 2047;
        int idx = (((bb << 2) + head) << 11) | n;
        if (which) g_ed[idx] = s; else g_es[idx] = s;
    }
    {
        int bb = m0 >> 11, jr = m0 & 2047;
#pragma unroll
        for (int it = 0; it < 4; it++) {
            int q = tid + 256 * it;       // 1024 uint4 = 64 cols x 128 rows fp16
            int c = q >> 4, seg = q & 15;
            uint4 v = *(uint4*)&t16[c][seg * 8];
            *(uint4*)&g_hT[((long)(bb * HF + n0 + c)) * Nn + jr + seg * 8] = v;
        }
    }
}

// ---------------- row stats v3: thread owns 8 j across all 4 heads, map in registers ----------------
__global__ void __launch_bounds__(256) rowstat_k(int layer, float* __restrict__ omap)
{
    __shared__ float red[8][4];
    int bi = blockIdx.x;
    int b = bi >> 11, i = bi & 2047;
    int tid = threadIdx.x, lane = tid & 31, wid = tid >> 5;
    int j0 = tid * 8;
    unsigned bits = (g_adjbits[i * 64 + (j0 >> 5)] >> (j0 & 31)) & 0xFFu;
    long ro = (long)(b << 2) << 11;

    float p[4][8], ls[4];
#pragma unroll
    for (int h = 0; h < 4; h++) {
        float esi = g_es[ro + (h << 11) + i];
        const float4* edv = (const float4*)(g_ed + ro + (h << 11) + j0);
        float4 e0 = edv[0], e1 = edv[1];
        float ev[8] = {e0.x, e0.y, e0.z, e0.w, e1.x, e1.y, e1.z, e1.w};
        float s = 0.f;
#pragma unroll
        for (int u = 0; u < 8; u++) {
            float t = esi + ev[u];
            float lk = fmaxf(t, 0.2f * t);
            float pe = __expf(lk);
            pe = ((bits >> u) & 1u) ? pe : 0.f;
            p[h][u] = pe;
            s += pe;
        }
        ls[h] = s;
    }
#pragma unroll
    for (int o = 16; o; o >>= 1) {
#pragma unroll
        for (int h = 0; h < 4; h++) ls[h] += __shfl_xor_sync(0xffffffffu, ls[h], o);
    }
    if (!lane) {
        red[wid][0] = ls[0]; red[wid][1] = ls[1];
        red[wid][2] = ls[2]; red[wid][3] = ls[3];
    }
    __syncthreads();
    float inv0, inv1, inv2, inv3;
    {
        float s0 = 0.f, s1 = 0.f, s2 = 0.f, s3 = 0.f;
#pragma unroll
        for (int w = 0; w < 8; w++) {
            s0 += red[w][0]; s1 += red[w][1]; s2 += red[w][2]; s3 += red[w][3];
        }
        inv0 = 0.125f / s0; inv1 = 0.125f / s1;
        inv2 = 0.125f / s2; inv3 = 0.125f / s3;
    }
    if (tid == 0) {
        g_inv[ro + i]               = inv0 * 8.f;
        g_inv[ro + (1 << 11) + i]   = inv1 * 8.f;
        g_inv[ro + (2 << 11) + i]   = inv2 * 8.f;
        g_inv[ro + (3 << 11) + i]   = inv3 * 8.f;
    }

    float m[8];
#pragma unroll
    for (int u = 0; u < 8; u++)
        m[u] = p[0][u] * inv0 + p[1][u] * inv1 + p[2][u] * inv2 + p[3][u] * inv3;

    float4* mrow = (float4*)(omap + ((long)bi << 11) + j0);
    float4 v0 = make_float4(m[0], m[1], m[2], m[3]);
    float4 v1 = make_float4(m[4], m[5], m[6], m[7]);
    if (layer) {
        float4 o0 = mrow[0], o1 = mrow[1];
        v0.x += o0.x; v0.y += o0.y; v0.z += o0.z; v0.w += o0.w;
        v1.x += o1.x; v1.y += o1.y; v1.z += o1.z; v1.w += o1.w;
    }
    mrow[0] = v0; mrow[1] = v1;
}

// ---------------- fused att-gen + wmma GEMM (fp16 2-term, M=64 tiles, 2 CTAs/SM) ----------------
// smem: A stage0 (hi 9216 | lo 9216) | A stage1 | B stage0 9216 | B stage1 9216 = 55296
#define A_LDM 72
#define SA_LO  9216
#define A_ST   18432
#define SB_OFF 36864
#define SB_ST  9216
#define SM_TOTAL 55296

__device__ __forceinline__ void gen_chunk(uint32_t sb, int stage, int c,
    float esi, const unsigned* __restrict__ awp, int bshift, uint32_t genoff, long edbase)
{
    unsigned bits = awp[c * 2] >> bshift;
    const float4* e4p = (const float4*)(g_ed + edbase + (long)c * 64);
    uint32_t ah = sb + stage * A_ST + genoff;
    uint32_t al = ah + SA_LO;
    unsigned uhi[8], ulo[8];
#pragma unroll
    for (int g = 0; g < 4; g++) {
        float4 e4 = e4p[g];
        float ev[4] = {e4.x, e4.y, e4.z, e4.w};
        float pv[4];
#pragma unroll
        for (int u = 0; u < 4; u++) {
            float s = esi + ev[u];
            float lk = fmaxf(s, 0.2f * s);
            float p = __expf(lk - EXP_BIAS);
            if (!((bits >> (g * 4 + u)) & 1u)) p = 0.f;
            pv[u] = p;
        }
        __half2 h01 = __floats2half2_rn(pv[0], pv[1]);
        __half2 h23 = __floats2half2_rn(pv[2], pv[3]);
        float r0 = pv[0] - __half2float(__low2half(h01));
        float r1 = pv[1] - __half2float(__high2half(h01));
        float r2 = pv[2] - __half2float(__low2half(h23));
        float r3 = pv[3] - __half2float(__high2half(h23));
        __half2 l01 = __floats2half2_rn(r0, r1);
        __half2 l23 = __floats2half2_rn(r2, r3);
        uhi[g * 2 + 0] = *(unsigned*)&h01; uhi[g * 2 + 1] = *(unsigned*)&h23;
        ulo[g * 2 + 0] = *(unsigned*)&l01; ulo[g * 2 + 1] = *(unsigned*)&l23;
    }
    asm volatile("st.shared.v4.b32 [%0], {%1,%2,%3,%4};" :: "r"(ah),
                 "r"(uhi[0]), "r"(uhi[1]), "r"(uhi[2]), "r"(uhi[3]) : "memory");
    asm volatile("st.shared.v4.b32 [%0], {%1,%2,%3,%4};" :: "r"(ah + 16),
                 "r"(uhi[4]), "r"(uhi[5]), "r"(uhi[6]), "r"(uhi[7]) : "memory");
    asm volatile("st.shared.v4.b32 [%0], {%1,%2,%3,%4};" :: "r"(al),
                 "r"(ulo[0]), "r"(ulo[1]), "r"(ulo[2]), "r"(ulo[3]) : "memory");
    asm volatile("st.shared.v4.b32 [%0], {%1,%2,%3,%4};" :: "r"(al + 16),
                 "r"(ulo[4]), "r"(ulo[5]), "r"(ulo[6]), "r"(ulo[7]) : "memory");
}

__global__ void __launch_bounds__(256, 2) attmma_k(int layer) {
    extern __shared__ char smem[];
    uint32_t sb = smem_u32(smem);
    int tid = threadIdx.x, wid = tid >> 5;
    int z = blockIdx.z;
    int b = z >> 2;
    int m0 = blockIdx.x * 64;
    int row0 = (wid >> 1) * 16;          // 4 row strips of 16
    int nh = (wid & 1) * 32;             // N-half per warp

    // gen constants: thread covers row gr, 16 cols starting q4*16
    int gr = tid >> 2, q4 = tid & 3;
    float esi = g_es[(long)z * Nn + m0 + gr];
    const unsigned* awp = g_adjbits + (long)(m0 + gr) * 64 + (q4 >> 1);
    int bshift = (q4 & 1) * 16;
    uint32_t genoff = gr * 144 + q4 * 32;
    long edbase = (long)z * Nn + q4 * 16;

    // B cp.async mapping: 64 rows x 128B per chunk, 256 threads x 2 x 16B
    int brow = tid >> 3, bseg = tid & 7;
    uint32_t bsoA = brow * 144 + bseg * 16;
    uint32_t bsoB = (brow + 32) * 144 + bseg * 16;
    long bgoA = ((long)z * 64 + brow) * Nn + bseg * 8;
    long bgoB = ((long)z * 64 + brow + 32) * Nn + bseg * 8;

    wmma::fragment<wmma::accumulator, 16, 16, 16, float> acc[2];
    wmma::fill_fragment(acc[0], 0.f);
    wmma::fill_fragment(acc[1], 0.f);

    gen_chunk(sb, 0, 0, esi, awp, bshift, genoff, edbase);
    CP16(sb + SB_OFF + bsoA, g_hT + bgoA);
    CP16(sb + SB_OFF + bsoB, g_hT + bgoB);
    CP_COMMIT();

    for (int c = 0; c < 32; ++c) {
        int cur = c & 1;
        CP_WAIT0();
        __syncthreads();

        if (c + 1 < 32) {
            uint32_t sN = sb + SB_OFF + (cur ^ 1) * SB_ST;
            CP16(sN + bsoA, g_hT + bgoA + (c + 1) * 64);
            CP16(sN + bsoB, g_hT + bgoB + (c + 1) * 64);
            CP_COMMIT();
        }

        const char* sA = smem + cur * A_ST;
        const __half* Ah = (const __half*)sA;
        const __half* Al = (const __half*)(sA + SA_LO);
        const __half* Bh = (const __half*)(smem + SB_OFF + cur * SB_ST);

#pragma unroll
        for (int kk = 0; kk < 4; kk++) {
            wmma::fragment<wmma::matrix_a, 16, 16, 16, __half, wmma::row_major> fa_h, fa_l;
            wmma::load_matrix_sync(fa_h, Ah + row0 * A_LDM + kk * 16, A_LDM);
            wmma::load_matrix_sync(fa_l, Al + row0 * A_LDM + kk * 16, A_LDM);
#pragma unroll
            for (int n = 0; n < 2; n++) {
                wmma::fragment<wmma::matrix_b, 16, 16, 16, __half, wmma::col_major> fb;
                wmma::load_matrix_sync(fb, Bh + (nh + n * 16) * A_LDM + kk * 16, A_LDM);
                wmma::mma_sync(acc[n], fa_h, fb, acc[n]);
                wmma::mma_sync(acc[n], fa_l, fb, acc[n]);
            }
        }

        if (c + 1 < 32)
            gen_chunk(sb, cur ^ 1, c + 1, esi, awp, bshift, genoff, edbase);
    }

    float* Cs = (float*)smem;
    wmma::store_matrix_sync(Cs + row0 * A_LDM + nh,      acc[0], A_LDM, wmma::mem_row_major);
    wmma::store_matrix_sync(Cs + row0 * A_LDM + nh + 16, acc[1], A_LDM, wmma::mem_row_major);
    __syncthreads();

    float* C = (layer == 0 ? g_x1 : g_x2) + ((long)(b * Nn + m0) * HF + (z & 3) * 64);
    const float* invp = g_inv + (long)z * Nn + m0;
#pragma unroll
    for (int i = 0; i < 4; i++) {
        int q = tid + 256 * i;           // 1024 float4 = 64 rows x 64 cols
        int row = q >> 4, cg = q & 15;
        float sc = invp[row] * EXP_BIAS_INV;
        float4 v = *(float4*)&Cs[row * A_LDM + cg * 4];
        v.x = fmaxf(v.x, 0.f) * sc; v.y = fmaxf(v.y, 0.f) * sc;
        v.z = fmaxf(v.z, 0.f) * sc; v.w = fmaxf(v.w, 0.f) * sc;
        *(float4*)(C + (long)row * HF + cg * 4) = v;
    }
}

// ---------------- pools ----------------
__global__ void pool_k(const float* __restrict__ xparam,
                       const float* __restrict__ w, const float* __restrict__ wb,
                       float* __restrict__ out, int mode)
{
    int warp = (blockIdx.x * 256 + threadIdx.x) >> 5;
    int lane = threadIdx.x & 31;
    const float* rows; int rowlen, off; float scale;
    if (mode == 0)      { rows = xparam; rowlen = Dd; off = 0;      scale = 1.f / 128.f; }
    else if (mode == 1) { rows = g_x1;   rowlen = HF; off = Nn;     scale = 1.f; }
    else                { rows = g_x2;   rowlen = HF; off = 2 * Nn; scale = 1.f; }
    const float* rp = rows + (long)warp * rowlen;
    float acc = 0.f;
    if (mode == 0) { for (int c = lane; c < rowlen; c += 32) acc += rp[c]; }
    else           { for (int c = lane; c < rowlen; c += 32) acc += rp[c] * w[c]; }
#pragma unroll
    for (int o = 16; o; o >>= 1) acc += __shfl_xor_sync(0xffffffffu, acc, o);
    if (!lane) {
        int b = warp >> 11, n = warp & 2047;
        out[(long)b * (3 * Nn) + off + n] = acc * scale + (mode == 0 ? 0.f : wb[0]);
    }
}

// ---------------- MLP head ----------------
__global__ void __launch_bounds__(256) fc_part_k(const float* __restrict__ in_param,
                                                 const float* __restrict__ W,
                                                 int use_y1, int IC, int OC)
{
    __shared__ float red0[256], red1[256];
    const float* in = use_y1 ? (const float*)g_y1 : in_param;
    int tid = threadIdx.x;
    int cl = tid & 63, ks = tid >> 6;
    int c = blockIdx.x * 64 + cl;
    int kchunk = IC >> 5;
    int k0 = (blockIdx.y * 4 + ks) * kchunk;
    const float* in0 = in;
    const float* in1 = in + IC;
    float a0 = 0.f, a1 = 0.f;
#pragma unroll 4
    for (int k = k0; k < k0 + kchunk; k++) {
        float w = W[(long)k * OC + c];
        a0 += in0[k] * w;
        a1 += in1[k] * w;
    }
    red0[tid] = a0; red1[tid] = a1;
    __syncthreads();
    if (ks == 0) {
        a0 = red0[tid] + red0[tid + 64] + red0[tid + 128] + red0[tid + 192];
        a1 = red1[tid] + red1[tid + 64] + red1[tid + 128] + red1[tid + 192];
        long base = (long)blockIdx.y * (2 * OC);
        g_part[base + c] = a0;
        g_part[base + OC + c] = a1;
    }
}

__global__ void fc_reduce_k(const float* __restrict__ bias, int mode, int OC, int tot)
{
    int t = blockIdx.x * 256 + threadIdx.x;
    if (t >= tot) return;
    float s = bias[t % OC];
#pragma unroll
    for (int p = 0; p < 8; p++) s += g_part[(long)p * tot + t];
    if (mode == 0) g_fc1[t] = s; else g_fc2[t] = s;
}

__global__ void ln_relu_k(int mode, float* __restrict__ out_param,
                          const float* __restrict__ g, const float* __restrict__ be)
{
    __shared__ float r1[8], r2[8];
    int C = (mode == 0) ? FC1n : FC2n;
    const float* in = (mode == 0) ? (const float*)g_fc1 : (const float*)g_fc2;
    float* outp = (mode == 0) ? (float*)g_y1 : out_param;
    int b = blockIdx.x, tid = threadIdx.x, lane = tid & 31, wid = tid >> 5;
    const float* row = in + (long)b * C;
    float s = 0.f, ss = 0.f;
    for (int c = tid; c < C; c += 256) { float v = row[c]; s += v; ss += v * v; }
#pragma unroll
    for (int o = 16; o; o >>= 1) {
        s  += __shfl_xor_sync(0xffffffffu, s, o);
        ss += __shfl_xor_sync(0xffffffffu, ss, o);
    }
    if (!lane) { r1[wid] = s; r2[wid] = ss; }
    __syncthreads();
    s = 0.f; ss = 0.f;
#pragma unroll
    for (int w = 0; w < 8; w++) { s += r1[w]; ss += r2[w]; }
    float m = s / C;
    float var = ss / C - m * m;
    float r = rsqrtf(var + 1e-5f);
    for (int c = tid; c < C; c += 256) {
        float v = row[c];
        outp[(long)b * C + c] = fmaxf((v - m) * r * g[c] + be[c], 0.f);
    }
}

__global__ void cls_k(const float* __restrict__ feat, const float* __restrict__ W,
                      const float* __restrict__ wb, float* __restrict__ out)
{
    int tid = threadIdx.x;
    if (tid >= 128) return;
    int lane = tid & 31, w = tid >> 5;
    int b = w >> 1, l = w & 1;
    float acc = 0.f;
    for (int k = lane; k < FC2n; k += 32) acc += feat[b * FC2n + k] * W[k * 2 + l];
#pragma unroll
    for (int o = 16; o; o >>= 1) acc += __shfl_xor_sync(0xffffffffu, acc, o);
    if (!lane) out[b * 2 + l] = acc + wb[l];
}

// ---------------- host launcher ----------------
extern "C" void kernel_launch(void* const* d_in, const int* in_sizes, int n_in,
                              void* d_out, int out_size)
{
    const float* x        = (const float*)d_in[0];
    const int*   adj      = (const int*)  d_in[1];
    const float* a1_src   = (const float*)d_in[4];
    const float* a1_dst   = (const float*)d_in[5];
    const float* pool1_W  = (const float*)d_in[6];
    const float* pool1_b  = (const float*)d_in[7];
    const float* a2_src   = (const float*)d_in[9];
    const float* a2_dst   = (const float*)d_in[10];
    const float* pool2_W  = (const float*)d_in[11];
    const float* pool2_b  = (const float*)d_in[12];
    const float* fc1_W    = (const float*)d_in[13];
    const float* fc1_b    = (const float*)d_in[14];
    const float* ln1_g    = (const float*)d_in[15];
    const float* ln1_b    = (const float*)d_in[16];
    const float* fc2_W    = (const float*)d_in[17];
    const float* fc2_b    = (const float*)d_in[18];
    const float* ln2_g    = (const float*)d_in[19];
    const float* ln2_b    = (const float*)d_in[20];
    const float* cls_W    = (const float*)d_in[21];
    const float* cls_b    = (const float*)d_in[22];

    float* out = (float*)d_out;

    cudaFuncSetAttribute(attmma_k, cudaFuncAttributeMaxDynamicSharedMemorySize, SM_TOTAL);

    repack_k<<<256, 256>>>((const float*)d_in[3], (const float*)d_in[8]);
    adjpack_k<<<16384, 256>>>(adj);

    // layer 1
    gemm_k<<<dim3(32, 4, 1), 256>>>(x, a1_src, a1_dst, 0);
    rowstat_k<<<4096, 256>>>(0, out + OUT_MAP);
    attmma_k<<<dim3(32, 1, 8), 256, SM_TOTAL>>>(0);

    pool_k<<<512, 256>>>(x, pool1_W, pool1_b, out + OUT_GAT, 0);
    pool_k<<<512, 256>>>(x, pool1_W, pool1_b, out + OUT_GAT, 1);

    // layer 2
    gemm_k<<<dim3(32, 4, 1), 256>>>(x, a2_src, a2_dst, 1);
    rowstat_k<<<4096, 256>>>(1, out + OUT_MAP);
    attmma_k<<<dim3(32, 1, 8), 256, SM_TOTAL>>>(1);

    pool_k<<<512, 256>>>(x, pool2_W, pool2_b, out + OUT_GAT, 2);

    // head
    fc_part_k<<<dim3(16, 8), 256>>>(out + OUT_GAT, fc1_W, 0, 3 * Nn, FC1n);
    fc_reduce_k<<<8, 256>>>(fc1_b, 0, FC1n, Bsz * FC1n);
    ln_relu_k<<<2, 256>>>(0, out, ln1_g, ln1_b);

    fc_part_k<<<dim3(4, 8), 256>>>(out, fc2_W, 1, FC1n, FC2n);
    fc_reduce_k<<<2, 256>>>(fc2_b, 1, FC2n, Bsz * FC2n);
    ln_relu_k<<<2, 256>>>(1, out + OUT_FC, ln2_g, ln2_b);

    cls_k<<<1, 128>>>(out + OUT_FC, cls_W, cls_b, out + OUT_LOG);
}

// round 9
// speedup vs baseline: 1.4642x; 1.1094x over previous
#include <cuda_runtime.h>
#include <cuda_bf16.h>
#include <cuda_fp16.h>
#include <mma.h>
#include <math.h>
#include <stdint.h>

using namespace nvcuda;

// ---------------- problem constants ----------------
#define Bsz 2
#define Nn  2048
#define Dd  128
#define Hh  4
#define Ff  64
#define HF  256
#define FC1n 1024
#define FC2n 256

// output layout (f32)
#define OUT_GAT 0
#define OUT_FC  12288
#define OUT_LOG 12800
#define OUT_MAP 12804

#define EXP_BIAS 8.0f
#define EXP_BIAS_INV 2980.9579870417283f   // e^8

// ---------------- scratch ----------------
__device__ float g_wcat1[Dd * HF];
__device__ float g_wcat2[HF * HF];
__device__ float g_x1[Bsz * Nn * HF];
__device__ float g_x2[Bsz * Nn * HF];
__device__ float g_es[Bsz * Hh * Nn];
__device__ float g_ed[Bsz * Hh * Nn];
__device__ float g_inv[Bsz * Hh * Nn];
__device__ unsigned g_adjbits[Nn * 64];                      // 512 KB bitmask
__device__ __half g_hT[Bsz * HF * Nn];                       // h^T fp16
__device__ float g_fc1[Bsz * FC1n];
__device__ float g_y1[Bsz * FC1n];
__device__ float g_fc2[Bsz * FC2n];
__device__ float g_part[8 * Bsz * FC1n];

// ---------------- f32x2 helpers (SIMT proj GEMM) ----------------
__device__ __forceinline__ unsigned long long pack2(float x, float y) {
    unsigned long long r;
    asm("mov.b64 %0, {%1, %2};" : "=l"(r) : "r"(__float_as_uint(x)), "r"(__float_as_uint(y)));
    return r;
}
__device__ __forceinline__ unsigned long long rep2(float x) {
    unsigned long long r; unsigned u = __float_as_uint(x);
    asm("mov.b64 %0, {%1, %1};" : "=l"(r) : "r"(u));
    return r;
}
__device__ __forceinline__ void fma2(unsigned long long &d, unsigned long long a, unsigned long long b) {
    asm("fma.rn.f32x2 %0, %1, %2, %0;" : "+l"(d) : "l"(a), "l"(b));
}
__device__ __forceinline__ float2 unpk2(unsigned long long v) {
    float2 f; f.x = __uint_as_float((unsigned)v); f.y = __uint_as_float((unsigned)(v >> 32));
    return f;
}

// ---------------- cp.async helpers ----------------
__device__ __forceinline__ uint32_t smem_u32(const void* p) {
    uint32_t a;
    asm("{ .reg .u64 t; cvta.to.shared.u64 t, %1; cvt.u32.u64 %0, t; }" : "=r"(a) : "l"(p));
    return a;
}
#define CP16(saddr, gptr) asm volatile("cp.async.cg.shared.global [%0], [%1], 16;" :: "r"(saddr), "l"(gptr) : "memory")
#define CP_COMMIT() asm volatile("cp.async.commit_group;" ::: "memory")
#define CP_WAIT0()  asm volatile("cp.async.wait_group 0;" ::: "memory")

// ---------------- repack ----------------
__global__ void repack_k(const float* __restrict__ W1, const float* __restrict__ W2) {
    int t = blockIdx.x * blockDim.x + threadIdx.x;
    if (t < Hh * Dd * Ff) {
        int h = t / (Dd * Ff); int r = t % (Dd * Ff); int d = r / Ff; int f = r % Ff;
        g_wcat1[d * HF + h * Ff + f] = W1[t];
    }
    if (t < Hh * HF * Ff) {
        int h = t / (HF * Ff); int r = t % (HF * Ff); int k = r / Ff; int f = r % Ff;
        g_wcat2[k * HF + h * Ff + f] = W2[t];
    }
}

// ---------------- adj -> bitmask ----------------
__global__ void adjpack_k(const int* __restrict__ adj) {
    int w = (blockIdx.x * blockDim.x + threadIdx.x) >> 5;   // word index
    int lane = threadIdx.x & 31;
    int i = w >> 6, widx = w & 63;
    int a = adj[(long)i * Nn + widx * 32 + lane];
    unsigned m = __ballot_sync(0xffffffffu, a > 0);
    if (!lane) g_adjbits[w] = m;
}

// ---------------- SIMT projection GEMM + fused es/ed + fused fp16 hT store ----------------
__global__ void __launch_bounds__(256) gemm_k(const float* __restrict__ xin,
                                              const float* __restrict__ asrc,
                                              const float* __restrict__ adst, int mode) {
    const float *A, *B; int K, lda;
    if (mode == 0) { A = xin;  B = g_wcat1; K = Dd; lda = Dd; }
    else           { A = g_x1; B = g_wcat2; K = HF; lda = HF; }
    const int ldb = HF;

    __shared__ float As[16][128];
    __shared__ float Bs[16][64];
    __shared__ float esp[16][129];
    __shared__ float edp[16][129];
    __shared__ float av[64], dv[64];
    __shared__ __half t16[64][136];

    int tid = threadIdx.x;
    int head = blockIdx.y;
    int m0 = blockIdx.x * 128, n0 = head * 64;
    int tx = tid & 15, ty = tid >> 4;
    int a_r = tid >> 2, a_k = (tid & 3) << 2;
    int b_k = tid >> 4, b_n = (tid & 15) << 2;

    if (tid < 64)       av[tid] = asrc[n0 + tid];
    else if (tid < 128) dv[tid - 64] = adst[n0 + tid - 64];

    const float* Ap0 = A + (long)(m0 + a_r) * lda + a_k;
    const float* Ap1 = Ap0 + (long)64 * lda;
    const float* Bp  = B + (long)b_k * ldb + n0 + b_n;

    unsigned long long acc[4][4];
#pragma unroll
    for (int i = 0; i < 4; i++)
#pragma unroll
        for (int j = 0; j < 4; j++) acc[i][j] = 0ULL;

    float4 av0 = *(const float4*)Ap0;
    float4 av1 = *(const float4*)Ap1;
    float4 bv  = *(const float4*)Bp;

    for (int k0 = 0; k0 < K; k0 += 16) {
        __syncthreads();
        As[a_k + 0][a_r] = av0.x; As[a_k + 1][a_r] = av0.y;
        As[a_k + 2][a_r] = av0.z; As[a_k + 3][a_r] = av0.w;
        As[a_k + 0][a_r + 64] = av1.x; As[a_k + 1][a_r + 64] = av1.y;
        As[a_k + 2][a_r + 64] = av1.z; As[a_k + 3][a_r + 64] = av1.w;
        *(float4*)&Bs[b_k][b_n] = bv;
        __syncthreads();
        if (k0 + 16 < K) {
            av0 = *(const float4*)(Ap0 + k0 + 16);
            av1 = *(const float4*)(Ap1 + k0 + 16);
            bv  = *(const float4*)(Bp + (long)(k0 + 16) * ldb);
        }
#pragma unroll
        for (int kk = 0; kk < 16; kk++) {
            float4 aA = *(const float4*)&As[kk][ty * 8];
            float4 aB = *(const float4*)&As[kk][ty * 8 + 4];
            float4 b4 = *(const float4*)&Bs[kk][tx * 4];
            unsigned long long au[4], bu[4];
            au[0] = pack2(aA.x, aA.y); au[1] = pack2(aA.z, aA.w);
            au[2] = pack2(aB.x, aB.y); au[3] = pack2(aB.z, aB.w);
            bu[0] = rep2(b4.x); bu[1] = rep2(b4.y); bu[2] = rep2(b4.z); bu[3] = rep2(b4.w);
#pragma unroll
            for (int ip = 0; ip < 4; ip++)
#pragma unroll
                for (int j = 0; j < 4; j++) fma2(acc[ip][j], au[ip], bu[j]);
        }
    }

    float as0 = av[tx * 4], as1 = av[tx * 4 + 1], as2 = av[tx * 4 + 2], as3 = av[tx * 4 + 3];
    float ad0 = dv[tx * 4], ad1 = dv[tx * 4 + 1], ad2 = dv[tx * 4 + 2], ad3 = dv[tx * 4 + 3];

#pragma unroll
    for (int ip = 0; ip < 4; ip++) {
        float2 c0 = unpk2(acc[ip][0]), c1 = unpk2(acc[ip][1]);
        float2 c2 = unpk2(acc[ip][2]), c3 = unpk2(acc[ip][3]);
        float4 lo = make_float4(c0.x, c1.x, c2.x, c3.x);
        float4 hi = make_float4(c0.y, c1.y, c2.y, c3.y);
        int rl = ty * 8 + 2 * ip;
        esp[tx][rl]     = lo.x * as0 + lo.y * as1 + lo.z * as2 + lo.w * as3;
        edp[tx][rl]     = lo.x * ad0 + lo.y * ad1 + lo.z * ad2 + lo.w * ad3;
        esp[tx][rl + 1] = hi.x * as0 + hi.y * as1 + hi.z * as2 + hi.w * as3;
        edp[tx][rl + 1] = hi.x * ad0 + hi.y * ad1 + hi.z * ad2 + hi.w * ad3;
        t16[tx * 4 + 0][rl]     = __float2half_rn(lo.x);
        t16[tx * 4 + 1][rl]     = __float2half_rn(lo.y);
        t16[tx * 4 + 2][rl]     = __float2half_rn(lo.z);
        t16[tx * 4 + 3][rl]     = __float2half_rn(lo.w);
        t16[tx * 4 + 0][rl + 1] = __float2half_rn(hi.x);
        t16[tx * 4 + 1][rl + 1] = __float2half_rn(hi.y);
        t16[tx * 4 + 2][rl + 1] = __float2half_rn(hi.z);
        t16[tx * 4 + 3][rl + 1] = __float2half_rn(hi.w);
    }
    __syncthreads();
    {
        int row = tid & 127, which = tid >> 7;
        const float (*src)[129] = which ? edp : esp;
        float s = 0.f;
#pragma unroll
        for (int t = 0; t < 16; t++) s += src[t][row];
        int r = m0 + row;
        int bb = r >> 11, n = r & 2047;
        int idx = (((bb << 2) + head) << 11) | n;
        if (which) g_ed[idx] = s; else g_es[idx] = s;
    }
    {
        int bb = m0 >> 11, jr = m0 & 2047;
#pragma unroll
        for (int it = 0; it < 4; it++) {
            int q = tid + 256 * it;       // 1024 uint4 = 64 cols x 128 rows fp16
            int c = q >> 4, seg = q & 15;
            uint4 v = *(uint4*)&t16[c][seg * 8];
            *(uint4*)&g_hT[((long)(bb * HF + n0 + c)) * Nn + jr + seg * 8] = v;
        }
    }
}

// ---------------- row stats v4: head pairs, reg-capped for occupancy ----------------
__global__ void __launch_bounds__(256, 5) rowstat_k(int layer, float* __restrict__ omap)
{
    __shared__ float red[2][8][2];
    int bi = blockIdx.x;
    int b = bi >> 11, i = bi & 2047;
    int tid = threadIdx.x, lane = tid & 31, wid = tid >> 5;
    int j0 = tid * 8;
    unsigned bits = (g_adjbits[i * 64 + (j0 >> 5)] >> (j0 & 31)) & 0xFFu;
    long ro = (long)(b << 2) << 11;

    float m[8];
#pragma unroll
    for (int u = 0; u < 8; u++) m[u] = 0.f;

#pragma unroll
    for (int pass = 0; pass < 2; pass++) {
        float p0[8], p1[8];
        float s0 = 0.f, s1 = 0.f;
        int h0 = pass * 2;
        {
            float esi = g_es[ro + (h0 << 11) + i];
            const float4* edv = (const float4*)(g_ed + ro + (h0 << 11) + j0);
            float4 e0 = edv[0], e1 = edv[1];
            float ev[8] = {e0.x, e0.y, e0.z, e0.w, e1.x, e1.y, e1.z, e1.w};
#pragma unroll
            for (int u = 0; u < 8; u++) {
                float t = esi + ev[u];
                float lk = fmaxf(t, 0.2f * t);
                float pe = __expf(lk);
                pe = ((bits >> u) & 1u) ? pe : 0.f;
                p0[u] = pe; s0 += pe;
            }
        }
        {
            float esi = g_es[ro + ((h0 + 1) << 11) + i];
            const float4* edv = (const float4*)(g_ed + ro + ((h0 + 1) << 11) + j0);
            float4 e0 = edv[0], e1 = edv[1];
            float ev[8] = {e0.x, e0.y, e0.z, e0.w, e1.x, e1.y, e1.z, e1.w};
#pragma unroll
            for (int u = 0; u < 8; u++) {
                float t = esi + ev[u];
                float lk = fmaxf(t, 0.2f * t);
                float pe = __expf(lk);
                pe = ((bits >> u) & 1u) ? pe : 0.f;
                p1[u] = pe; s1 += pe;
            }
        }
#pragma unroll
        for (int o = 16; o; o >>= 1) {
            s0 += __shfl_xor_sync(0xffffffffu, s0, o);
            s1 += __shfl_xor_sync(0xffffffffu, s1, o);
        }
        if (!lane) { red[pass][wid][0] = s0; red[pass][wid][1] = s1; }
        __syncthreads();
        float t0 = 0.f, t1 = 0.f;
#pragma unroll
        for (int w = 0; w < 8; w++) { t0 += red[pass][w][0]; t1 += red[pass][w][1]; }
        float inv0 = 1.f / t0, inv1 = 1.f / t1;
        if (tid == 0) {
            g_inv[ro + (h0 << 11) + i]       = inv0;
            g_inv[ro + ((h0 + 1) << 11) + i] = inv1;
        }
        float q0 = 0.125f * inv0, q1 = 0.125f * inv1;
#pragma unroll
        for (int u = 0; u < 8; u++) m[u] += p0[u] * q0 + p1[u] * q1;
    }

    float4* mrow = (float4*)(omap + ((long)bi << 11) + j0);
    float4 v0 = make_float4(m[0], m[1], m[2], m[3]);
    float4 v1 = make_float4(m[4], m[5], m[6], m[7]);
    if (layer) {
        float4 o0 = mrow[0], o1 = mrow[1];
        v0.x += o0.x; v0.y += o0.y; v0.z += o0.z; v0.w += o0.w;
        v1.x += o1.x; v1.y += o1.y; v1.z += o1.z; v1.w += o1.w;
    }
    mrow[0] = v0; mrow[1] = v1;
}

// ---------------- fused att-gen + wmma GEMM (fp16 1-term, M=64 tiles) ----------------
// smem: A stage0 9216 | A stage1 9216 | B stage0 9216 | B stage1 9216 = 36864
#define A_LDM 72
#define A_ST   9216
#define SB_OFF 18432
#define SB_ST  9216
#define SM_TOTAL 36864

__device__ __forceinline__ void gen_chunk(uint32_t sb, int stage, int c,
    float esi, const unsigned* __restrict__ awp, int bshift, uint32_t genoff, long edbase)
{
    unsigned bits = awp[c * 2] >> bshift;
    const float4* e4p = (const float4*)(g_ed + edbase + (long)c * 64);
    uint32_t ah = sb + stage * A_ST + genoff;
    unsigned uhi[8];
#pragma unroll
    for (int g = 0; g < 4; g++) {
        float4 e4 = e4p[g];
        float ev[4] = {e4.x, e4.y, e4.z, e4.w};
        float pv[4];
#pragma unroll
        for (int u = 0; u < 4; u++) {
            float s = esi + ev[u];
            float lk = fmaxf(s, 0.2f * s);
            float p = __expf(lk - EXP_BIAS);
            if (!((bits >> (g * 4 + u)) & 1u)) p = 0.f;
            pv[u] = p;
        }
        __half2 h01 = __floats2half2_rn(pv[0], pv[1]);
        __half2 h23 = __floats2half2_rn(pv[2], pv[3]);
        uhi[g * 2 + 0] = *(unsigned*)&h01; uhi[g * 2 + 1] = *(unsigned*)&h23;
    }
    asm volatile("st.shared.v4.b32 [%0], {%1,%2,%3,%4};" :: "r"(ah),
                 "r"(uhi[0]), "r"(uhi[1]), "r"(uhi[2]), "r"(uhi[3]) : "memory");
    asm volatile("st.shared.v4.b32 [%0], {%1,%2,%3,%4};" :: "r"(ah + 16),
                 "r"(uhi[4]), "r"(uhi[5]), "r"(uhi[6]), "r"(uhi[7]) : "memory");
}

__global__ void __launch_bounds__(256, 2) attmma_k(int layer) {
    extern __shared__ char smem[];
    uint32_t sb = smem_u32(smem);
    int tid = threadIdx.x, wid = tid >> 5;
    int z = blockIdx.z;
    int b = z >> 2;
    int m0 = blockIdx.x * 64;
    int row0 = (wid >> 1) * 16;          // 4 row strips of 16
    int nh = (wid & 1) * 32;             // N-half per warp

    // gen constants: thread covers row gr, 16 cols starting q4*16
    int gr = tid >> 2, q4 = tid & 3;
    float esi = g_es[(long)z * Nn + m0 + gr];
    const unsigned* awp = g_adjbits + (long)(m0 + gr) * 64 + (q4 >> 1);
    int bshift = (q4 & 1) * 16;
    uint32_t genoff = gr * 144 + q4 * 32;
    long edbase = (long)z * Nn + q4 * 16;

    // B cp.async mapping: 64 rows x 128B per chunk, 256 threads x 2 x 16B
    int brow = tid >> 3, bseg = tid & 7;
    uint32_t bsoA = brow * 144 + bseg * 16;
    uint32_t bsoB = (brow + 32) * 144 + bseg * 16;
    long bgoA = ((long)z * 64 + brow) * Nn + bseg * 8;
    long bgoB = ((long)z * 64 + brow + 32) * Nn + bseg * 8;

    wmma::fragment<wmma::accumulator, 16, 16, 16, float> acc[2];
    wmma::fill_fragment(acc[0], 0.f);
    wmma::fill_fragment(acc[1], 0.f);

    gen_chunk(sb, 0, 0, esi, awp, bshift, genoff, edbase);
    CP16(sb + SB_OFF + bsoA, g_hT + bgoA);
    CP16(sb + SB_OFF + bsoB, g_hT + bgoB);
    CP_COMMIT();

    for (int c = 0; c < 32; ++c) {
        int cur = c & 1;
        CP_WAIT0();
        __syncthreads();

        if (c + 1 < 32) {
            uint32_t sN = sb + SB_OFF + (cur ^ 1) * SB_ST;
            CP16(sN + bsoA, g_hT + bgoA + (c + 1) * 64);
            CP16(sN + bsoB, g_hT + bgoB + (c + 1) * 64);
            CP_COMMIT();
        }

        const __half* Ah = (const __half*)(smem + cur * A_ST);
        const __half* Bh = (const __half*)(smem + SB_OFF + cur * SB_ST);

#pragma unroll
        for (int kk = 0; kk < 4; kk++) {
            wmma::fragment<wmma::matrix_a, 16, 16, 16, __half, wmma::row_major> fa;
            wmma::load_matrix_sync(fa, Ah + row0 * A_LDM + kk * 16, A_LDM);
#pragma unroll
            for (int n = 0; n < 2; n++) {
                wmma::fragment<wmma::matrix_b, 16, 16, 16, __half, wmma::col_major> fb;
                wmma::load_matrix_sync(fb, Bh + (nh + n * 16) * A_LDM + kk * 16, A_LDM);
                wmma::mma_sync(acc[n], fa, fb, acc[n]);
            }
        }

        if (c + 1 < 32)
            gen_chunk(sb, cur ^ 1, c + 1, esi, awp, bshift, genoff, edbase);
    }

    float* Cs = (float*)smem;
    wmma::store_matrix_sync(Cs + row0 * A_LDM + nh,      acc[0], A_LDM, wmma::mem_row_major);
    wmma::store_matrix_sync(Cs + row0 * A_LDM + nh + 16, acc[1], A_LDM, wmma::mem_row_major);
    __syncthreads();

    float* C = (layer == 0 ? g_x1 : g_x2) + ((long)(b * Nn + m0) * HF + (z & 3) * 64);
    const float* invp = g_inv + (long)z * Nn + m0;
#pragma unroll
    for (int i = 0; i < 4; i++) {
        int q = tid + 256 * i;           // 1024 float4 = 64 rows x 64 cols
        int row = q >> 4, cg = q & 15;
        float sc = invp[row] * EXP_BIAS_INV;
        float4 v = *(float4*)&Cs[row * A_LDM + cg * 4];
        v.x = fmaxf(v.x, 0.f) * sc; v.y = fmaxf(v.y, 0.f) * sc;
        v.z = fmaxf(v.z, 0.f) * sc; v.w = fmaxf(v.w, 0.f) * sc;
        *(float4*)(C + (long)row * HF + cg * 4) = v;
    }
}

// ---------------- pools ----------------
__global__ void pool_k(const float* __restrict__ xparam,
                       const float* __restrict__ w, const float* __restrict__ wb,
                       float* __restrict__ out, int mode)
{
    int warp = (blockIdx.x * 256 + threadIdx.x) >> 5;
    int lane = threadIdx.x & 31;
    const float* rows; int rowlen, off; float scale;
    if (mode == 0)      { rows = xparam; rowlen = Dd; off = 0;      scale = 1.f / 128.f; }
    else if (mode == 1) { rows = g_x1;   rowlen = HF; off = Nn;     scale = 1.f; }
    else                { rows = g_x2;   rowlen = HF; off = 2 * Nn; scale = 1.f; }
    const float* rp = rows + (long)warp * rowlen;
    float acc = 0.f;
    if (mode == 0) { for (int c = lane; c < rowlen; c += 32) acc += rp[c]; }
    else           { for (int c = lane; c < rowlen; c += 32) acc += rp[c] * w[c]; }
#pragma unroll
    for (int o = 16; o; o >>= 1) acc += __shfl_xor_sync(0xffffffffu, acc, o);
    if (!lane) {
        int b = warp >> 11, n = warp & 2047;
        out[(long)b * (3 * Nn) + off + n] = acc * scale + (mode == 0 ? 0.f : wb[0]);
    }
}

// ---------------- MLP head ----------------
__global__ void __launch_bounds__(256) fc_part_k(const float* __restrict__ in_param,
                                                 const float* __restrict__ W,
                                                 int use_y1, int IC, int OC)
{
    __shared__ float red0[256], red1[256];
    const float* in = use_y1 ? (const float*)g_y1 : in_param;
    int tid = threadIdx.x;
    int cl = tid & 63, ks = tid >> 6;
    int c = blockIdx.x * 64 + cl;
    int kchunk = IC >> 5;
    int k0 = (blockIdx.y * 4 + ks) * kchunk;
    const float* in0 = in;
    const float* in1 = in + IC;
    float a0 = 0.f, a1 = 0.f;
#pragma unroll 4
    for (int k = k0; k < k0 + kchunk; k++) {
        float w = W[(long)k * OC + c];
        a0 += in0[k] * w;
        a1 += in1[k] * w;
    }
    red0[tid] = a0; red1[tid] = a1;
    __syncthreads();
    if (ks == 0) {
        a0 = red0[tid] + red0[tid + 64] + red0[tid + 128] + red0[tid + 192];
        a1 = red1[tid] + red1[tid + 64] + red1[tid + 128] + red1[tid + 192];
        long base = (long)blockIdx.y * (2 * OC);
        g_part[base + c] = a0;
        g_part[base + OC + c] = a1;
    }
}

__global__ void fc_reduce_k(const float* __restrict__ bias, int mode, int OC, int tot)
{
    int t = blockIdx.x * 256 + threadIdx.x;
    if (t >= tot) return;
    float s = bias[t % OC];
#pragma unroll
    for (int p = 0; p < 8; p++) s += g_part[(long)p * tot + t];
    if (mode == 0) g_fc1[t] = s; else g_fc2[t] = s;
}

__global__ void ln_relu_k(int mode, float* __restrict__ out_param,
                          const float* __restrict__ g, const float* __restrict__ be)
{
    __shared__ float r1[8], r2[8];
    int C = (mode == 0) ? FC1n : FC2n;
    const float* in = (mode == 0) ? (const float*)g_fc1 : (const float*)g_fc2;
    float* outp = (mode == 0) ? (float*)g_y1 : out_param;
    int b = blockIdx.x, tid = threadIdx.x, lane = tid & 31, wid = tid >> 5;
    const float* row = in + (long)b * C;
    float s = 0.f, ss = 0.f;
    for (int c = tid; c < C; c += 256) { float v = row[c]; s += v; ss += v * v; }
#pragma unroll
    for (int o = 16; o; o >>= 1) {
        s  += __shfl_xor_sync(0xffffffffu, s, o);
        ss += __shfl_xor_sync(0xffffffffu, ss, o);
    }
    if (!lane) { r1[wid] = s; r2[wid] = ss; }
    __syncthreads();
    s = 0.f; ss = 0.f;
#pragma unroll
    for (int w = 0; w < 8; w++) { s += r1[w]; ss += r2[w]; }
    float m = s / C;
    float var = ss / C - m * m;
    float r = rsqrtf(var + 1e-5f);
    for (int c = tid; c < C; c += 256) {
        float v = row[c];
        outp[(long)b * C + c] = fmaxf((v - m) * r * g[c] + be[c], 0.f);
    }
}

__global__ void cls_k(const float* __restrict__ feat, const float* __restrict__ W,
                      const float* __restrict__ wb, float* __restrict__ out)
{
    int tid = threadIdx.x;
    if (tid >= 128) return;
    int lane = tid & 31, w = tid >> 5;
    int b = w >> 1, l = w & 1;
    float acc = 0.f;
    for (int k = lane; k < FC2n; k += 32) acc += feat[b * FC2n + k] * W[k * 2 + l];
#pragma unroll
    for (int o = 16; o; o >>= 1) acc += __shfl_xor_sync(0xffffffffu, acc, o);
    if (!lane) out[b * 2 + l] = acc + wb[l];
}

// ---------------- host launcher ----------------
extern "C" void kernel_launch(void* const* d_in, const int* in_sizes, int n_in,
                              void* d_out, int out_size)
{
    const float* x        = (const float*)d_in[0];
    const int*   adj      = (const int*)  d_in[1];
    const float* a1_src   = (const float*)d_in[4];
    const float* a1_dst   = (const float*)d_in[5];
    const float* pool1_W  = (const float*)d_in[6];
    const float* pool1_b  = (const float*)d_in[7];
    const float* a2_src   = (const float*)d_in[9];
    const float* a2_dst   = (const float*)d_in[10];
    const float* pool2_W  = (const float*)d_in[11];
    const float* pool2_b  = (const float*)d_in[12];
    const float* fc1_W    = (const float*)d_in[13];
    const float* fc1_b    = (const float*)d_in[14];
    const float* ln1_g    = (const float*)d_in[15];
    const float* ln1_b    = (const float*)d_in[16];
    const float* fc2_W    = (const float*)d_in[17];
    const float* fc2_b    = (const float*)d_in[18];
    const float* ln2_g    = (const float*)d_in[19];
    const float* ln2_b    = (const float*)d_in[20];
    const float* cls_W    = (const float*)d_in[21];
    const float* cls_b    = (const float*)d_in[22];

    float* out = (float*)d_out;

    cudaFuncSetAttribute(attmma_k, cudaFuncAttributeMaxDynamicSharedMemorySize, SM_TOTAL);

    repack_k<<<256, 256>>>((const float*)d_in[3], (const float*)d_in[8]);
    adjpack_k<<<16384, 256>>>(adj);

    // layer 1
    gemm_k<<<dim3(32, 4, 1), 256>>>(x, a1_src, a1_dst, 0);
    rowstat_k<<<4096, 256>>>(0, out + OUT_MAP);
    attmma_k<<<dim3(32, 1, 8), 256, SM_TOTAL>>>(0);

    pool_k<<<512, 256>>>(x, pool1_W, pool1_b, out + OUT_GAT, 0);
    pool_k<<<512, 256>>>(x, pool1_W, pool1_b, out + OUT_GAT, 1);

    // layer 2
    gemm_k<<<dim3(32, 4, 1), 256>>>(x, a2_src, a2_dst, 1);
    rowstat_k<<<4096, 256>>>(1, out + OUT_MAP);
    attmma_k<<<dim3(32, 1, 8), 256, SM_TOTAL>>>(1);

    pool_k<<<512, 256>>>(x, pool2_W, pool2_b, out + OUT_GAT, 2);

    // head
    fc_part_k<<<dim3(16, 8), 256>>>(out + OUT_GAT, fc1_W, 0, 3 * Nn, FC1n);
    fc_reduce_k<<<8, 256>>>(fc1_b, 0, FC1n, Bsz * FC1n);
    ln_relu_k<<<2, 256>>>(0, out, ln1_g, ln1_b);

    fc_part_k<<<dim3(4, 8), 256>>>(out, fc2_W, 1, FC1n, FC2n);
    fc_reduce_k<<<2, 256>>>(fc2_b, 1, FC2n, Bsz * FC2n);
    ln_relu_k<<<2, 256>>>(1, out + OUT_FC, ln2_g, ln2_b);

    cls_k<<<1, 128>>>(out + OUT_FC, cls_W, cls_b, out + OUT_LOG);
}

// round 10
// speedup vs baseline: 1.5862x; 1.0834x over previous
#include <cuda_runtime.h>
#include <cuda_bf16.h>
#include <cuda_fp16.h>
#include <mma.h>
#include <math.h>
#include <stdint.h>

using namespace nvcuda;

// ---------------- problem constants ----------------
#define Bsz 2
#define Nn  2048
#define Dd  128
#define Hh  4
#define Ff  64
#define HF  256
#define FC1n 1024
#define FC2n 256

// output layout (f32)
#define OUT_GAT 0
#define OUT_FC  12288
#define OUT_LOG 12800
#define OUT_MAP 12804

#define LOG2E 1.4426950408889634f
#define LG_BIAS 12.0f               // bias in log2 domain; 2^12
#define LG_BIAS_INV (1.0f / 4096.0f)

// ---------------- scratch ----------------
__device__ float g_wcat1[Dd * HF];
__device__ float g_wcat2[HF * HF];
__device__ float g_x1[Bsz * Nn * HF];
__device__ float g_x2[Bsz * Nn * HF];
__device__ float g_es[Bsz * Hh * Nn];     // pre-scaled by log2e
__device__ float g_ed[Bsz * Hh * Nn];     // pre-scaled by log2e
__device__ float g_inv[Bsz * Hh * Nn];    // true 1/rowsum (written by attmma)
__device__ unsigned g_adjbits[Nn * 64];   // 512 KB bitmask
__device__ __half g_hT[Bsz * HF * Nn];    // h^T fp16
__device__ float g_fc1[Bsz * FC1n];
__device__ float g_y1[Bsz * FC1n];
__device__ float g_fc2[Bsz * FC2n];
__device__ float g_part[8 * Bsz * FC1n];

// ---------------- f32x2 helpers (SIMT proj GEMM) ----------------
__device__ __forceinline__ unsigned long long pack2(float x, float y) {
    unsigned long long r;
    asm("mov.b64 %0, {%1, %2};" : "=l"(r) : "r"(__float_as_uint(x)), "r"(__float_as_uint(y)));
    return r;
}
__device__ __forceinline__ unsigned long long rep2(float x) {
    unsigned long long r; unsigned u = __float_as_uint(x);
    asm("mov.b64 %0, {%1, %1};" : "=l"(r) : "r"(u));
    return r;
}
__device__ __forceinline__ void fma2(unsigned long long &d, unsigned long long a, unsigned long long b) {
    asm("fma.rn.f32x2 %0, %1, %2, %0;" : "+l"(d) : "l"(a), "l"(b));
}
__device__ __forceinline__ float2 unpk2(unsigned long long v) {
    float2 f; f.x = __uint_as_float((unsigned)v); f.y = __uint_as_float((unsigned)(v >> 32));
    return f;
}

// ---------------- cp.async helpers ----------------
__device__ __forceinline__ uint32_t smem_u32(const void* p) {
    uint32_t a;
    asm("{ .reg .u64 t; cvta.to.shared.u64 t, %1; cvt.u32.u64 %0, t; }" : "=r"(a) : "l"(p));
    return a;
}
#define CP16(saddr, gptr) asm volatile("cp.async.cg.shared.global [%0], [%1], 16;" :: "r"(saddr), "l"(gptr) : "memory")
#define CP_COMMIT() asm volatile("cp.async.commit_group;" ::: "memory")
#define CP_WAIT0()  asm volatile("cp.async.wait_group 0;" ::: "memory")

// ---------------- repack ----------------
__global__ void repack_k(const float* __restrict__ W1, const float* __restrict__ W2) {
    int t = blockIdx.x * blockDim.x + threadIdx.x;
    if (t < Hh * Dd * Ff) {
        int h = t / (Dd * Ff); int r = t % (Dd * Ff); int d = r / Ff; int f = r % Ff;
        g_wcat1[d * HF + h * Ff + f] = W1[t];
    }
    if (t < Hh * HF * Ff) {
        int h = t / (HF * Ff); int r = t % (HF * Ff); int k = r / Ff; int f = r % Ff;
        g_wcat2[k * HF + h * Ff + f] = W2[t];
    }
}

// ---------------- adj -> bitmask ----------------
__global__ void adjpack_k(const int* __restrict__ adj) {
    int w = (blockIdx.x * blockDim.x + threadIdx.x) >> 5;   // word index
    int lane = threadIdx.x & 31;
    int i = w >> 6, widx = w & 63;
    int a = adj[(long)i * Nn + widx * 32 + lane];
    unsigned m = __ballot_sync(0xffffffffu, a > 0);
    if (!lane) g_adjbits[w] = m;
}

// ---------------- SIMT projection GEMM + fused es/ed (log2-scaled) + fp16 hT store ----------------
__global__ void __launch_bounds__(256) gemm_k(const float* __restrict__ xin,
                                              const float* __restrict__ asrc,
                                              const float* __restrict__ adst, int mode) {
    const float *A, *B; int K, lda;
    if (mode == 0) { A = xin;  B = g_wcat1; K = Dd; lda = Dd; }
    else           { A = g_x1; B = g_wcat2; K = HF; lda = HF; }
    const int ldb = HF;

    __shared__ float As[16][128];
    __shared__ float Bs[16][64];
    __shared__ float esp[16][129];
    __shared__ float edp[16][129];
    __shared__ float av[64], dv[64];
    __shared__ __half t16[64][136];

    int tid = threadIdx.x;
    int head = blockIdx.y;
    int m0 = blockIdx.x * 128, n0 = head * 64;
    int tx = tid & 15, ty = tid >> 4;
    int a_r = tid >> 2, a_k = (tid & 3) << 2;
    int b_k = tid >> 4, b_n = (tid & 15) << 2;

    if (tid < 64)       av[tid] = asrc[n0 + tid] * LOG2E;
    else if (tid < 128) dv[tid - 64] = adst[n0 + tid - 64] * LOG2E;

    const float* Ap0 = A + (long)(m0 + a_r) * lda + a_k;
    const float* Ap1 = Ap0 + (long)64 * lda;
    const float* Bp  = B + (long)b_k * ldb + n0 + b_n;

    unsigned long long acc[4][4];
#pragma unroll
    for (int i = 0; i < 4; i++)
#pragma unroll
        for (int j = 0; j < 4; j++) acc[i][j] = 0ULL;

    float4 av0 = *(const float4*)Ap0;
    float4 av1 = *(const float4*)Ap1;
    float4 bv  = *(const float4*)Bp;

    for (int k0 = 0; k0 < K; k0 += 16) {
        __syncthreads();
        As[a_k + 0][a_r] = av0.x; As[a_k + 1][a_r] = av0.y;
        As[a_k + 2][a_r] = av0.z; As[a_k + 3][a_r] = av0.w;
        As[a_k + 0][a_r + 64] = av1.x; As[a_k + 1][a_r + 64] = av1.y;
        As[a_k + 2][a_r + 64] = av1.z; As[a_k + 3][a_r + 64] = av1.w;
        *(float4*)&Bs[b_k][b_n] = bv;
        __syncthreads();
        if (k0 + 16 < K) {
            av0 = *(const float4*)(Ap0 + k0 + 16);
            av1 = *(const float4*)(Ap1 + k0 + 16);
            bv  = *(const float4*)(Bp + (long)(k0 + 16) * ldb);
        }
#pragma unroll
        for (int kk = 0; kk < 16; kk++) {
            float4 aA = *(const float4*)&As[kk][ty * 8];
            float4 aB = *(const float4*)&As[kk][ty * 8 + 4];
            float4 b4 = *(const float4*)&Bs[kk][tx * 4];
            unsigned long long au[4], bu[4];
            au[0] = pack2(aA.x, aA.y); au[1] = pack2(aA.z, aA.w);
            au[2] = pack2(aB.x, aB.y); au[3] = pack2(aB.z, aB.w);
            bu[0] = rep2(b4.x); bu[1] = rep2(b4.y); bu[2] = rep2(b4.z); bu[3] = rep2(b4.w);
#pragma unroll
            for (int ip = 0; ip < 4; ip++)
#pragma unroll
                for (int j = 0; j < 4; j++) fma2(acc[ip][j], au[ip], bu[j]);
        }
    }

    float as0 = av[tx * 4], as1 = av[tx * 4 + 1], as2 = av[tx * 4 + 2], as3 = av[tx * 4 + 3];
    float ad0 = dv[tx * 4], ad1 = dv[tx * 4 + 1], ad2 = dv[tx * 4 + 2], ad3 = dv[tx * 4 + 3];

#pragma unroll
    for (int ip = 0; ip < 4; ip++) {
        float2 c0 = unpk2(acc[ip][0]), c1 = unpk2(acc[ip][1]);
        float2 c2 = unpk2(acc[ip][2]), c3 = unpk2(acc[ip][3]);
        float4 lo = make_float4(c0.x, c1.x, c2.x, c3.x);
        float4 hi = make_float4(c0.y, c1.y, c2.y, c3.y);
        int rl = ty * 8 + 2 * ip;
        esp[tx][rl]     = lo.x * as0 + lo.y * as1 + lo.z * as2 + lo.w * as3;
        edp[tx][rl]     = lo.x * ad0 + lo.y * ad1 + lo.z * ad2 + lo.w * ad3;
        esp[tx][rl + 1] = hi.x * as0 + hi.y * as1 + hi.z * as2 + hi.w * as3;
        edp[tx][rl + 1] = hi.x * ad0 + hi.y * ad1 + hi.z * ad2 + hi.w * ad3;
        t16[tx * 4 + 0][rl]     = __float2half_rn(lo.x);
        t16[tx * 4 + 1][rl]     = __float2half_rn(lo.y);
        t16[tx * 4 + 2][rl]     = __float2half_rn(lo.z);
        t16[tx * 4 + 3][rl]     = __float2half_rn(lo.w);
        t16[tx * 4 + 0][rl + 1] = __float2half_rn(hi.x);
        t16[tx * 4 + 1][rl + 1] = __float2half_rn(hi.y);
        t16[tx * 4 + 2][rl + 1] = __float2half_rn(hi.z);
        t16[tx * 4 + 3][rl + 1] = __float2half_rn(hi.w);
    }
    __syncthreads();
    {
        int row = tid & 127, which = tid >> 7;
        const float (*src)[129] = which ? edp : esp;
        float s = 0.f;
#pragma unroll
        for (int t = 0; t < 16; t++) s += src[t][row];
        int r = m0 + row;
        int bb = r >> 11, n = r & 2047;
        int idx = (((bb << 2) + head) << 11) | n;
        if (which) g_ed[idx] = s; else g_es[idx] = s;
    }
    {
        int bb = m0 >> 11, jr = m0 & 2047;
#pragma unroll
        for (int it = 0; it < 4; it++) {
            int q = tid + 256 * it;       // 1024 uint4 = 64 cols x 128 rows fp16
            int c = q >> 4, seg = q & 15;
            uint4 v = *(uint4*)&t16[c][seg * 8];
            *(uint4*)&g_hT[((long)(bb * HF + n0 + c)) * Nn + jr + seg * 8] = v;
        }
    }
}

// ---------------- fused att-gen + wmma GEMM (fp16 1-term) + row-sum/inv ----------------
// smem: A stage0 9216 | A stage1 9216 | B stage0 9216 | B stage1 9216 = 36864
#define A_LDM 72
#define A_ST   9216
#define SB_OFF 18432
#define SB_ST  9216
#define SM_TOTAL 36864

__device__ __forceinline__ void gen_chunk(uint32_t sb, int stage, int c,
    float esi, const unsigned* __restrict__ awp, int bshift, uint32_t genoff, long edbase,
    float& ps)
{
    unsigned bits = awp[c * 2] >> bshift;
    const float4* e4p = (const float4*)(g_ed + edbase + (long)c * 64);
    uint32_t ah = sb + stage * A_ST + genoff;
    unsigned uhi[8];
#pragma unroll
    for (int g = 0; g < 4; g++) {
        float4 e4 = e4p[g];
        float ev[4] = {e4.x, e4.y, e4.z, e4.w};
        float pv[4];
#pragma unroll
        for (int u = 0; u < 4; u++) {
            float lg = esi + ev[u];                 // log2-domain score
            float lk = fmaxf(lg, 0.2f * lg);        // leaky (log2e folded upstream)
            float p = exp2f(lk - LG_BIAS);
            if (!((bits >> (g * 4 + u)) & 1u)) p = 0.f;
            pv[u] = p;
            ps += p;
        }
        __half2 h01 = __floats2half2_rn(pv[0], pv[1]);
        __half2 h23 = __floats2half2_rn(pv[2], pv[3]);
        uhi[g * 2 + 0] = *(unsigned*)&h01; uhi[g * 2 + 1] = *(unsigned*)&h23;
    }
    asm volatile("st.shared.v4.b32 [%0], {%1,%2,%3,%4};" :: "r"(ah),
                 "r"(uhi[0]), "r"(uhi[1]), "r"(uhi[2]), "r"(uhi[3]) : "memory");
    asm volatile("st.shared.v4.b32 [%0], {%1,%2,%3,%4};" :: "r"(ah + 16),
                 "r"(uhi[4]), "r"(uhi[5]), "r"(uhi[6]), "r"(uhi[7]) : "memory");
}

__global__ void __launch_bounds__(256, 2) attmma_k(int layer) {
    extern __shared__ char smem[];
    __shared__ float sinv[64];
    uint32_t sb = smem_u32(smem);
    int tid = threadIdx.x, wid = tid >> 5;
    int z = blockIdx.z;
    int b = z >> 2;
    int m0 = blockIdx.x * 64;
    int row0 = (wid >> 1) * 16;          // 4 row strips of 16
    int nh = (wid & 1) * 32;             // N-half per warp

    // gen constants: thread covers row gr, 16 cols starting q4*16
    int gr = tid >> 2, q4 = tid & 3;
    float esi = g_es[(long)z * Nn + m0 + gr];
    const unsigned* awp = g_adjbits + (long)(m0 + gr) * 64 + (q4 >> 1);
    int bshift = (q4 & 1) * 16;
    uint32_t genoff = gr * 144 + q4 * 32;
    long edbase = (long)z * Nn + q4 * 16;

    // B cp.async mapping: 64 rows x 128B per chunk, 256 threads x 2 x 16B
    int brow = tid >> 3, bseg = tid & 7;
    uint32_t bsoA = brow * 144 + bseg * 16;
    uint32_t bsoB = (brow + 32) * 144 + bseg * 16;
    long bgoA = ((long)z * 64 + brow) * Nn + bseg * 8;
    long bgoB = ((long)z * 64 + brow + 32) * Nn + bseg * 8;

    wmma::fragment<wmma::accumulator, 16, 16, 16, float> acc[2];
    wmma::fill_fragment(acc[0], 0.f);
    wmma::fill_fragment(acc[1], 0.f);

    float ps = 0.f;                      // biased row-sum partial (this thread's cols)

    gen_chunk(sb, 0, 0, esi, awp, bshift, genoff, edbase, ps);
    CP16(sb + SB_OFF + bsoA, g_hT + bgoA);
    CP16(sb + SB_OFF + bsoB, g_hT + bgoB);
    CP_COMMIT();

    for (int c = 0; c < 32; ++c) {
        int cur = c & 1;
        CP_WAIT0();
        __syncthreads();

        if (c + 1 < 32) {
            uint32_t sN = sb + SB_OFF + (cur ^ 1) * SB_ST;
            CP16(sN + bsoA, g_hT + bgoA + (c + 1) * 64);
            CP16(sN + bsoB, g_hT + bgoB + (c + 1) * 64);
            CP_COMMIT();
        }

        const __half* Ah = (const __half*)(smem + cur * A_ST);
        const __half* Bh = (const __half*)(smem + SB_OFF + cur * SB_ST);

#pragma unroll
        for (int kk = 0; kk < 4; kk++) {
            wmma::fragment<wmma::matrix_a, 16, 16, 16, __half, wmma::row_major> fa;
            wmma::load_matrix_sync(fa, Ah + row0 * A_LDM + kk * 16, A_LDM);
#pragma unroll
            for (int n = 0; n < 2; n++) {
                wmma::fragment<wmma::matrix_b, 16, 16, 16, __half, wmma::col_major> fb;
                wmma::load_matrix_sync(fb, Bh + (nh + n * 16) * A_LDM + kk * 16, A_LDM);
                wmma::mma_sync(acc[n], fa, fb, acc[n]);
            }
        }

        if (c + 1 < 32)
            gen_chunk(sb, cur ^ 1, c + 1, esi, awp, bshift, genoff, edbase, ps);
    }

    // row-sum reduction over the 4 threads covering each row (lanes differ in low 2 bits)
    ps += __shfl_xor_sync(0xffffffffu, ps, 1);
    ps += __shfl_xor_sync(0xffffffffu, ps, 2);
    if (q4 == 0) {
        float inv = 1.f / ps;            // biased inverse (matches biased accumulator)
        sinv[gr] = inv;
        g_inv[(long)z * Nn + m0 + gr] = inv * LG_BIAS_INV;  // true 1/rowsum for map_k
    }

    float* Cs = (float*)smem;
    wmma::store_matrix_sync(Cs + row0 * A_LDM + nh,      acc[0], A_LDM, wmma::mem_row_major);
    wmma::store_matrix_sync(Cs + row0 * A_LDM + nh + 16, acc[1], A_LDM, wmma::mem_row_major);
    __syncthreads();

    float* C = (layer == 0 ? g_x1 : g_x2) + ((long)(b * Nn + m0) * HF + (z & 3) * 64);
#pragma unroll
    for (int i = 0; i < 4; i++) {
        int q = tid + 256 * i;           // 1024 float4 = 64 rows x 64 cols
        int row = q >> 4, cg = q & 15;
        float sc = sinv[row];
        float4 v = *(float4*)&Cs[row * A_LDM + cg * 4];
        v.x = fmaxf(v.x, 0.f) * sc; v.y = fmaxf(v.y, 0.f) * sc;
        v.z = fmaxf(v.z, 0.f) * sc; v.w = fmaxf(v.w, 0.f) * sc;
        *(float4*)(C + (long)row * HF + cg * 4) = v;
    }
}

// ---------------- attention map: reduction-free (inv precomputed by attmma) ----------------
__global__ void __launch_bounds__(256) map_k(int layer, float* __restrict__ omap)
{
    int bi = blockIdx.x;
    int b = bi >> 11, i = bi & 2047;
    int tid = threadIdx.x;
    int j0 = tid * 8;
    unsigned bits = (g_adjbits[i * 64 + (j0 >> 5)] >> (j0 & 31)) & 0xFFu;
    long ro = (long)(b << 2) << 11;

    float m[8];
#pragma unroll
    for (int u = 0; u < 8; u++) m[u] = 0.f;

#pragma unroll
    for (int h = 0; h < 4; h++) {
        long hb = ro + ((long)h << 11);
        float esi = g_es[hb + i];
        float invh = 0.125f * g_inv[hb + i];
        const float4* edv = (const float4*)(g_ed + hb + j0);
        float4 e0 = edv[0], e1 = edv[1];
        float ev[8] = {e0.x, e0.y, e0.z, e0.w, e1.x, e1.y, e1.z, e1.w};
#pragma unroll
        for (int u = 0; u < 8; u++) {
            float lg = esi + ev[u];
            float lk = fmaxf(lg, 0.2f * lg);
            float p = exp2f(lk) * invh;
            m[u] += ((bits >> u) & 1u) ? p : 0.f;
        }
    }

    float4* mrow = (float4*)(omap + ((long)bi << 11) + j0);
    float4 v0 = make_float4(m[0], m[1], m[2], m[3]);
    float4 v1 = make_float4(m[4], m[5], m[6], m[7]);
    if (layer) {
        float4 o0 = mrow[0], o1 = mrow[1];
        v0.x += o0.x; v0.y += o0.y; v0.z += o0.z; v0.w += o0.w;
        v1.x += o1.x; v1.y += o1.y; v1.z += o1.z; v1.w += o1.w;
    }
    mrow[0] = v0; mrow[1] = v1;
}

// ---------------- pools ----------------
__global__ void pool_k(const float* __restrict__ xparam,
                       const float* __restrict__ w, const float* __restrict__ wb,
                       float* __restrict__ out, int mode)
{
    int warp = (blockIdx.x * 256 + threadIdx.x) >> 5;
    int lane = threadIdx.x & 31;
    const float* rows; int rowlen, off; float scale;
    if (mode == 0)      { rows = xparam; rowlen = Dd; off = 0;      scale = 1.f / 128.f; }
    else if (mode == 1) { rows = g_x1;   rowlen = HF; off = Nn;     scale = 1.f; }
    else                { rows = g_x2;   rowlen = HF; off = 2 * Nn; scale = 1.f; }
    const float* rp = rows + (long)warp * rowlen;
    float acc = 0.f;
    if (mode == 0) { for (int c = lane; c < rowlen; c += 32) acc += rp[c]; }
    else           { for (int c = lane; c < rowlen; c += 32) acc += rp[c] * w[c]; }
#pragma unroll
    for (int o = 16; o; o >>= 1) acc += __shfl_xor_sync(0xffffffffu, acc, o);
    if (!lane) {
        int b = warp >> 11, n = warp & 2047;
        out[(long)b * (3 * Nn) + off + n] = acc * scale + (mode == 0 ? 0.f : wb[0]);
    }
}

// ---------------- MLP head ----------------
__global__ void __launch_bounds__(256) fc_part_k(const float* __restrict__ in_param,
                                                 const float* __restrict__ W,
                                                 int use_y1, int IC, int OC)
{
    __shared__ float red0[256], red1[256];
    const float* in = use_y1 ? (const float*)g_y1 : in_param;
    int tid = threadIdx.x;
    int cl = tid & 63, ks = tid >> 6;
    int c = blockIdx.x * 64 + cl;
    int kchunk = IC >> 5;
    int k0 = (blockIdx.y * 4 + ks) * kchunk;
    const float* in0 = in;
    const float* in1 = in + IC;
    float a0 = 0.f, a1 = 0.f;
#pragma unroll 4
    for (int k = k0; k < k0 + kchunk; k++) {
        float w = W[(long)k * OC + c];
        a0 += in0[k] * w;
        a1 += in1[k] * w;
    }
    red0[tid] = a0; red1[tid] = a1;
    __syncthreads();
    if (ks == 0) {
        a0 = red0[tid] + red0[tid + 64] + red0[tid + 128] + red0[tid + 192];
        a1 = red1[tid] + red1[tid + 64] + red1[tid + 128] + red1[tid + 192];
        long base = (long)blockIdx.y * (2 * OC);
        g_part[base + c] = a0;
        g_part[base + OC + c] = a1;
    }
}

__global__ void fc_reduce_k(const float* __restrict__ bias, int mode, int OC, int tot)
{
    int t = blockIdx.x * 256 + threadIdx.x;
    if (t >= tot) return;
    float s = bias[t % OC];
#pragma unroll
    for (int p = 0; p < 8; p++) s += g_part[(long)p * tot + t];
    if (mode == 0) g_fc1[t] = s; else g_fc2[t] = s;
}

__global__ void ln_relu_k(int mode, float* __restrict__ out_param,
                          const float* __restrict__ g, const float* __restrict__ be)
{
    __shared__ float r1[8], r2[8];
    int C = (mode == 0) ? FC1n : FC2n;
    const float* in = (mode == 0) ? (const float*)g_fc1 : (const float*)g_fc2;
    float* outp = (mode == 0) ? (float*)g_y1 : out_param;
    int b = blockIdx.x, tid = threadIdx.x, lane = tid & 31, wid = tid >> 5;
    const float* row = in + (long)b * C;
    float s = 0.f, ss = 0.f;
    for (int c = tid; c < C; c += 256) { float v = row[c]; s += v; ss += v * v; }
#pragma unroll
    for (int o = 16; o; o >>= 1) {
        s  += __shfl_xor_sync(0xffffffffu, s, o);
        ss += __shfl_xor_sync(0xffffffffu, ss, o);
    }
    if (!lane) { r1[wid] = s; r2[wid] = ss; }
    __syncthreads();
    s = 0.f; ss = 0.f;
#pragma unroll
    for (int w = 0; w < 8; w++) { s += r1[w]; ss += r2[w]; }
    float m = s / C;
    float var = ss / C - m * m;
    float r = rsqrtf(var + 1e-5f);
    for (int c = tid; c < C; c += 256) {
        float v = row[c];
        outp[(long)b * C + c] = fmaxf((v - m) * r * g[c] + be[c], 0.f);
    }
}

__global__ void cls_k(const float* __restrict__ feat, const float* __restrict__ W,
                      const float* __restrict__ wb, float* __restrict__ out)
{
    int tid = threadIdx.x;
    if (tid >= 128) return;
    int lane = tid & 31, w = tid >> 5;
    int b = w >> 1, l = w & 1;
    float acc = 0.f;
    for (int k = lane; k < FC2n; k += 32) acc += feat[b * FC2n + k] * W[k * 2 + l];
#pragma unroll
    for (int o = 16; o; o >>= 1) acc += __shfl_xor_sync(0xffffffffu, acc, o);
    if (!lane) out[b * 2 + l] = acc + wb[l];
}

// ---------------- host launcher ----------------
extern "C" void kernel_launch(void* const* d_in, const int* in_sizes, int n_in,
                              void* d_out, int out_size)
{
    const float* x        = (const float*)d_in[0];
    const int*   adj      = (const int*)  d_in[1];
    const float* a1_src   = (const float*)d_in[4];
    const float* a1_dst   = (const float*)d_in[5];
    const float* pool1_W  = (const float*)d_in[6];
    const float* pool1_b  = (const float*)d_in[7];
    const float* a2_src   = (const float*)d_in[9];
    const float* a2_dst   = (const float*)d_in[10];
    const float* pool2_W  = (const float*)d_in[11];
    const float* pool2_b  = (const float*)d_in[12];
    const float* fc1_W    = (const float*)d_in[13];
    const float* fc1_b    = (const float*)d_in[14];
    const float* ln1_g    = (const float*)d_in[15];
    const float* ln1_b    = (const float*)d_in[16];
    const float* fc2_W    = (const float*)d_in[17];
    const float* fc2_b    = (const float*)d_in[18];
    const float* ln2_g    = (const float*)d_in[19];
    const float* ln2_b    = (const float*)d_in[20];
    const float* cls_W    = (const float*)d_in[21];
    const float* cls_b    = (const float*)d_in[22];

    float* out = (float*)d_out;

    cudaFuncSetAttribute(attmma_k, cudaFuncAttributeMaxDynamicSharedMemorySize, SM_TOTAL);

    repack_k<<<256, 256>>>((const float*)d_in[3], (const float*)d_in[8]);
    adjpack_k<<<16384, 256>>>(adj);

    // layer 1: gemm -> attmma (computes inv) -> map
    gemm_k<<<dim3(32, 4, 1), 256>>>(x, a1_src, a1_dst, 0);
    attmma_k<<<dim3(32, 1, 8), 256, SM_TOTAL>>>(0);
    map_k<<<4096, 256>>>(0, out + OUT_MAP);

    pool_k<<<512, 256>>>(x, pool1_W, pool1_b, out + OUT_GAT, 0);
    pool_k<<<512, 256>>>(x, pool1_W, pool1_b, out + OUT_GAT, 1);

    // layer 2
    gemm_k<<<dim3(32, 4, 1), 256>>>(x, a2_src, a2_dst, 1);
    attmma_k<<<dim3(32, 1, 8), 256, SM_TOTAL>>>(1);
    map_k<<<4096, 256>>>(1, out + OUT_MAP);

    pool_k<<<512, 256>>>(x, pool2_W, pool2_b, out + OUT_GAT, 2);

    // head
    fc_part_k<<<dim3(16, 8), 256>>>(out + OUT_GAT, fc1_W, 0, 3 * Nn, FC1n);
    fc_reduce_k<<<8, 256>>>(fc1_b, 0, FC1n, Bsz * FC1n);
    ln_relu_k<<<2, 256>>>(0, out, ln1_g, ln1_b);

    fc_part_k<<<dim3(4, 8), 256>>>(out, fc2_W, 1, FC1n, FC2n);
    fc_reduce_k<<<2, 256>>>(fc2_b, 1, FC2n, Bsz * FC2n);
    ln_relu_k<<<2, 256>>>(1, out + OUT_FC, ln2_g, ln2_b);

    cls_k<<<1, 128>>>(out + OUT_FC, cls_W, cls_b, out + OUT_LOG);
}

// round 11
// speedup vs baseline: 1.6756x; 1.0563x over previous
#include <cuda_runtime.h>
#include <cuda_bf16.h>
#include <cuda_fp16.h>
#include <mma.h>
#include <math.h>
#include <stdint.h>

using namespace nvcuda;

// ---------------- problem constants ----------------
#define Bsz 2
#define Nn  2048
#define Dd  128
#define Hh  4
#define Ff  64
#define HF  256
#define FC1n 1024
#define FC2n 256

// output layout (f32)
#define OUT_GAT 0
#define OUT_FC  12288
#define OUT_LOG 12800
#define OUT_MAP 12804

#define LOG2E 1.4426950408889634f
#define LG_BIAS 12.0f               // bias in log2 domain; 2^12
#define LG_BIAS_INV (1.0f / 4096.0f)

// ---------------- scratch ----------------
__device__ float g_wcat1[Dd * HF];
__device__ float g_wcat2[HF * HF];
__device__ float g_x1[Bsz * Nn * HF];
__device__ float g_x2[Bsz * Nn * HF];
__device__ float g_es[Bsz * Hh * Nn];     // pre-scaled by log2e
__device__ float g_ed[Bsz * Hh * Nn];     // pre-scaled by log2e
__device__ float g_inv[Bsz * Hh * Nn];    // true 1/rowsum (written by attmma)
__device__ unsigned g_adjbits[Nn * 64];   // 512 KB bitmask
__device__ __half g_hT[Bsz * HF * Nn];    // h^T fp16
__device__ float g_fc1[Bsz * FC1n];
__device__ float g_y1[Bsz * FC1n];
__device__ float g_fc2[Bsz * FC2n];
__device__ float g_part[8 * Bsz * FC1n];

// ---------------- f32x2 helpers (SIMT proj GEMM) ----------------
__device__ __forceinline__ unsigned long long pack2(float x, float y) {
    unsigned long long r;
    asm("mov.b64 %0, {%1, %2};" : "=l"(r) : "r"(__float_as_uint(x)), "r"(__float_as_uint(y)));
    return r;
}
__device__ __forceinline__ unsigned long long rep2(float x) {
    unsigned long long r; unsigned u = __float_as_uint(x);
    asm("mov.b64 %0, {%1, %1};" : "=l"(r) : "r"(u));
    return r;
}
__device__ __forceinline__ void fma2(unsigned long long &d, unsigned long long a, unsigned long long b) {
    asm("fma.rn.f32x2 %0, %1, %2, %0;" : "+l"(d) : "l"(a), "l"(b));
}
__device__ __forceinline__ float2 unpk2(unsigned long long v) {
    float2 f; f.x = __uint_as_float((unsigned)v); f.y = __uint_as_float((unsigned)(v >> 32));
    return f;
}

// ---------------- cp.async + barrier helpers ----------------
__device__ __forceinline__ uint32_t smem_u32(const void* p) {
    uint32_t a;
    asm("{ .reg .u64 t; cvta.to.shared.u64 t, %1; cvt.u32.u64 %0, t; }" : "=r"(a) : "l"(p));
    return a;
}
#define CP16(saddr, gptr) asm volatile("cp.async.cg.shared.global [%0], [%1], 16;" :: "r"(saddr), "l"(gptr) : "memory")
#define CP_COMMIT() asm volatile("cp.async.commit_group;" ::: "memory")
#define CP_WAIT1()  asm volatile("cp.async.wait_group 1;" ::: "memory")
#define CP_WAIT0()  asm volatile("cp.async.wait_group 0;" ::: "memory")
#define NB_SYNC(id)   asm volatile("bar.sync %0, 256;"   :: "r"(id) : "memory")
#define NB_ARRIVE(id) asm volatile("bar.arrive %0, 256;" :: "r"(id) : "memory")

// ---------------- repack ----------------
__global__ void repack_k(const float* __restrict__ W1, const float* __restrict__ W2) {
    int t = blockIdx.x * blockDim.x + threadIdx.x;
    if (t < Hh * Dd * Ff) {
        int h = t / (Dd * Ff); int r = t % (Dd * Ff); int d = r / Ff; int f = r % Ff;
        g_wcat1[d * HF + h * Ff + f] = W1[t];
    }
    if (t < Hh * HF * Ff) {
        int h = t / (HF * Ff); int r = t % (HF * Ff); int k = r / Ff; int f = r % Ff;
        g_wcat2[k * HF + h * Ff + f] = W2[t];
    }
}

// ---------------- adj -> bitmask ----------------
__global__ void adjpack_k(const int* __restrict__ adj) {
    int w = (blockIdx.x * blockDim.x + threadIdx.x) >> 5;   // word index
    int lane = threadIdx.x & 31;
    int i = w >> 6, widx = w & 63;
    int a = adj[(long)i * Nn + widx * 32 + lane];
    unsigned m = __ballot_sync(0xffffffffu, a > 0);
    if (!lane) g_adjbits[w] = m;
}

// ---------------- SIMT projection GEMM + fused es/ed (log2-scaled) + fp16 hT store ----------------
__global__ void __launch_bounds__(256) gemm_k(const float* __restrict__ xin,
                                              const float* __restrict__ asrc,
                                              const float* __restrict__ adst, int mode) {
    const float *A, *B; int K, lda;
    if (mode == 0) { A = xin;  B = g_wcat1; K = Dd; lda = Dd; }
    else           { A = g_x1; B = g_wcat2; K = HF; lda = HF; }
    const int ldb = HF;

    __shared__ float As[16][128];
    __shared__ float Bs[16][64];
    __shared__ float esp[16][129];
    __shared__ float edp[16][129];
    __shared__ float av[64], dv[64];
    __shared__ __half t16[64][136];

    int tid = threadIdx.x;
    int head = blockIdx.y;
    int m0 = blockIdx.x * 128, n0 = head * 64;
    int tx = tid & 15, ty = tid >> 4;
    int a_r = tid >> 2, a_k = (tid & 3) << 2;
    int b_k = tid >> 4, b_n = (tid & 15) << 2;

    if (tid < 64)       av[tid] = asrc[n0 + tid] * LOG2E;
    else if (tid < 128) dv[tid - 64] = adst[n0 + tid - 64] * LOG2E;

    const float* Ap0 = A + (long)(m0 + a_r) * lda + a_k;
    const float* Ap1 = Ap0 + (long)64 * lda;
    const float* Bp  = B + (long)b_k * ldb + n0 + b_n;

    unsigned long long acc[4][4];
#pragma unroll
    for (int i = 0; i < 4; i++)
#pragma unroll
        for (int j = 0; j < 4; j++) acc[i][j] = 0ULL;

    float4 av0 = *(const float4*)Ap0;
    float4 av1 = *(const float4*)Ap1;
    float4 bv  = *(const float4*)Bp;

    for (int k0 = 0; k0 < K; k0 += 16) {
        __syncthreads();
        As[a_k + 0][a_r] = av0.x; As[a_k + 1][a_r] = av0.y;
        As[a_k + 2][a_r] = av0.z; As[a_k + 3][a_r] = av0.w;
        As[a_k + 0][a_r + 64] = av1.x; As[a_k + 1][a_r + 64] = av1.y;
        As[a_k + 2][a_r + 64] = av1.z; As[a_k + 3][a_r + 64] = av1.w;
        *(float4*)&Bs[b_k][b_n] = bv;
        __syncthreads();
        if (k0 + 16 < K) {
            av0 = *(const float4*)(Ap0 + k0 + 16);
            av1 = *(const float4*)(Ap1 + k0 + 16);
            bv  = *(const float4*)(Bp + (long)(k0 + 16) * ldb);
        }
#pragma unroll
        for (int kk = 0; kk < 16; kk++) {
            float4 aA = *(const float4*)&As[kk][ty * 8];
            float4 aB = *(const float4*)&As[kk][ty * 8 + 4];
            float4 b4 = *(const float4*)&Bs[kk][tx * 4];
            unsigned long long au[4], bu[4];
            au[0] = pack2(aA.x, aA.y); au[1] = pack2(aA.z, aA.w);
            au[2] = pack2(aB.x, aB.y); au[3] = pack2(aB.z, aB.w);
            bu[0] = rep2(b4.x); bu[1] = rep2(b4.y); bu[2] = rep2(b4.z); bu[3] = rep2(b4.w);
#pragma unroll
            for (int ip = 0; ip < 4; ip++)
#pragma unroll
                for (int j = 0; j < 4; j++) fma2(acc[ip][j], au[ip], bu[j]);
        }
    }

    float as0 = av[tx * 4], as1 = av[tx * 4 + 1], as2 = av[tx * 4 + 2], as3 = av[tx * 4 + 3];
    float ad0 = dv[tx * 4], ad1 = dv[tx * 4 + 1], ad2 = dv[tx * 4 + 2], ad3 = dv[tx * 4 + 3];

#pragma unroll
    for (int ip = 0; ip < 4; ip++) {
        float2 c0 = unpk2(acc[ip][0]), c1 = unpk2(acc[ip][1]);
        float2 c2 = unpk2(acc[ip][2]), c3 = unpk2(acc[ip][3]);
        float4 lo = make_float4(c0.x, c1.x, c2.x, c3.x);
        float4 hi = make_float4(c0.y, c1.y, c2.y, c3.y);
        int rl = ty * 8 + 2 * ip;
        esp[tx][rl]     = lo.x * as0 + lo.y * as1 + lo.z * as2 + lo.w * as3;
        edp[tx][rl]     = lo.x * ad0 + lo.y * ad1 + lo.z * ad2 + lo.w * ad3;
        esp[tx][rl + 1] = hi.x * as0 + hi.y * as1 + hi.z * as2 + hi.w * as3;
        edp[tx][rl + 1] = hi.x * ad0 + hi.y * ad1 + hi.z * ad2 + hi.w * ad3;
        t16[tx * 4 + 0][rl]     = __float2half_rn(lo.x);
        t16[tx * 4 + 1][rl]     = __float2half_rn(lo.y);
        t16[tx * 4 + 2][rl]     = __float2half_rn(lo.z);
        t16[tx * 4 + 3][rl]     = __float2half_rn(lo.w);
        t16[tx * 4 + 0][rl + 1] = __float2half_rn(hi.x);
        t16[tx * 4 + 1][rl + 1] = __float2half_rn(hi.y);
        t16[tx * 4 + 2][rl + 1] = __float2half_rn(hi.z);
        t16[tx * 4 + 3][rl + 1] = __float2half_rn(hi.w);
    }
    __syncthreads();
    {
        int row = tid & 127, which = tid >> 7;
        const float (*src)[129] = which ? edp : esp;
        float s = 0.f;
#pragma unroll
        for (int t = 0; t < 16; t++) s += src[t][row];
        int r = m0 + row;
        int bb = r >> 11, n = r & 2047;
        int idx = (((bb << 2) + head) << 11) | n;
        if (which) g_ed[idx] = s; else g_es[idx] = s;
    }
    {
        int bb = m0 >> 11, jr = m0 & 2047;
#pragma unroll
        for (int it = 0; it < 4; it++) {
            int q = tid + 256 * it;       // 1024 uint4 = 64 cols x 128 rows fp16
            int c = q >> 4, seg = q & 15;
            uint4 v = *(uint4*)&t16[c][seg * 8];
            *(uint4*)&g_hT[((long)(bb * HF + n0 + c)) * Nn + jr + seg * 8] = v;
        }
    }
}

// ---------------- warp-specialized att-gen + wmma GEMM ----------------
// 4 producer warps (gen A, row sums) | 4 consumer warps (B cp.async + HMMA).
// smem: A stage0 9216 | A stage1 9216 | B stage0 9216 | B stage1 9216 = 36864
#define A_LDM 72
#define A_ST   9216
#define SB_OFF 18432
#define SB_ST  9216
#define SM_TOTAL 36864
// named barriers: 1=F0 2=F1 (A stage full), 3=E0 4=E1 (A stage empty)

__device__ __forceinline__ void gen_chunk(uint32_t sb, int stage, int c,
    float esi, long awbase, long edbase, uint32_t genoff, float& ps)
{
    unsigned bits = g_adjbits[awbase + c * 2];
    const float4* e4p = (const float4*)(g_ed + edbase + (long)c * 64);
    uint32_t ah = sb + stage * A_ST + genoff;
#pragma unroll
    for (int gp = 0; gp < 4; gp++) {       // 2 groups of 4 per store
        unsigned uhi[4];
#pragma unroll
        for (int g = 0; g < 2; g++) {
            float4 e4 = e4p[gp * 2 + g];
            float ev[4] = {e4.x, e4.y, e4.z, e4.w};
            float pv[4];
#pragma unroll
            for (int u = 0; u < 4; u++) {
                float lg = esi + ev[u];
                float lk = fmaxf(lg, 0.2f * lg);
                float p = exp2f(lk - LG_BIAS);
                if (!((bits >> (gp * 8 + g * 4 + u)) & 1u)) p = 0.f;
                pv[u] = p;
                ps += p;
            }
            __half2 h01 = __floats2half2_rn(pv[0], pv[1]);
            __half2 h23 = __floats2half2_rn(pv[2], pv[3]);
            uhi[g * 2 + 0] = *(unsigned*)&h01;
            uhi[g * 2 + 1] = *(unsigned*)&h23;
        }
        asm volatile("st.shared.v4.b32 [%0], {%1,%2,%3,%4};" :: "r"(ah + gp * 16),
                     "r"(uhi[0]), "r"(uhi[1]), "r"(uhi[2]), "r"(uhi[3]) : "memory");
    }
}

__global__ void __launch_bounds__(256, 2) attmma_k(int layer) {
    extern __shared__ char smem[];
    __shared__ float sinv[64];
    uint32_t sb = smem_u32(smem);
    int tid = threadIdx.x, wid = tid >> 5;
    int z = blockIdx.z;
    int b = z >> 2;
    int m0 = blockIdx.x * 64;

    wmma::fragment<wmma::accumulator, 16, 16, 16, float> acc[4];

    if (wid < 4) {
        // ---------------- producer: generate A tiles + row sums ----------------
        int gr = tid >> 1;                 // row 0..63
        int q  = tid & 1;                  // 32-col half
        float esi = g_es[(long)z * Nn + m0 + gr];
        long awbase = (long)(m0 + gr) * 64 + q;
        long edbase = (long)z * Nn + q * 32;
        uint32_t genoff = gr * 144 + q * 64;
        float ps = 0.f;

        gen_chunk(sb, 0, 0, esi, awbase, edbase, genoff, ps);
        NB_ARRIVE(1);                      // full0
        gen_chunk(sb, 1, 1, esi, awbase, edbase, genoff, ps);
        NB_ARRIVE(2);                      // full1
        for (int c = 2; c < 32; c++) {
            int s = c & 1;
            NB_SYNC(3 + s);                // wait empty s
            gen_chunk(sb, s, c, esi, awbase, edbase, genoff, ps);
            NB_ARRIVE(1 + s);              // full s
        }
        ps += __shfl_xor_sync(0xffffffffu, ps, 1);
        if (q == 0) {
            float inv = 1.f / ps;          // biased inverse
            sinv[gr] = inv;
            g_inv[(long)z * Nn + m0 + gr] = inv * LG_BIAS_INV;
        }
    } else {
        // ---------------- consumer: B cp.async + HMMA ----------------
        int c0 = tid - 128;                // 0..127
        int row0 = (wid - 4) * 16;
#pragma unroll
        for (int n = 0; n < 4; n++) wmma::fill_fragment(acc[n], 0.f);

        // B mapping: 64 rows x 128B per chunk; 128 threads x 4 x 16B
        uint32_t bso[4]; long bgo[4];
#pragma unroll
        for (int i = 0; i < 4; i++) {
            int idx = c0 + 128 * i;
            int row = idx >> 3, seg = idx & 7;
            bso[i] = row * 144 + seg * 16;
            bgo[i] = ((long)z * 64 + row) * Nn + seg * 8;
        }
        {
            uint32_t s0 = sb + SB_OFF;
#pragma unroll
            for (int i = 0; i < 4; i++) CP16(s0 + bso[i], g_hT + bgo[i]);
            CP_COMMIT();
        }

        for (int c = 0; c < 32; c++) {
            int s = c & 1;
            if (c + 1 < 32) {
                uint32_t sN = sb + SB_OFF + ((c + 1) & 1) * SB_ST;
#pragma unroll
                for (int i = 0; i < 4; i++) CP16(sN + bso[i], g_hT + bgo[i] + (c + 1) * 64);
                CP_COMMIT();
                CP_WAIT1();
            } else {
                CP_WAIT0();
            }
            NB_SYNC(1 + s);                // wait A full s

            const __half* Ah = (const __half*)(smem + s * A_ST);
            const __half* Bh = (const __half*)(smem + SB_OFF + s * SB_ST);
#pragma unroll
            for (int kk = 0; kk < 4; kk++) {
                wmma::fragment<wmma::matrix_a, 16, 16, 16, __half, wmma::row_major> fa;
                wmma::load_matrix_sync(fa, Ah + row0 * A_LDM + kk * 16, A_LDM);
#pragma unroll
                for (int n = 0; n < 4; n++) {
                    wmma::fragment<wmma::matrix_b, 16, 16, 16, __half, wmma::col_major> fb;
                    wmma::load_matrix_sync(fb, Bh + n * 16 * A_LDM + kk * 16, A_LDM);
                    wmma::mma_sync(acc[n], fa, fb, acc[n]);
                }
            }
            NB_ARRIVE(3 + s);              // A stage s empty
        }
    }

    __syncthreads();                       // converge; A/B stages now dead
    float* Cs = (float*)smem;              // 64 x 72 f32 = 18432 B
    if (wid >= 4) {
        int row0 = (wid - 4) * 16;
#pragma unroll
        for (int n = 0; n < 4; n++)
            wmma::store_matrix_sync(Cs + row0 * A_LDM + n * 16, acc[n], A_LDM, wmma::mem_row_major);
    }
    __syncthreads();

    float* C = (layer == 0 ? g_x1 : g_x2) + ((long)(b * Nn + m0) * HF + (z & 3) * 64);
#pragma unroll
    for (int i = 0; i < 4; i++) {
        int q = tid + 256 * i;             // 1024 float4 = 64 rows x 64 cols
        int row = q >> 4, cg = q & 15;
        float sc = sinv[row];
        float4 v = *(float4*)&Cs[row * A_LDM + cg * 4];
        v.x = fmaxf(v.x, 0.f) * sc; v.y = fmaxf(v.y, 0.f) * sc;
        v.z = fmaxf(v.z, 0.f) * sc; v.w = fmaxf(v.w, 0.f) * sc;
        *(float4*)(C + (long)row * HF + cg * 4) = v;
    }
}

// ---------------- attention map: reduction-free (inv precomputed by attmma) ----------------
__global__ void __launch_bounds__(256) map_k(int layer, float* __restrict__ omap)
{
    int bi = blockIdx.x;
    int b = bi >> 11, i = bi & 2047;
    int tid = threadIdx.x;
    int j0 = tid * 8;
    unsigned bits = (g_adjbits[i * 64 + (j0 >> 5)] >> (j0 & 31)) & 0xFFu;
    long ro = (long)(b << 2) << 11;

    float m[8];
#pragma unroll
    for (int u = 0; u < 8; u++) m[u] = 0.f;

#pragma unroll
    for (int h = 0; h < 4; h++) {
        long hb = ro + ((long)h << 11);
        float esi = g_es[hb + i];
        float invh = 0.125f * g_inv[hb + i];
        const float4* edv = (const float4*)(g_ed + hb + j0);
        float4 e0 = edv[0], e1 = edv[1];
        float ev[8] = {e0.x, e0.y, e0.z, e0.w, e1.x, e1.y, e1.z, e1.w};
#pragma unroll
        for (int u = 0; u < 8; u++) {
            float lg = esi + ev[u];
            float lk = fmaxf(lg, 0.2f * lg);
            float p = exp2f(lk) * invh;
            m[u] += ((bits >> u) & 1u) ? p : 0.f;
        }
    }

    float4* mrow = (float4*)(omap + ((long)bi << 11) + j0);
    float4 v0 = make_float4(m[0], m[1], m[2], m[3]);
    float4 v1 = make_float4(m[4], m[5], m[6], m[7]);
    if (layer) {
        float4 o0 = mrow[0], o1 = mrow[1];
        v0.x += o0.x; v0.y += o0.y; v0.z += o0.z; v0.w += o0.w;
        v1.x += o1.x; v1.y += o1.y; v1.z += o1.z; v1.w += o1.w;
    }
    mrow[0] = v0; mrow[1] = v1;
}

// ---------------- pools ----------------
__global__ void pool_k(const float* __restrict__ xparam,
                       const float* __restrict__ w, const float* __restrict__ wb,
                       float* __restrict__ out, int mode)
{
    int warp = (blockIdx.x * 256 + threadIdx.x) >> 5;
    int lane = threadIdx.x & 31;
    const float* rows; int rowlen, off; float scale;
    if (mode == 0)      { rows = xparam; rowlen = Dd; off = 0;      scale = 1.f / 128.f; }
    else if (mode == 1) { rows = g_x1;   rowlen = HF; off = Nn;     scale = 1.f; }
    else                { rows = g_x2;   rowlen = HF; off = 2 * Nn; scale = 1.f; }
    const float* rp = rows + (long)warp * rowlen;
    float acc = 0.f;
    if (mode == 0) { for (int c = lane; c < rowlen; c += 32) acc += rp[c]; }
    else           { for (int c = lane; c < rowlen; c += 32) acc += rp[c] * w[c]; }
#pragma unroll
    for (int o = 16; o; o >>= 1) acc += __shfl_xor_sync(0xffffffffu, acc, o);
    if (!lane) {
        int b = warp >> 11, n = warp & 2047;
        out[(long)b * (3 * Nn) + off + n] = acc * scale + (mode == 0 ? 0.f : wb[0]);
    }
}

// ---------------- MLP head ----------------
__global__ void __launch_bounds__(256) fc_part_k(const float* __restrict__ in_param,
                                                 const float* __restrict__ W,
                                                 int use_y1, int IC, int OC)
{
    __shared__ float red0[256], red1[256];
    const float* in = use_y1 ? (const float*)g_y1 : in_param;
    int tid = threadIdx.x;
    int cl = tid & 63, ks = tid >> 6;
    int c = blockIdx.x * 64 + cl;
    int kchunk = IC >> 5;
    int k0 = (blockIdx.y * 4 + ks) * kchunk;
    const float* in0 = in;
    const float* in1 = in + IC;
    float a0 = 0.f, a1 = 0.f;
#pragma unroll 4
    for (int k = k0; k < k0 + kchunk; k++) {
        float w = W[(long)k * OC + c];
        a0 += in0[k] * w;
        a1 += in1[k] * w;
    }
    red0[tid] = a0; red1[tid] = a1;
    __syncthreads();
    if (ks == 0) {
        a0 = red0[tid] + red0[tid + 64] + red0[tid + 128] + red0[tid + 192];
        a1 = red1[tid] + red1[tid + 64] + red1[tid + 128] + red1[tid + 192];
        long base = (long)blockIdx.y * (2 * OC);
        g_part[base + c] = a0;
        g_part[base + OC + c] = a1;
    }
}

__global__ void fc_reduce_k(const float* __restrict__ bias, int mode, int OC, int tot)
{
    int t = blockIdx.x * 256 + threadIdx.x;
    if (t >= tot) return;
    float s = bias[t % OC];
#pragma unroll
    for (int p = 0; p < 8; p++) s += g_part[(long)p * tot + t];
    if (mode == 0) g_fc1[t] = s; else g_fc2[t] = s;
}

__global__ void ln_relu_k(int mode, float* __restrict__ out_param,
                          const float* __restrict__ g, const float* __restrict__ be)
{
    __shared__ float r1[8], r2[8];
    int C = (mode == 0) ? FC1n : FC2n;
    const float* in = (mode == 0) ? (const float*)g_fc1 : (const float*)g_fc2;
    float* outp = (mode == 0) ? (float*)g_y1 : out_param;
    int b = blockIdx.x, tid = threadIdx.x, lane = tid & 31, wid = tid >> 5;
    const float* row = in + (long)b * C;
    float s = 0.f, ss = 0.f;
    for (int c = tid; c < C; c += 256) { float v = row[c]; s += v; ss += v * v; }
#pragma unroll
    for (int o = 16; o; o >>= 1) {
        s  += __shfl_xor_sync(0xffffffffu, s, o);
        ss += __shfl_xor_sync(0xffffffffu, ss, o);
    }
    if (!lane) { r1[wid] = s; r2[wid] = ss; }
    __syncthreads();
    s = 0.f; ss = 0.f;
#pragma unroll
    for (int w = 0; w < 8; w++) { s += r1[w]; ss += r2[w]; }
    float m = s / C;
    float var = ss / C - m * m;
    float r = rsqrtf(var + 1e-5f);
    for (int c = tid; c < C; c += 256) {
        float v = row[c];
        outp[(long)b * C + c] = fmaxf((v - m) * r * g[c] + be[c], 0.f);
    }
}

__global__ void cls_k(const float* __restrict__ feat, const float* __restrict__ W,
                      const float* __restrict__ wb, float* __restrict__ out)
{
    int tid = threadIdx.x;
    if (tid >= 128) return;
    int lane = tid & 31, w = tid >> 5;
    int b = w >> 1, l = w & 1;
    float acc = 0.f;
    for (int k = lane; k < FC2n; k += 32) acc += feat[b * FC2n + k] * W[k * 2 + l];
#pragma unroll
    for (int o = 16; o; o >>= 1) acc += __shfl_xor_sync(0xffffffffu, acc, o);
    if (!lane) out[b * 2 + l] = acc + wb[l];
}

// ---------------- host launcher ----------------
extern "C" void kernel_launch(void* const* d_in, const int* in_sizes, int n_in,
                              void* d_out, int out_size)
{
    const float* x        = (const float*)d_in[0];
    const int*   adj      = (const int*)  d_in[1];
    const float* a1_src   = (const float*)d_in[4];
    const float* a1_dst   = (const float*)d_in[5];
    const float* pool1_W  = (const float*)d_in[6];
    const float* pool1_b  = (const float*)d_in[7];
    const float* a2_src   = (const float*)d_in[9];
    const float* a2_dst   = (const float*)d_in[10];
    const float* pool2_W  = (const float*)d_in[11];
    const float* pool2_b  = (const float*)d_in[12];
    const float* fc1_W    = (const float*)d_in[13];
    const float* fc1_b    = (const float*)d_in[14];
    const float* ln1_g    = (const float*)d_in[15];
    const float* ln1_b    = (const float*)d_in[16];
    const float* fc2_W    = (const float*)d_in[17];
    const float* fc2_b    = (const float*)d_in[18];
    const float* ln2_g    = (const float*)d_in[19];
    const float* ln2_b    = (const float*)d_in[20];
    const float* cls_W    = (const float*)d_in[21];
    const float* cls_b    = (const float*)d_in[22];

    float* out = (float*)d_out;

    cudaFuncSetAttribute(attmma_k, cudaFuncAttributeMaxDynamicSharedMemorySize, SM_TOTAL);

    repack_k<<<256, 256>>>((const float*)d_in[3], (const float*)d_in[8]);
    adjpack_k<<<16384, 256>>>(adj);

    // layer 1: gemm -> attmma (computes inv) -> map
    gemm_k<<<dim3(32, 4, 1), 256>>>(x, a1_src, a1_dst, 0);
    attmma_k<<<dim3(32, 1, 8), 256, SM_TOTAL>>>(0);
    map_k<<<4096, 256>>>(0, out + OUT_MAP);

    pool_k<<<512, 256>>>(x, pool1_W, pool1_b, out + OUT_GAT, 0);
    pool_k<<<512, 256>>>(x, pool1_W, pool1_b, out + OUT_GAT, 1);

    // layer 2
    gemm_k<<<dim3(32, 4, 1), 256>>>(x, a2_src, a2_dst, 1);
    attmma_k<<<dim3(32, 1, 8), 256, SM_TOTAL>>>(1);
    map_k<<<4096, 256>>>(1, out + OUT_MAP);

    pool_k<<<512, 256>>>(x, pool2_W, pool2_b, out + OUT_GAT, 2);

    // head
    fc_part_k<<<dim3(16, 8), 256>>>(out + OUT_GAT, fc1_W, 0, 3 * Nn, FC1n);
    fc_reduce_k<<<8, 256>>>(fc1_b, 0, FC1n, Bsz * FC1n);
    ln_relu_k<<<2, 256>>>(0, out, ln1_g, ln1_b);

    fc_part_k<<<dim3(4, 8), 256>>>(out, fc2_W, 1, FC1n, FC2n);
    fc_reduce_k<<<2, 256>>>(fc2_b, 1, FC2n, Bsz * FC2n);
    ln_relu_k<<<2, 256>>>(1, out + OUT_FC, ln2_g, ln2_b);

    cls_k<<<1, 128>>>(out + OUT_FC, cls_W, cls_b, out + OUT_LOG);
}

// round 15
// speedup vs baseline: 1.7251x; 1.0295x over previous
#include <cuda_runtime.h>
#include <cuda_bf16.h>
#include <cuda_fp16.h>
#include <mma.h>
#include <math.h>
#include <stdint.h>

using namespace nvcuda;

// ---------------- problem constants ----------------
#define Bsz 2
#define Nn  2048
#define Dd  128
#define Hh  4
#define Ff  64
#define HF  256
#define FC1n 1024
#define FC2n 256

// output layout (f32)
#define OUT_GAT 0
#define OUT_FC  12288
#define OUT_LOG 12800
#define OUT_MAP 12804

#define LOG2E 1.4426950408889634f
#define LG_BIAS 12.0f               // bias in log2 domain; 2^12
#define LG_BIAS_INV (1.0f / 4096.0f)

// ---------------- scratch ----------------
__device__ float g_wcat1[Dd * HF];
__device__ float g_wcat2[HF * HF];
__device__ float g_x1[Bsz * Nn * HF];
__device__ float g_x2[Bsz * Nn * HF];
__device__ float g_es[Bsz * Hh * Nn];     // layer-1 (pre-scaled by log2e)
__device__ float g_ed[Bsz * Hh * Nn];
__device__ float g_inv[Bsz * Hh * Nn];
__device__ float g_es2[Bsz * Hh * Nn];    // layer-2
__device__ float g_ed2[Bsz * Hh * Nn];
__device__ float g_inv2[Bsz * Hh * Nn];
__device__ unsigned g_adjbits[Nn * 64];   // 512 KB bitmask
__device__ __half g_hT[Bsz * HF * Nn];    // h^T fp16
__device__ float g_fc1[Bsz * FC1n];
__device__ float g_y1[Bsz * FC1n];
__device__ float g_fc2[Bsz * FC2n];
__device__ float g_part[8 * Bsz * FC1n];

// ---------------- f32x2 helpers (SIMT proj GEMM) ----------------
__device__ __forceinline__ unsigned long long pack2(float x, float y) {
    unsigned long long r;
    asm("mov.b64 %0, {%1, %2};" : "=l"(r) : "r"(__float_as_uint(x)), "r"(__float_as_uint(y)));
    return r;
}
__device__ __forceinline__ unsigned long long rep2(float x) {
    unsigned long long r; unsigned u = __float_as_uint(x);
    asm("mov.b64 %0, {%1, %1};" : "=l"(r) : "r"(u));
    return r;
}
__device__ __forceinline__ void fma2(unsigned long long &d, unsigned long long a, unsigned long long b) {
    asm("fma.rn.f32x2 %0, %1, %2, %0;" : "+l"(d) : "l"(a), "l"(b));
}
__device__ __forceinline__ float2 unpk2(unsigned long long v) {
    float2 f; f.x = __uint_as_float((unsigned)v); f.y = __uint_as_float((unsigned)(v >> 32));
    return f;
}

// ---------------- cp.async + barrier helpers ----------------
__device__ __forceinline__ uint32_t smem_u32(const void* p) {
    uint32_t a;
    asm("{ .reg .u64 t; cvta.to.shared.u64 t, %1; cvt.u32.u64 %0, t; }" : "=r"(a) : "l"(p));
    return a;
}
#define CP16(saddr, gptr) asm volatile("cp.async.cg.shared.global [%0], [%1], 16;" :: "r"(saddr), "l"(gptr) : "memory")
#define CP_COMMIT() asm volatile("cp.async.commit_group;" ::: "memory")
#define CP_WAIT1()  asm volatile("cp.async.wait_group 1;" ::: "memory")
#define CP_WAIT0()  asm volatile("cp.async.wait_group 0;" ::: "memory")
#define NB_SYNC(id)   asm volatile("bar.sync %0, 256;"   :: "r"(id) : "memory")
#define NB_ARRIVE(id) asm volatile("bar.arrive %0, 256;" :: "r"(id) : "memory")

// ---------------- repack ----------------
__global__ void repack_k(const float* __restrict__ W1, const float* __restrict__ W2) {
    int t = blockIdx.x * blockDim.x + threadIdx.x;
    if (t < Hh * Dd * Ff) {
        int h = t / (Dd * Ff); int r = t % (Dd * Ff); int d = r / Ff; int f = r % Ff;
        g_wcat1[d * HF + h * Ff + f] = W1[t];
    }
    if (t < Hh * HF * Ff) {
        int h = t / (HF * Ff); int r = t % (HF * Ff); int k = r / Ff; int f = r % Ff;
        g_wcat2[k * HF + h * Ff + f] = W2[t];
    }
}

// ---------------- adj -> bitmask ----------------
__global__ void adjpack_k(const int* __restrict__ adj) {
    int w = (blockIdx.x * blockDim.x + threadIdx.x) >> 5;   // word index
    int lane = threadIdx.x & 31;
    int i = w >> 6, widx = w & 63;
    int a = adj[(long)i * Nn + widx * 32 + lane];
    unsigned m = __ballot_sync(0xffffffffu, a > 0);
    if (!lane) g_adjbits[w] = m;
}

// ---------------- SIMT projection GEMM + fused es/ed (log2-scaled) + fp16 hT store ----------------
__global__ void __launch_bounds__(256) gemm_k(const float* __restrict__ xin,
                                              const float* __restrict__ asrc,
                                              const float* __restrict__ adst, int mode) {
    const float *A, *B; int K, lda;
    float *esOut, *edOut;
    if (mode == 0) { A = xin;  B = g_wcat1; K = Dd; lda = Dd; esOut = g_es;  edOut = g_ed;  }
    else           { A = g_x1; B = g_wcat2; K = HF; lda = HF; esOut = g_es2; edOut = g_ed2; }
    const int ldb = HF;

    __shared__ float As[16][128];
    __shared__ float Bs[16][64];
    __shared__ float esp[16][129];
    __shared__ float edp[16][129];
    __shared__ float av[64], dv[64];
    __shared__ __half t16[64][136];

    int tid = threadIdx.x;
    int head = blockIdx.y;
    int m0 = blockIdx.x * 128, n0 = head * 64;
    int tx = tid & 15, ty = tid >> 4;
    int a_r = tid >> 2, a_k = (tid & 3) << 2;
    int b_k = tid >> 4, b_n = (tid & 15) << 2;

    if (tid < 64)       av[tid] = asrc[n0 + tid] * LOG2E;
    else if (tid < 128) dv[tid - 64] = adst[n0 + tid - 64] * LOG2E;

    const float* Ap0 = A + (long)(m0 + a_r) * lda + a_k;
    const float* Ap1 = Ap0 + (long)64 * lda;
    const float* Bp  = B + (long)b_k * ldb + n0 + b_n;

    unsigned long long acc[4][4];
#pragma unroll
    for (int i = 0; i < 4; i++)
#pragma unroll
        for (int j = 0; j < 4; j++) acc[i][j] = 0ULL;

    float4 av0 = *(const float4*)Ap0;
    float4 av1 = *(const float4*)Ap1;
    float4 bv  = *(const float4*)Bp;

    for (int k0 = 0; k0 < K; k0 += 16) {
        __syncthreads();
        As[a_k + 0][a_r] = av0.x; As[a_k + 1][a_r] = av0.y;
        As[a_k + 2][a_r] = av0.z; As[a_k + 3][a_r] = av0.w;
        As[a_k + 0][a_r + 64] = av1.x; As[a_k + 1][a_r + 64] = av1.y;
        As[a_k + 2][a_r + 64] = av1.z; As[a_k + 3][a_r + 64] = av1.w;
        *(float4*)&Bs[b_k][b_n] = bv;
        __syncthreads();
        if (k0 + 16 < K) {
            av0 = *(const float4*)(Ap0 + k0 + 16);
            av1 = *(const float4*)(Ap1 + k0 + 16);
            bv  = *(const float4*)(Bp + (long)(k0 + 16) * ldb);
        }
#pragma unroll
        for (int kk = 0; kk < 16; kk++) {
            float4 aA = *(const float4*)&As[kk][ty * 8];
            float4 aB = *(const float4*)&As[kk][ty * 8 + 4];
            float4 b4 = *(const float4*)&Bs[kk][tx * 4];
            unsigned long long au[4], bu[4];
            au[0] = pack2(aA.x, aA.y); au[1] = pack2(aA.z, aA.w);
            au[2] = pack2(aB.x, aB.y); au[3] = pack2(aB.z, aB.w);
            bu[0] = rep2(b4.x); bu[1] = rep2(b4.y); bu[2] = rep2(b4.z); bu[3] = rep2(b4.w);
#pragma unroll
            for (int ip = 0; ip < 4; ip++)
#pragma unroll
                for (int j = 0; j < 4; j++) fma2(acc[ip][j], au[ip], bu[j]);
        }
    }

    float as0 = av[tx * 4], as1 = av[tx * 4 + 1], as2 = av[tx * 4 + 2], as3 = av[tx * 4 + 3];
    float ad0 = dv[tx * 4], ad1 = dv[tx * 4 + 1], ad2 = dv[tx * 4 + 2], ad3 = dv[tx * 4 + 3];

#pragma unroll
    for (int ip = 0; ip < 4; ip++) {
        float2 c0 = unpk2(acc[ip][0]), c1 = unpk2(acc[ip][1]);
        float2 c2 = unpk2(acc[ip][2]), c3 = unpk2(acc[ip][3]);
        float4 lo = make_float4(c0.x, c1.x, c2.x, c3.x);
        float4 hi = make_float4(c0.y, c1.y, c2.y, c3.y);
        int rl = ty * 8 + 2 * ip;
        esp[tx][rl]     = lo.x * as0 + lo.y * as1 + lo.z * as2 + lo.w * as3;
        edp[tx][rl]     = lo.x * ad0 + lo.y * ad1 + lo.z * ad2 + lo.w * ad3;
        esp[tx][rl + 1] = hi.x * as0 + hi.y * as1 + hi.z * as2 + hi.w * as3;
        edp[tx][rl + 1] = hi.x * ad0 + hi.y * ad1 + hi.z * ad2 + hi.w * ad3;
        t16[tx * 4 + 0][rl]     = __float2half_rn(lo.x);
        t16[tx * 4 + 1][rl]     = __float2half_rn(lo.y);
        t16[tx * 4 + 2][rl]     = __float2half_rn(lo.z);
        t16[tx * 4 + 3][rl]     = __float2half_rn(lo.w);
        t16[tx * 4 + 0][rl + 1] = __float2half_rn(hi.x);
        t16[tx * 4 + 1][rl + 1] = __float2half_rn(hi.y);
        t16[tx * 4 + 2][rl + 1] = __float2half_rn(hi.z);
        t16[tx * 4 + 3][rl + 1] = __float2half_rn(hi.w);
    }
    __syncthreads();
    {
        int row = tid & 127, which = tid >> 7;
        const float (*src)[129] = which ? edp : esp;
        float s = 0.f;
#pragma unroll
        for (int t = 0; t < 16; t++) s += src[t][row];
        int r = m0 + row;
        int bb = r >> 11, n = r & 2047;
        int idx = (((bb << 2) + head) << 11) | n;
        if (which) edOut[idx] = s; else esOut[idx] = s;
    }
    {
        int bb = m0 >> 11, jr = m0 & 2047;
#pragma unroll
        for (int it = 0; it < 4; it++) {
            int q = tid + 256 * it;       // 1024 uint4 = 64 cols x 128 rows fp16
            int c = q >> 4, seg = q & 15;
            uint4 v = *(uint4*)&t16[c][seg * 8];
            *(uint4*)&g_hT[((long)(bb * HF + n0 + c)) * Nn + jr + seg * 8] = v;
        }
    }
}

// ---------------- warp-specialized att-gen + wmma GEMM (round-11 body; layer -> pointer swap) ----------------
// 4 producer warps (gen A, row sums) | 4 consumer warps (B cp.async + HMMA).
// smem: A stage0 9216 | A stage1 9216 | B stage0 9216 | B stage1 9216 = 36864
#define A_LDM 72
#define A_ST   9216
#define SB_OFF 18432
#define SB_ST  9216
#define SM_TOTAL 36864
// named barriers: 1=F0 2=F1 (A stage full), 3=E0 4=E1 (A stage empty)

__device__ __forceinline__ void gen_chunk(uint32_t sb, int stage, int c,
    float esi, long awbase, const float* __restrict__ edp, uint32_t genoff, float& ps)
{
    unsigned bits = g_adjbits[awbase + c * 2];
    const float4* e4p = (const float4*)(edp + (long)c * 64);
    uint32_t ah = sb + stage * A_ST + genoff;
#pragma unroll
    for (int gp = 0; gp < 4; gp++) {
        unsigned uhi[4];
#pragma unroll
        for (int g = 0; g < 2; g++) {
            float4 e4 = e4p[gp * 2 + g];
            float ev[4] = {e4.x, e4.y, e4.z, e4.w};
            float pv[4];
#pragma unroll
            for (int u = 0; u < 4; u++) {
                float lg = esi + ev[u];
                float lk = fmaxf(lg, 0.2f * lg);
                float p = exp2f(lk - LG_BIAS);
                if (!((bits >> (gp * 8 + g * 4 + u)) & 1u)) p = 0.f;
                pv[u] = p;
                ps += p;
            }
            __half2 h01 = __floats2half2_rn(pv[0], pv[1]);
            __half2 h23 = __floats2half2_rn(pv[2], pv[3]);
            uhi[g * 2 + 0] = *(unsigned*)&h01;
            uhi[g * 2 + 1] = *(unsigned*)&h23;
        }
        asm volatile("st.shared.v4.b32 [%0], {%1,%2,%3,%4};" :: "r"(ah + gp * 16),
                     "r"(uhi[0]), "r"(uhi[1]), "r"(uhi[2]), "r"(uhi[3]) : "memory");
    }
}

__global__ void __launch_bounds__(256, 2) attmma_k(int layer) {
    extern __shared__ char smem[];
    __shared__ float sinv[64];
    uint32_t sb = smem_u32(smem);
    int tid = threadIdx.x, wid = tid >> 5;
    int z = blockIdx.z;
    int b = z >> 2;
    int m0 = blockIdx.x * 64;

    const float* esArr = layer ? g_es2 : g_es;
    const float* edArr = layer ? g_ed2 : g_ed;
    float* invArr      = layer ? g_inv2 : g_inv;

    wmma::fragment<wmma::accumulator, 16, 16, 16, float> acc[4];

    if (wid < 4) {
        // ---------------- producer: generate A tiles + row sums ----------------
        int gr = tid >> 1;                 // row 0..63
        int q  = tid & 1;                  // 32-col half
        float esi = esArr[(long)z * Nn + m0 + gr];
        long awbase = (long)(m0 + gr) * 64 + q;
        const float* edp = edArr + (long)z * Nn + q * 32;
        uint32_t genoff = gr * 144 + q * 64;
        float ps = 0.f;

        gen_chunk(sb, 0, 0, esi, awbase, edp, genoff, ps);
        NB_ARRIVE(1);                      // full0
        gen_chunk(sb, 1, 1, esi, awbase, edp, genoff, ps);
        NB_ARRIVE(2);                      // full1
        for (int c = 2; c < 32; c++) {
            int s = c & 1;
            NB_SYNC(3 + s);                // wait empty s
            gen_chunk(sb, s, c, esi, awbase, edp, genoff, ps);
            NB_ARRIVE(1 + s);              // full s
        }
        ps += __shfl_xor_sync(0xffffffffu, ps, 1);
        if (q == 0) {
            float inv = 1.f / ps;          // biased inverse
            sinv[gr] = inv;
            invArr[(long)z * Nn + m0 + gr] = inv * LG_BIAS_INV;
        }
    } else {
        // ---------------- consumer: B cp.async + HMMA ----------------
        int c0 = tid - 128;                // 0..127
        int row0 = (wid - 4) * 16;
#pragma unroll
        for (int n = 0; n < 4; n++) wmma::fill_fragment(acc[n], 0.f);

        // B mapping: 64 rows x 128B per chunk; 128 threads x 4 x 16B
        uint32_t bso[4]; long bgo[4];
#pragma unroll
        for (int i = 0; i < 4; i++) {
            int idx = c0 + 128 * i;
            int row = idx >> 3, seg = idx & 7;
            bso[i] = row * 144 + seg * 16;
            bgo[i] = ((long)z * 64 + row) * Nn + seg * 8;
        }
        {
            uint32_t s0 = sb + SB_OFF;
#pragma unroll
            for (int i = 0; i < 4; i++) CP16(s0 + bso[i], g_hT + bgo[i]);
            CP_COMMIT();
        }

        for (int c = 0; c < 32; c++) {
            int s = c & 1;
            if (c + 1 < 32) {
                uint32_t sN = sb + SB_OFF + ((c + 1) & 1) * SB_ST;
#pragma unroll
                for (int i = 0; i < 4; i++) CP16(sN + bso[i], g_hT + bgo[i] + (c + 1) * 64);
                CP_COMMIT();
                CP_WAIT1();
            } else {
                CP_WAIT0();
            }
            NB_SYNC(1 + s);                // wait A full s

            const __half* Ah = (const __half*)(smem + s * A_ST);
            const __half* Bh = (const __half*)(smem + SB_OFF + s * SB_ST);
#pragma unroll
            for (int kk = 0; kk < 4; kk++) {
                wmma::fragment<wmma::matrix_a, 16, 16, 16, __half, wmma::row_major> fa;
                wmma::load_matrix_sync(fa, Ah + row0 * A_LDM + kk * 16, A_LDM);
#pragma unroll
                for (int n = 0; n < 4; n++) {
                    wmma::fragment<wmma::matrix_b, 16, 16, 16, __half, wmma::col_major> fb;
                    wmma::load_matrix_sync(fb, Bh + n * 16 * A_LDM + kk * 16, A_LDM);
                    wmma::mma_sync(acc[n], fa, fb, acc[n]);
                }
            }
            NB_ARRIVE(3 + s);              // A stage s empty
        }
    }

    __syncthreads();                       // converge; A/B stages now dead
    float* Cs = (float*)smem;              // 64 x 72 f32 = 18432 B
    if (wid >= 4) {
        int row0 = (wid - 4) * 16;
#pragma unroll
        for (int n = 0; n < 4; n++)
            wmma::store_matrix_sync(Cs + row0 * A_LDM + n * 16, acc[n], A_LDM, wmma::mem_row_major);
    }
    __syncthreads();

    float* C = (layer == 0 ? g_x1 : g_x2) + ((long)(b * Nn + m0) * HF + (z & 3) * 64);
#pragma unroll
    for (int i = 0; i < 4; i++) {
        int q = tid + 256 * i;             // 1024 float4 = 64 rows x 64 cols
        int row = q >> 4, cg = q & 15;
        float sc = sinv[row];
        float4 v = *(float4*)&Cs[row * A_LDM + cg * 4];
        v.x = fmaxf(v.x, 0.f) * sc; v.y = fmaxf(v.y, 0.f) * sc;
        v.z = fmaxf(v.z, 0.f) * sc; v.w = fmaxf(v.w, 0.f) * sc;
        *(float4*)(C + (long)row * HF + cg * 4) = v;
    }
}

// ---------------- attention map: both layers in one pass, single write ----------------
__global__ void __launch_bounds__(256) map2_k(float* __restrict__ omap)
{
    int bi = blockIdx.x;
    int b = bi >> 11, i = bi & 2047;
    int tid = threadIdx.x;
    int j0 = tid * 8;
    unsigned bits = (g_adjbits[i * 64 + (j0 >> 5)] >> (j0 & 31)) & 0xFFu;
    long ro = (long)(b << 2) << 11;

    float m[8];
#pragma unroll
    for (int u = 0; u < 8; u++) m[u] = 0.f;

#pragma unroll
    for (int layer = 0; layer < 2; layer++) {
        const float* esArr = layer ? g_es2 : g_es;
        const float* edArr = layer ? g_ed2 : g_ed;
        const float* invArr = layer ? g_inv2 : g_inv;
#pragma unroll
        for (int h = 0; h < 4; h++) {
            long hb = ro + ((long)h << 11);
            float esi = esArr[hb + i];
            float invh = 0.125f * invArr[hb + i];
            const float4* edv = (const float4*)(edArr + hb + j0);
            float4 e0 = edv[0], e1 = edv[1];
            float ev[8] = {e0.x, e0.y, e0.z, e0.w, e1.x, e1.y, e1.z, e1.w};
#pragma unroll
            for (int u = 0; u < 8; u++) {
                float lg = esi + ev[u];
                float lk = fmaxf(lg, 0.2f * lg);
                float p = exp2f(lk) * invh;
                m[u] += ((bits >> u) & 1u) ? p : 0.f;
            }
        }
    }

    float4* mrow = (float4*)(omap + ((long)bi << 11) + j0);
    mrow[0] = make_float4(m[0], m[1], m[2], m[3]);
    mrow[1] = make_float4(m[4], m[5], m[6], m[7]);
}

// ---------------- pools ----------------
__global__ void pool_k(const float* __restrict__ xparam,
                       const float* __restrict__ w, const float* __restrict__ wb,
                       float* __restrict__ out, int mode)
{
    int warp = (blockIdx.x * 256 + threadIdx.x) >> 5;
    int lane = threadIdx.x & 31;
    const float* rows; int rowlen, off; float scale;
    if (mode == 0)      { rows = xparam; rowlen = Dd; off = 0;      scale = 1.f / 128.f; }
    else if (mode == 1) { rows = g_x1;   rowlen = HF; off = Nn;     scale = 1.f; }
    else                { rows = g_x2;   rowlen = HF; off = 2 * Nn; scale = 1.f; }
    const float* rp = rows + (long)warp * rowlen;
    float acc = 0.f;
    if (mode == 0) { for (int c = lane; c < rowlen; c += 32) acc += rp[c]; }
    else           { for (int c = lane; c < rowlen; c += 32) acc += rp[c] * w[c]; }
#pragma unroll
    for (int o = 16; o; o >>= 1) acc += __shfl_xor_sync(0xffffffffu, acc, o);
    if (!lane) {
        int b = warp >> 11, n = warp & 2047;
        out[(long)b * (3 * Nn) + off + n] = acc * scale + (mode == 0 ? 0.f : wb[0]);
    }
}

// ---------------- MLP head ----------------
__global__ void __launch_bounds__(256) fc_part_k(const float* __restrict__ in_param,
                                                 const float* __restrict__ W,
                                                 int use_y1, int IC, int OC)
{
    __shared__ float red0[256], red1[256];
    const float* in = use_y1 ? (const float*)g_y1 : in_param;
    int tid = threadIdx.x;
    int cl = tid & 63, ks = tid >> 6;
    int c = blockIdx.x * 64 + cl;
    int kchunk = IC >> 5;
    int k0 = (blockIdx.y * 4 + ks) * kchunk;
    const float* in0 = in;
    const float* in1 = in + IC;
    float a0 = 0.f, a1 = 0.f;
#pragma unroll 4
    for (int k = k0; k < k0 + kchunk; k++) {
        float w = W[(long)k * OC + c];
        a0 += in0[k] * w;
        a1 += in1[k] * w;
    }
    red0[tid] = a0; red1[tid] = a1;
    __syncthreads();
    if (ks == 0) {
        a0 = red0[tid] + red0[tid + 64] + red0[tid + 128] + red0[tid + 192];
        a1 = red1[tid] + red1[tid + 64] + red1[tid + 128] + red1[tid + 192];
        long base = (long)blockIdx.y * (2 * OC);
        g_part[base + c] = a0;
        g_part[base + OC + c] = a1;
    }
}

__global__ void fc_reduce_k(const float* __restrict__ bias, int mode, int OC, int tot)
{
    int t = blockIdx.x * 256 + threadIdx.x;
    if (t >= tot) return;
    float s = bias[t % OC];
#pragma unroll
    for (int p = 0; p < 8; p++) s += g_part[(long)p * tot + t];
    if (mode == 0) g_fc1[t] = s; else g_fc2[t] = s;
}

__global__ void ln_relu_k(int mode, float* __restrict__ out_param,
                          const float* __restrict__ g, const float* __restrict__ be)
{
    __shared__ float r1[8], r2[8];
    int C = (mode == 0) ? FC1n : FC2n;
    const float* in = (mode == 0) ? (const float*)g_fc1 : (const float*)g_fc2;
    float* outp = (mode == 0) ? (float*)g_y1 : out_param;
    int b = blockIdx.x, tid = threadIdx.x, lane = tid & 31, wid = tid >> 5;
    const float* row = in + (long)b * C;
    float s = 0.f, ss = 0.f;
    for (int c = tid; c < C; c += 256) { float v = row[c]; s += v; ss += v * v; }
#pragma unroll
    for (int o = 16; o; o >>= 1) {
        s  += __shfl_xor_sync(0xffffffffu, s, o);
        ss += __shfl_xor_sync(0xffffffffu, ss, o);
    }
    if (!lane) { r1[wid] = s; r2[wid] = ss; }
    __syncthreads();
    s = 0.f; ss = 0.f;
#pragma unroll
    for (int w = 0; w < 8; w++) { s += r1[w]; ss += r2[w]; }
    float m = s / C;
    float var = ss / C - m * m;
    float r = rsqrtf(var + 1e-5f);
    for (int c = tid; c < C; c += 256) {
        float v = row[c];
        outp[(long)b * C + c] = fmaxf((v - m) * r * g[c] + be[c], 0.f);
    }
}

__global__ void cls_k(const float* __restrict__ feat, const float* __restrict__ W,
                      const float* __restrict__ wb, float* __restrict__ out)
{
    int tid = threadIdx.x;
    if (tid >= 128) return;
    int lane = tid & 31, w = tid >> 5;
    int b = w >> 1, l = w & 1;
    float acc = 0.f;
    for (int k = lane; k < FC2n; k += 32) acc += feat[b * FC2n + k] * W[k * 2 + l];
#pragma unroll
    for (int o = 16; o; o >>= 1) acc += __shfl_xor_sync(0xffffffffu, acc, o);
    if (!lane) out[b * 2 + l] = acc + wb[l];
}

// ---------------- host launcher (single stream, sequential) ----------------
extern "C" void kernel_launch(void* const* d_in, const int* in_sizes, int n_in,
                              void* d_out, int out_size)
{
    const float* x        = (const float*)d_in[0];
    const int*   adj      = (const int*)  d_in[1];
    const float* a1_src   = (const float*)d_in[4];
    const float* a1_dst   = (const float*)d_in[5];
    const float* pool1_W  = (const float*)d_in[6];
    const float* pool1_b  = (const float*)d_in[7];
    const float* a2_src   = (const float*)d_in[9];
    const float* a2_dst   = (const float*)d_in[10];
    const float* pool2_W  = (const float*)d_in[11];
    const float* pool2_b  = (const float*)d_in[12];
    const float* fc1_W    = (const float*)d_in[13];
    const float* fc1_b    = (const float*)d_in[14];
    const float* ln1_g    = (const float*)d_in[15];
    const float* ln1_b    = (const float*)d_in[16];
    const float* fc2_W    = (const float*)d_in[17];
    const float* fc2_b    = (const float*)d_in[18];
    const float* ln2_g    = (const float*)d_in[19];
    const float* ln2_b    = (const float*)d_in[20];
    const float* cls_W    = (const float*)d_in[21];
    const float* cls_b    = (const float*)d_in[22];

    float* out = (float*)d_out;

    cudaFuncSetAttribute(attmma_k, cudaFuncAttributeMaxDynamicSharedMemorySize, SM_TOTAL);

    repack_k<<<256, 256>>>((const float*)d_in[3], (const float*)d_in[8]);
    adjpack_k<<<16384, 256>>>(adj);

    // layer 1: gemm -> attmma (computes inv)
    gemm_k<<<dim3(32, 4, 1), 256>>>(x, a1_src, a1_dst, 0);
    attmma_k<<<dim3(32, 1, 8), 256, SM_TOTAL>>>(0);

    pool_k<<<512, 256>>>(x, pool1_W, pool1_b, out + OUT_GAT, 0);
    pool_k<<<512, 256>>>(x, pool1_W, pool1_b, out + OUT_GAT, 1);

    // layer 2
    gemm_k<<<dim3(32, 4, 1), 256>>>(x, a2_src, a2_dst, 1);
    attmma_k<<<dim3(32, 1, 8), 256, SM_TOTAL>>>(1);

    // fused attention map (both layers, single write)
    map2_k<<<4096, 256>>>(out + OUT_MAP);

    pool_k<<<512, 256>>>(x, pool2_W, pool2_b, out + OUT_GAT, 2);

    // head
    fc_part_k<<<dim3(16, 8), 256>>>(out + OUT_GAT, fc1_W, 0, 3 * Nn, FC1n);
    fc_reduce_k<<<8, 256>>>(fc1_b, 0, FC1n, Bsz * FC1n);
    ln_relu_k<<<2, 256>>>(0, out, ln1_g, ln1_b);

    fc_part_k<<<dim3(4, 8), 256>>>(out, fc2_W, 1, FC1n, FC2n);
    fc_reduce_k<<<2, 256>>>(fc2_b, 1, FC2n, Bsz * FC2n);
    ln_relu_k<<<2, 256>>>(1, out + OUT_FC, ln2_g, ln2_b);

    cls_k<<<1, 128>>>(out + OUT_FC, cls_W, cls_b, out + OUT_LOG);
}